// round 9
// baseline (speedup 1.0000x reference)
#include <cuda_runtime.h>

// B=2048, DKV=64, L=128, H=16, DT=32, KW=13, PAD=6
#define NT 256
#define QS 132     // qb/kb/vb row stride
#define SCS 34     // qh/kh/vh scratch row stride
#define ATS 516    // att smem row stride

// shared layout (floats), peak 25728 (=102,912B) -> 2 CTAs/SM with full carveout
#define OFF_QKV 0            // 3*32*132 = 12672            [P1 out, P2 A]
#define OFF_IN  12672        // 64*140 = 8960                [P1]
#define OFF_CW  21632        // 32*8*14 = 3584 -> 25216      [P1 weight chunk]
#define OFF_SCR 12672        // 4 heads*3*32*34 = 13056 -> 25728 [P2]
#define OFF_Y   0            // 32*140 = 4480                [P3 -> P4]
#define OFF_ATT 4480         // 32*516 = 16512 -> 20992      [P3]
#define OFF_FCW 4480         // 64*8*14 = 7168 -> 11648      [P4 chunk, over dead ATT]
#define OFF_Z   11648        // 8192 -> 19840                [P4 -> P5]
#define SMEM_FLOATS 25728
#define SMEM_BYTES (SMEM_FLOATS * 4)

typedef unsigned long long u64;

// gmem scratch (allowed: __device__ globals, no allocation)
__device__ float g_att[2048 * 32 * 512];   // per-batch attention concat
__device__ float g_pwT[512 * 128];         // proj_w transposed: pwT[j][m]

__device__ __forceinline__ u64 pk2(float lo, float hi) {
    u64 r; asm("mov.b64 %0,{%1,%2};" : "=l"(r) : "f"(lo), "f"(hi)); return r;
}
__device__ __forceinline__ u64 dup2(float x) { return pk2(x, x); }
__device__ __forceinline__ void upk2(float& lo, float& hi, u64 v) {
    asm("mov.b64 {%0,%1},%2;" : "=f"(lo), "=f"(hi) : "l"(v));
}
__device__ __forceinline__ void fma2(u64& d, u64 a, u64 b) {
    asm("fma.rn.f32x2 %0,%1,%2,%0;" : "+l"(d) : "l"(a), "l"(b));
}
__device__ __forceinline__ u64 add2(u64 a, u64 b) {
    u64 d; asm("add.rn.f32x2 %0,%1,%2;" : "=l"(d) : "l"(a), "l"(b)); return d;
}
__device__ __forceinline__ u64 lds64(const float* p) {
    return *reinterpret_cast<const u64*>(p);
}

__global__ void transpose_pw_kernel(const float* __restrict__ pw) {
    int idx = blockIdx.x * 512 + threadIdx.x;   // 65536 total
    int j = idx >> 7, m = idx & 127;
    g_pwT[idx] = pw[m * 512 + j];
}

// One warp: C(32x32) = A(32x128) @ B(128x32); A smem (stride QS, lds64 l-pairs),
// B streamed from gmem (dedup'd lines), C to smem (stride SCS).
template<int TN>
__device__ __forceinline__ void gemm32(const float* __restrict__ A,
                                       const float* __restrict__ Bg,
                                       float* __restrict__ C,
                                       int tbase, int tr, int dc)
{
    u64 acc[TN][4];
#pragma unroll
    for (int i = 0; i < TN; i++)
#pragma unroll
        for (int j = 0; j < 4; j++) acc[i][j] = 0ull;
    const float* Ar[TN];
#pragma unroll
    for (int i = 0; i < TN; i++) Ar[i] = A + (tbase + tr + 8 * i) * QS;

    const float* bp = Bg + dc * 8;
    ulonglong2 cE0 = __ldg((const ulonglong2*)bp);
    ulonglong2 cE1 = __ldg((const ulonglong2*)(bp + 4));
    ulonglong2 cO0 = __ldg((const ulonglong2*)(bp + 32));
    ulonglong2 cO1 = __ldg((const ulonglong2*)(bp + 36));
#pragma unroll 2
    for (int l2 = 0; l2 < 64; l2++) {
        const int nb = (l2 < 63) ? (2 * l2 + 2) : 126;
        ulonglong2 nE0 = __ldg((const ulonglong2*)(bp + nb * 32));
        ulonglong2 nE1 = __ldg((const ulonglong2*)(bp + nb * 32 + 4));
        ulonglong2 nO0 = __ldg((const ulonglong2*)(bp + nb * 32 + 32));
        ulonglong2 nO1 = __ldg((const ulonglong2*)(bp + nb * 32 + 36));
#pragma unroll
        for (int i = 0; i < TN; i++) {
            u64 a01 = lds64(Ar[i] + 2 * l2);
            float alo, ahi; upk2(alo, ahi, a01);
            u64 d0 = dup2(alo), d1 = dup2(ahi);
            fma2(acc[i][0], d0, cE0.x); fma2(acc[i][1], d0, cE0.y);
            fma2(acc[i][2], d0, cE1.x); fma2(acc[i][3], d0, cE1.y);
            fma2(acc[i][0], d1, cO0.x); fma2(acc[i][1], d1, cO0.y);
            fma2(acc[i][2], d1, cO1.x); fma2(acc[i][3], d1, cO1.y);
        }
        cE0 = nE0; cE1 = nE1; cO0 = nO0; cO1 = nO1;
    }
#pragma unroll
    for (int i = 0; i < TN; i++)
#pragma unroll
        for (int j = 0; j < 4; j++)
            *reinterpret_cast<u64*>(C + (tbase + tr + 8 * i) * SCS + dc * 8 + 2 * j) = acc[i][j];
}

__global__ void __launch_bounds__(NT, 2)
ha_kernel(const float* __restrict__ gq, const float* __restrict__ gk, const float* __restrict__ gv,
          const float* __restrict__ cq_w, const float* __restrict__ cq_b,
          const float* __restrict__ ck_w, const float* __restrict__ ck_b,
          const float* __restrict__ cv_w, const float* __restrict__ cv_b,
          const float* __restrict__ w_qs, const float* __restrict__ w_ks, const float* __restrict__ w_vs,
          const float* __restrict__ proj_w, const float* __restrict__ proj_b,
          const float* __restrict__ fc_w, const float* __restrict__ fc_b,
          const float* __restrict__ ln_a, const float* __restrict__ ln_b,
          float* __restrict__ out)
{
    extern __shared__ float s[];
    const int tid  = threadIdx.x;
    const int w    = tid >> 5;       // 0..7
    const int lane = tid & 31;
    const size_t boff = (size_t)blockIdx.x * 8192;   // 64*128
    float* gatt = g_att + (size_t)blockIdx.x * 32 * 512;

    // ============ Phase 1: conv1d q/k/v (64->32, kw13, pad6), f32x2 over output pairs ============
    {
        const int co = tid >> 3;          // 0..31
        const int l0 = (tid & 7) * 16;    // 16 outputs per thread (8 pairs)
#pragma unroll 1
        for (int m = 0; m < 3; m++) {
            const float* xin = (m == 0 ? gq : m == 1 ? gk : gv) + boff;
            const float* cw  = (m == 0 ? cq_w : m == 1 ? ck_w : cv_w);
            const float* cb  = (m == 0 ? cq_b : m == 1 ? ck_b : cv_b);
            float* dst = s + OFF_QKV + m * 4224;
            __syncthreads();
            for (int i = tid; i < 64 * 12; i += NT) {
                int ci = i / 12, j = i % 12;
                s[OFF_IN + ci * 140 + (j < 6 ? j : j + 128)] = 0.f;
            }
            for (int i = tid; i < 8192; i += NT)
                s[OFF_IN + (i >> 7) * 140 + 6 + (i & 127)] = xin[i];

            u64 acc2[8];
            {
                float bv = __ldg(&cb[co]);
#pragma unroll
                for (int i = 0; i < 8; i++) acc2[i] = dup2(bv);   // each half = distinct output
            }
#pragma unroll 1
            for (int c = 0; c < 8; c++) {
                const int ci0 = c * 8;
                __syncthreads();
                // stage weight chunk: [co][ci 0..7][kk], tap stride 14
                for (int i = tid; i < 32 * 8 * 13; i += NT) {
                    int coi = i / 104, r = i % 104, ci = r / 13, kk = r % 13;
                    s[OFF_CW + (coi * 8 + ci) * 14 + kk] = cw[(coi * 64 + ci0 + ci) * 13 + kk];
                }
                __syncthreads();
#pragma unroll 1
                for (int ci = 0; ci < 8; ci++) {
                    const float* xp = s + OFF_IN + (ci0 + ci) * 140 + l0;  // xw[0]=x[l0-6]
                    float xw[28];
#pragma unroll
                    for (int q4 = 0; q4 < 7; q4++) {
                        float4 t4 = *(const float4*)(xp + q4 * 4);
                        xw[q4 * 4 + 0] = t4.x; xw[q4 * 4 + 1] = t4.y;
                        xw[q4 * 4 + 2] = t4.z; xw[q4 * 4 + 3] = t4.w;
                    }
                    u64 p[27];
#pragma unroll
                    for (int j = 0; j < 27; j++) p[j] = pk2(xw[j], xw[j + 1]);
                    const float* wr = s + OFF_CW + (co * 8 + ci) * 14;
                    float wk[13];
#pragma unroll
                    for (int t = 0; t < 6; t++) {
                        float lo, hi; upk2(lo, hi, lds64(wr + 2 * t));
                        wk[2 * t] = lo; wk[2 * t + 1] = hi;
                    }
                    wk[12] = wr[12];
#pragma unroll
                    for (int kk = 0; kk < 13; kk++) {
                        u64 wv = dup2(wk[kk]);
#pragma unroll
                        for (int i = 0; i < 8; i++)
                            fma2(acc2[i], p[kk + 2 * i], wv);
                    }
                }
            }
#pragma unroll
            for (int i = 0; i < 8; i++)
                *reinterpret_cast<u64*>(dst + co * QS + l0 + 2 * i) = acc2[i];
        }
    }

    // ============ Phase 2: per-head projections + attention, 4 passes of 4 heads ============
    {
        const int dc = lane & 3, tr = lane >> 2;
        const float inv_t = 0.08838834764831845f;   // 1/sqrt(128)
#pragma unroll 1
        for (int p = 0; p < 4; p++) {
            __syncthreads();
            // full gemm: g = w (0..7)
            {
                const int g = w, hl = g / 3, mm = g % 3;
                const float* Bsrc = (mm == 0 ? w_qs : mm == 1 ? w_ks : w_vs) + (p * 4 + hl) * 4096;
                gemm32<4>(s + OFF_QKV + mm * 4224, Bsrc,
                          s + OFF_SCR + hl * 3264 + mm * 1088, 0, tr, dc);
            }
            // half gemm: g = 8 + (w>>1) (8..11)
            {
                const int g = 8 + (w >> 1), hl = g / 3, mm = g % 3;
                const float* Bsrc = (mm == 0 ? w_qs : mm == 1 ? w_ks : w_vs) + (p * 4 + hl) * 4096;
                gemm32<2>(s + OFF_QKV + mm * 4224, Bsrc,
                          s + OFF_SCR + hl * 3264 + mm * 1088, (w & 1) * 16, tr, dc);
            }
            __syncthreads();
            // attention: 2 warps per head (4 heads)
            {
                const int hl = w >> 1, qbase = (w & 1) * 16;
                float* qh = s + OFF_SCR + hl * 3264;
                float* kh = qh + 1088;
                float* vh = qh + 2176;
                const float* qr0 = qh + (qbase + tr) * SCS;
                const float* qr1 = qh + (qbase + tr + 8) * SCS;
                u64 sc2[2][8];
#pragma unroll
                for (int i = 0; i < 2; i++)
#pragma unroll
                    for (int j = 0; j < 8; j++) sc2[i][j] = 0ull;
#pragma unroll 4
                for (int d2 = 0; d2 < 16; d2++) {
                    u64 q0 = lds64(qr0 + 2 * d2);
                    u64 q1 = lds64(qr1 + 2 * d2);
#pragma unroll
                    for (int j = 0; j < 8; j++) {
                        u64 kv = lds64(kh + (dc * 8 + j) * SCS + 2 * d2);
                        fma2(sc2[0][j], q0, kv);
                        fma2(sc2[1][j], q1, kv);
                    }
                }
                float sc[2][8];
#pragma unroll
                for (int i = 0; i < 2; i++)
#pragma unroll
                    for (int j = 0; j < 8; j++) {
                        float lo, hi; upk2(lo, hi, sc2[i][j]); sc[i][j] = lo + hi;
                    }
#pragma unroll
                for (int i = 0; i < 2; i++) {
                    float mx = -1e30f;
#pragma unroll
                    for (int j = 0; j < 8; j++) { sc[i][j] *= inv_t; mx = fmaxf(mx, sc[i][j]); }
                    mx = fmaxf(mx, __shfl_xor_sync(0xffffffffu, mx, 1));
                    mx = fmaxf(mx, __shfl_xor_sync(0xffffffffu, mx, 2));
                    float sum = 0.f;
#pragma unroll
                    for (int j = 0; j < 8; j++) { sc[i][j] = __expf(sc[i][j] - mx); sum += sc[i][j]; }
                    sum += __shfl_xor_sync(0xffffffffu, sum, 1);
                    sum += __shfl_xor_sync(0xffffffffu, sum, 2);
                    float inv = 1.f / sum;
#pragma unroll
                    for (int j = 0; j < 8; j++) sc[i][j] *= inv;
                }
                // attn -> qh rows (each lane its own rows)
#pragma unroll
                for (int i = 0; i < 2; i++)
#pragma unroll
                    for (int j = 0; j < 8; j++)
                        qh[(qbase + tr + 8 * i) * SCS + dc * 8 + j] = sc[i][j];
                __syncwarp();
                u64 av2[2][4];
#pragma unroll
                for (int i = 0; i < 2; i++)
#pragma unroll
                    for (int jp = 0; jp < 4; jp++) av2[i][jp] = 0ull;
#pragma unroll 4
                for (int k2 = 0; k2 < 32; k2++) {
                    u64 a0 = dup2(qr0[k2]);
                    u64 a1 = dup2(qr1[k2]);
#pragma unroll
                    for (int jp = 0; jp < 4; jp++) {
                        u64 vv = lds64(vh + k2 * SCS + dc * 8 + 2 * jp);
                        fma2(av2[0][jp], a0, vv);
                        fma2(av2[1][jp], a1, vv);
                    }
                }
                const int h = p * 4 + hl;
#pragma unroll
                for (int i = 0; i < 2; i++)
#pragma unroll
                    for (int jp = 0; jp < 4; jp++)
                        *reinterpret_cast<u64*>(gatt + (qbase + tr + 8 * i) * 512
                                                + h * 32 + dc * 8 + 2 * jp) = av2[i][jp];
            }
        }
    }

    // ============ Phase 3: stage ATT from gmem, proj with transposed weights ============
    __syncthreads();
    for (int i = tid; i < 16384; i += NT)
        s[OFF_ATT + (i >> 9) * 516 + (i & 511)] = gatt[i];
    for (int i = tid; i < 32 * 12; i += NT) {
        int t = i / 12, j = i % 12;
        s[OFF_Y + t * 140 + (j < 6 ? j : j + 128)] = 0.f;
    }
    __syncthreads();
    {
        const int tq = lane >> 4, ml = lane & 15;
        const int m0 = (w >> 2) * 64 + ml * 4;      // 4 m's per thread
        const int tb = (w & 3) * 8 + tq * 4;        // 4 t-rows per thread
        u64 acc[4][2];
#pragma unroll
        for (int t = 0; t < 4; t++) { acc[t][0] = 0ull; acc[t][1] = 0ull; }
        const float* bp0 = g_pwT + m0;
        ulonglong2 c0 = __ldg((const ulonglong2*)bp0);
        ulonglong2 c1 = __ldg((const ulonglong2*)(bp0 + 128));
#pragma unroll 2
        for (int j2 = 0; j2 < 256; j2++) {                   // full 512 reduction (2 j per iter)
            const int nj = (j2 < 255) ? (2 * j2 + 2) : 510;
            ulonglong2 n0 = __ldg((const ulonglong2*)(bp0 + nj * 128));
            ulonglong2 n1 = __ldg((const ulonglong2*)(bp0 + (nj + 1) * 128));
#pragma unroll
            for (int t = 0; t < 4; t++) {
                u64 a01 = lds64(s + OFF_ATT + (tb + t) * 516 + 2 * j2);
                float alo, ahi; upk2(alo, ahi, a01);
                u64 d0 = dup2(alo), d1 = dup2(ahi);
                fma2(acc[t][0], d0, c0.x); fma2(acc[t][1], d0, c0.y);
                fma2(acc[t][0], d1, c1.x); fma2(acc[t][1], d1, c1.y);
            }
            c0 = n0; c1 = n1;
        }
        float4 bb = __ldg((const float4*)(proj_b + m0));
#pragma unroll
        for (int t = 0; t < 4; t++) {
            float y0, y1, y2, y3;
            upk2(y0, y1, acc[t][0]);
            upk2(y2, y3, acc[t][1]);
            float* yp = s + OFF_Y + (tb + t) * 140 + 6 + m0;
            *reinterpret_cast<u64*>(yp)     = pk2(y0 + bb.x, y1 + bb.y);
            *reinterpret_cast<u64*>(yp + 2) = pk2(y2 + bb.z, y3 + bb.w);
        }
    }
    __syncthreads();

    // ============ Phase 4: final conv (32->64, kw13) + residual, f32x2 output pairs ============
    {
        const int co = (tid >> 3) * 2;    // this thread: co, co+1
        const int l0 = (tid & 7) * 16;
        u64 acc2[2][8];
        {
            float b0 = __ldg(&fc_b[co]), b1 = __ldg(&fc_b[co + 1]);
#pragma unroll
            for (int i = 0; i < 8; i++) { acc2[0][i] = dup2(b0); acc2[1][i] = dup2(b1); }
        }
#pragma unroll 1
        for (int c = 0; c < 4; c++) {
            const int ci0 = c * 8;
            __syncthreads();
            for (int i = tid; i < 64 * 8 * 13; i += NT) {
                int coi = i / 104, r = i % 104, ci = r / 13, kk = r % 13;
                s[OFF_FCW + (coi * 8 + ci) * 14 + kk] = fc_w[(coi * 32 + ci0 + ci) * 13 + kk];
            }
            __syncthreads();
#pragma unroll 1
            for (int ci = 0; ci < 8; ci++) {
                const float* xp = s + OFF_Y + (ci0 + ci) * 140 + l0;
                float xw[28];
#pragma unroll
                for (int q4 = 0; q4 < 7; q4++) {
                    float4 t4 = *(const float4*)(xp + q4 * 4);
                    xw[q4 * 4 + 0] = t4.x; xw[q4 * 4 + 1] = t4.y;
                    xw[q4 * 4 + 2] = t4.z; xw[q4 * 4 + 3] = t4.w;
                }
                u64 p[27];
#pragma unroll
                for (int j = 0; j < 27; j++) p[j] = pk2(xw[j], xw[j + 1]);
#pragma unroll
                for (int c2 = 0; c2 < 2; c2++) {
                    const float* wr = s + OFF_FCW + ((co + c2) * 8 + ci) * 14;
                    float wk[13];
#pragma unroll
                    for (int t = 0; t < 6; t++) {
                        float lo, hi; upk2(lo, hi, lds64(wr + 2 * t));
                        wk[2 * t] = lo; wk[2 * t + 1] = hi;
                    }
                    wk[12] = wr[12];
#pragma unroll
                    for (int kk = 0; kk < 13; kk++) {
                        u64 wv = dup2(wk[kk]);
#pragma unroll
                        for (int i = 0; i < 8; i++)
                            fma2(acc2[c2][i], p[kk + 2 * i], wv);
                    }
                }
            }
        }
        const float* qres = gq + boff;
#pragma unroll
        for (int c2 = 0; c2 < 2; c2++) {
            float* zp = s + OFF_Z + (co + c2) * 128 + l0;
#pragma unroll
            for (int i2 = 0; i2 < 4; i2++) {
                ulonglong2 r = __ldg((const ulonglong2*)(qres + (co + c2) * 128 + l0 + i2 * 4));
                *reinterpret_cast<u64*>(zp + i2 * 4)     = add2(acc2[c2][i2 * 2], r.x);
                *reinterpret_cast<u64*>(zp + i2 * 4 + 2) = add2(acc2[c2][i2 * 2 + 1], r.y);
            }
        }
    }
    __syncthreads();

    // ============ Phase 5: LayerNorm (unbiased std, /(sigma+eps)) ============
    {
#pragma unroll
        for (int it = 0; it < 8; it++) {
            int r = w + it * 8;
            const float* zr = s + OFF_Z + r * 128;
            float v0 = zr[lane], v1 = zr[lane + 32], v2 = zr[lane + 64], v3 = zr[lane + 96];
            float sm = v0 + v1 + v2 + v3;
#pragma unroll
            for (int o = 16; o > 0; o >>= 1) sm += __shfl_xor_sync(0xffffffffu, sm, o);
            float mu = sm * (1.f / 128.f);
            float d0 = v0 - mu, d1 = v1 - mu, d2 = v2 - mu, d3 = v3 - mu;
            float s2 = d0 * d0 + d1 * d1 + d2 * d2 + d3 * d3;
#pragma unroll
            for (int o = 16; o > 0; o >>= 1) s2 += __shfl_xor_sync(0xffffffffu, s2, o);
            float sigma = sqrtf(s2 * (1.f / 127.f));
            float inv = 1.f / (sigma + 1e-3f);
            float* orow = out + boff + r * 128;
            orow[lane]      = d0 * inv * __ldg(&ln_a[lane])      + __ldg(&ln_b[lane]);
            orow[lane + 32] = d1 * inv * __ldg(&ln_a[lane + 32]) + __ldg(&ln_b[lane + 32]);
            orow[lane + 64] = d2 * inv * __ldg(&ln_a[lane + 64]) + __ldg(&ln_b[lane + 64]);
            orow[lane + 96] = d3 * inv * __ldg(&ln_a[lane + 96]) + __ldg(&ln_b[lane + 96]);
        }
    }
}

extern "C" void kernel_launch(void* const* d_in, const int* in_sizes, int n_in,
                              void* d_out, int out_size)
{
    const float* q      = (const float*)d_in[0];
    const float* k      = (const float*)d_in[1];
    const float* v      = (const float*)d_in[2];
    const float* cq_w   = (const float*)d_in[3];
    const float* cq_b   = (const float*)d_in[4];
    const float* ck_w   = (const float*)d_in[5];
    const float* ck_b   = (const float*)d_in[6];
    const float* cv_w   = (const float*)d_in[7];
    const float* cv_b   = (const float*)d_in[8];
    const float* w_qs   = (const float*)d_in[9];
    const float* w_ks   = (const float*)d_in[10];
    const float* w_vs   = (const float*)d_in[11];
    const float* proj_w = (const float*)d_in[12];
    const float* proj_b = (const float*)d_in[13];
    const float* fc_w   = (const float*)d_in[14];
    const float* fc_b   = (const float*)d_in[15];
    const float* ln_a   = (const float*)d_in[16];
    const float* ln_b   = (const float*)d_in[17];
    float* outp = (float*)d_out;

    const int B = in_sizes[0] / (64 * 128);

    transpose_pw_kernel<<<128, 512>>>(proj_w);

    cudaFuncSetAttribute(ha_kernel, cudaFuncAttributeMaxDynamicSharedMemorySize, SMEM_BYTES);
    // Force max shared-memory carveout so TWO 103KB CTAs fit per SM (228KB carveout).
    cudaFuncSetAttribute(ha_kernel, cudaFuncAttributePreferredSharedMemoryCarveout, 100);
    ha_kernel<<<B, NT, SMEM_BYTES>>>(q, k, v, cq_w, cq_b, ck_w, ck_b, cv_w, cv_b,
                                     w_qs, w_ks, w_vs, proj_w, proj_b, fc_w, fc_b,
                                     ln_a, ln_b, outp);
}

// round 10
// speedup vs baseline: 1.2517x; 1.2517x over previous
#include <cuda_runtime.h>

// B=2048, DKV=64, L=128, H=16, DT=32, KW=13, PAD=6
#define NT 256
#define QS 132     // qb/kb/vb row stride
#define SCS 34     // qh/kh/vh scratch row stride
#define ATS 516    // att smem row stride
#define WR 160     // swizzled conv-window row stride (40 chunks of 16B)

// physical float offset of logical float f within a swizzled WR row:
// chunk skew c -> c + (c>>3) kills the 64B-stride 4-way bank conflict
#define SWZ(f) ((((((f) >> 2) + ((f) >> 5))) << 2) | ((f) & 3))

// shared layout (floats), peak 26496 (=105,984B) -> 2 CTAs/SM
#define OFF_QKV 0            // 3*32*132 = 12672            [P1 out, P2 A]
#define OFF_IN  12672        // 64*160 = 10240 -> 22912      [P1, swizzled rows]
#define OFF_CW  22912        // 32*8*14 = 3584 -> 26496      [P1 weight chunk]
#define OFF_SCR 12672        // 4 heads*3*32*34 = 13056 -> 25728 [P2]
#define OFF_Y   0            // 32*160 = 5120                [P3 -> P4, swizzled rows]
#define OFF_ATT 5120         // 32*516 = 16512 -> 21632      [P3]
#define OFF_FCW 5120         // 64*8*14 = 7168 -> 12288      [P4 chunk, over dead ATT]
#define OFF_Z   12288        // 8192 -> 20480                [P4 -> P5]
#define SMEM_FLOATS 26496
#define SMEM_BYTES (SMEM_FLOATS * 4)

typedef unsigned long long u64;

// gmem scratch (allowed: __device__ globals, no allocation)
__device__ float g_att[2048 * 32 * 512];   // per-batch attention concat
__device__ float g_pwT[512 * 128];         // proj_w transposed: pwT[j][m]

__device__ __forceinline__ u64 pk2(float lo, float hi) {
    u64 r; asm("mov.b64 %0,{%1,%2};" : "=l"(r) : "f"(lo), "f"(hi)); return r;
}
__device__ __forceinline__ u64 dup2(float x) { return pk2(x, x); }
__device__ __forceinline__ void upk2(float& lo, float& hi, u64 v) {
    asm("mov.b64 {%0,%1},%2;" : "=f"(lo), "=f"(hi) : "l"(v));
}
__device__ __forceinline__ void fma2(u64& d, u64 a, u64 b) {
    asm("fma.rn.f32x2 %0,%1,%2,%0;" : "+l"(d) : "l"(a), "l"(b));
}
__device__ __forceinline__ u64 lds64(const float* p) {
    return *reinterpret_cast<const u64*>(p);
}

__global__ void transpose_pw_kernel(const float* __restrict__ pw) {
    int idx = blockIdx.x * 512 + threadIdx.x;   // 65536 total
    int j = idx >> 7, m = idx & 127;
    g_pwT[idx] = pw[m * 512 + j];
}

// One warp: C(32x32) = A(32x128) @ B(128x32); A smem (stride QS, lds64 l-pairs),
// B streamed from gmem (dedup'd lines), C to smem (stride SCS).
template<int TN>
__device__ __forceinline__ void gemm32(const float* __restrict__ A,
                                       const float* __restrict__ Bg,
                                       float* __restrict__ C,
                                       int tbase, int tr, int dc)
{
    u64 acc[TN][4];
#pragma unroll
    for (int i = 0; i < TN; i++)
#pragma unroll
        for (int j = 0; j < 4; j++) acc[i][j] = 0ull;
    const float* Ar[TN];
#pragma unroll
    for (int i = 0; i < TN; i++) Ar[i] = A + (tbase + tr + 8 * i) * QS;

    const float* bp = Bg + dc * 8;
    ulonglong2 cE0 = __ldg((const ulonglong2*)bp);
    ulonglong2 cE1 = __ldg((const ulonglong2*)(bp + 4));
    ulonglong2 cO0 = __ldg((const ulonglong2*)(bp + 32));
    ulonglong2 cO1 = __ldg((const ulonglong2*)(bp + 36));
#pragma unroll 2
    for (int l2 = 0; l2 < 64; l2++) {
        const int nb = (l2 < 63) ? (2 * l2 + 2) : 126;
        ulonglong2 nE0 = __ldg((const ulonglong2*)(bp + nb * 32));
        ulonglong2 nE1 = __ldg((const ulonglong2*)(bp + nb * 32 + 4));
        ulonglong2 nO0 = __ldg((const ulonglong2*)(bp + nb * 32 + 32));
        ulonglong2 nO1 = __ldg((const ulonglong2*)(bp + nb * 32 + 36));
#pragma unroll
        for (int i = 0; i < TN; i++) {
            u64 a01 = lds64(Ar[i] + 2 * l2);
            float alo, ahi; upk2(alo, ahi, a01);
            u64 d0 = dup2(alo), d1 = dup2(ahi);
            fma2(acc[i][0], d0, cE0.x); fma2(acc[i][1], d0, cE0.y);
            fma2(acc[i][2], d0, cE1.x); fma2(acc[i][3], d0, cE1.y);
            fma2(acc[i][0], d1, cO0.x); fma2(acc[i][1], d1, cO0.y);
            fma2(acc[i][2], d1, cO1.x); fma2(acc[i][3], d1, cO1.y);
        }
        cE0 = nE0; cE1 = nE1; cO0 = nO0; cO1 = nO1;
    }
#pragma unroll
    for (int i = 0; i < TN; i++)
#pragma unroll
        for (int j = 0; j < 4; j++)
            *reinterpret_cast<u64*>(C + (tbase + tr + 8 * i) * SCS + dc * 8 + 2 * j) = acc[i][j];
}

__global__ void __launch_bounds__(NT, 2)
ha_kernel(const float* __restrict__ gq, const float* __restrict__ gk, const float* __restrict__ gv,
          const float* __restrict__ cq_w, const float* __restrict__ cq_b,
          const float* __restrict__ ck_w, const float* __restrict__ ck_b,
          const float* __restrict__ cv_w, const float* __restrict__ cv_b,
          const float* __restrict__ w_qs, const float* __restrict__ w_ks, const float* __restrict__ w_vs,
          const float* __restrict__ proj_w, const float* __restrict__ proj_b,
          const float* __restrict__ fc_w, const float* __restrict__ fc_b,
          const float* __restrict__ ln_a, const float* __restrict__ ln_b,
          float* __restrict__ out)
{
    extern __shared__ float s[];
    const int tid  = threadIdx.x;
    const int w    = tid >> 5;       // 0..7
    const int lane = tid & 31;
    const size_t boff = (size_t)blockIdx.x * 8192;   // 64*128
    float* gatt = g_att + (size_t)blockIdx.x * 32 * 512;

    // ============ Phase 1: conv1d q/k/v (64->32, kw13, pad6), scalar FFMA, swizzled window ============
    {
        const int co = tid >> 3;          // 0..31
        const int l0 = (tid & 7) * 16;    // 16 outputs per thread
        const int cb = l0 >> 2;           // base 16B-chunk of window
#pragma unroll 1
        for (int m = 0; m < 3; m++) {
            const float* xin = (m == 0 ? gq : m == 1 ? gk : gv) + boff;
            const float* cw  = (m == 0 ? cq_w : m == 1 ? ck_w : cv_w);
            const float* cb_ = (m == 0 ? cq_b : m == 1 ? ck_b : cv_b);
            float* dst = s + OFF_QKV + m * 4224;
            __syncthreads();
            for (int i = tid; i < 64 * 12; i += NT) {
                int ci = i / 12, j = i % 12;
                int f = (j < 6) ? j : j + 128;
                s[OFF_IN + ci * WR + SWZ(f)] = 0.f;
            }
            for (int i = tid; i < 8192; i += NT) {
                int f = 6 + (i & 127);
                s[OFF_IN + (i >> 7) * WR + SWZ(f)] = xin[i];
            }

            float acc[16];
            {
                float bv = __ldg(&cb_[co]);
#pragma unroll
                for (int i = 0; i < 16; i++) acc[i] = bv;
            }
#pragma unroll 1
            for (int c = 0; c < 8; c++) {
                const int ci0 = c * 8;
                __syncthreads();
                // stage weight chunk: [co][ci 0..7][kk], tap stride 14
                for (int i = tid; i < 32 * 8 * 13; i += NT) {
                    int coi = i / 104, r = i % 104, ci = r / 13, kk = r % 13;
                    s[OFF_CW + (coi * 8 + ci) * 14 + kk] = cw[(coi * 64 + ci0 + ci) * 13 + kk];
                }
                __syncthreads();
#pragma unroll 1
                for (int ci = 0; ci < 8; ci++) {
                    const float* xp = s + OFF_IN + (ci0 + ci) * WR;
                    float xw[28];
#pragma unroll
                    for (int q4 = 0; q4 < 7; q4++) {
                        int cc = cb + q4;
                        float4 t4 = *(const float4*)(xp + ((cc + (cc >> 3)) << 2));
                        xw[q4 * 4 + 0] = t4.x; xw[q4 * 4 + 1] = t4.y;
                        xw[q4 * 4 + 2] = t4.z; xw[q4 * 4 + 3] = t4.w;
                    }
                    const float* wr = s + OFF_CW + (co * 8 + ci) * 14;
                    float wk[13];
#pragma unroll
                    for (int t = 0; t < 6; t++) {
                        float lo, hi; upk2(lo, hi, lds64(wr + 2 * t));
                        wk[2 * t] = lo; wk[2 * t + 1] = hi;
                    }
                    wk[12] = wr[12];
#pragma unroll
                    for (int kk = 0; kk < 13; kk++) {
                        float wv = wk[kk];
#pragma unroll
                        for (int i = 0; i < 16; i++)
                            acc[i] = fmaf(xw[i + kk], wv, acc[i]);
                    }
                }
            }
#pragma unroll
            for (int q4 = 0; q4 < 4; q4++)
                *(float4*)(dst + co * QS + l0 + q4 * 4) =
                    make_float4(acc[q4 * 4], acc[q4 * 4 + 1], acc[q4 * 4 + 2], acc[q4 * 4 + 3]);
        }
    }

    // ============ Phase 2: per-head projections + attention, 4 passes of 4 heads ============
    {
        const int dc = lane & 3, tr = lane >> 2;
        const float inv_t = 0.08838834764831845f;   // 1/sqrt(128)
#pragma unroll 1
        for (int p = 0; p < 4; p++) {
            __syncthreads();
            // full gemm: g = w (0..7)
            {
                const int g = w, hl = g / 3, mm = g % 3;
                const float* Bsrc = (mm == 0 ? w_qs : mm == 1 ? w_ks : w_vs) + (p * 4 + hl) * 4096;
                gemm32<4>(s + OFF_QKV + mm * 4224, Bsrc,
                          s + OFF_SCR + hl * 3264 + mm * 1088, 0, tr, dc);
            }
            // half gemm: g = 8 + (w>>1) (8..11)
            {
                const int g = 8 + (w >> 1), hl = g / 3, mm = g % 3;
                const float* Bsrc = (mm == 0 ? w_qs : mm == 1 ? w_ks : w_vs) + (p * 4 + hl) * 4096;
                gemm32<2>(s + OFF_QKV + mm * 4224, Bsrc,
                          s + OFF_SCR + hl * 3264 + mm * 1088, (w & 1) * 16, tr, dc);
            }
            __syncthreads();
            // attention: 2 warps per head (4 heads)
            {
                const int hl = w >> 1, qbase = (w & 1) * 16;
                float* qh = s + OFF_SCR + hl * 3264;
                float* kh = qh + 1088;
                float* vh = qh + 2176;
                const float* qr0 = qh + (qbase + tr) * SCS;
                const float* qr1 = qh + (qbase + tr + 8) * SCS;
                u64 sc2[2][8];
#pragma unroll
                for (int i = 0; i < 2; i++)
#pragma unroll
                    for (int j = 0; j < 8; j++) sc2[i][j] = 0ull;
#pragma unroll 4
                for (int d2 = 0; d2 < 16; d2++) {
                    u64 q0 = lds64(qr0 + 2 * d2);
                    u64 q1 = lds64(qr1 + 2 * d2);
#pragma unroll
                    for (int j = 0; j < 8; j++) {
                        u64 kv = lds64(kh + (dc * 8 + j) * SCS + 2 * d2);
                        fma2(sc2[0][j], q0, kv);
                        fma2(sc2[1][j], q1, kv);
                    }
                }
                float sc[2][8];
#pragma unroll
                for (int i = 0; i < 2; i++)
#pragma unroll
                    for (int j = 0; j < 8; j++) {
                        float lo, hi; upk2(lo, hi, sc2[i][j]); sc[i][j] = lo + hi;
                    }
#pragma unroll
                for (int i = 0; i < 2; i++) {
                    float mx = -1e30f;
#pragma unroll
                    for (int j = 0; j < 8; j++) { sc[i][j] *= inv_t; mx = fmaxf(mx, sc[i][j]); }
                    mx = fmaxf(mx, __shfl_xor_sync(0xffffffffu, mx, 1));
                    mx = fmaxf(mx, __shfl_xor_sync(0xffffffffu, mx, 2));
                    float sum = 0.f;
#pragma unroll
                    for (int j = 0; j < 8; j++) { sc[i][j] = __expf(sc[i][j] - mx); sum += sc[i][j]; }
                    sum += __shfl_xor_sync(0xffffffffu, sum, 1);
                    sum += __shfl_xor_sync(0xffffffffu, sum, 2);
                    float inv = 1.f / sum;
#pragma unroll
                    for (int j = 0; j < 8; j++) sc[i][j] *= inv;
                }
                // attn -> qh rows (each lane its own rows)
#pragma unroll
                for (int i = 0; i < 2; i++)
#pragma unroll
                    for (int j = 0; j < 8; j++)
                        qh[(qbase + tr + 8 * i) * SCS + dc * 8 + j] = sc[i][j];
                __syncwarp();
                u64 av2[2][4];
#pragma unroll
                for (int i = 0; i < 2; i++)
#pragma unroll
                    for (int jp = 0; jp < 4; jp++) av2[i][jp] = 0ull;
#pragma unroll 4
                for (int k2 = 0; k2 < 32; k2++) {
                    u64 a0 = dup2(qr0[k2]);
                    u64 a1 = dup2(qr1[k2]);
#pragma unroll
                    for (int jp = 0; jp < 4; jp++) {
                        u64 vv = lds64(vh + k2 * SCS + dc * 8 + 2 * jp);
                        fma2(av2[0][jp], a0, vv);
                        fma2(av2[1][jp], a1, vv);
                    }
                }
                const int h = p * 4 + hl;
#pragma unroll
                for (int i = 0; i < 2; i++)
#pragma unroll
                    for (int jp = 0; jp < 4; jp++)
                        *reinterpret_cast<u64*>(gatt + (qbase + tr + 8 * i) * 512
                                                + h * 32 + dc * 8 + 2 * jp) = av2[i][jp];
            }
        }
    }

    // ============ Phase 3: stage ATT from gmem, proj with transposed weights ============
    __syncthreads();
    for (int i = tid; i < 16384; i += NT)
        s[OFF_ATT + (i >> 9) * 516 + (i & 511)] = gatt[i];
    for (int i = tid; i < 32 * 12; i += NT) {
        int t = i / 12, j = i % 12;
        int f = (j < 6) ? j : j + 128;
        s[OFF_Y + t * WR + SWZ(f)] = 0.f;
    }
    __syncthreads();
    {
        const int tq = lane >> 4, ml = lane & 15;
        const int m0 = (w >> 2) * 64 + ml * 4;      // 4 m's per thread
        const int tb = (w & 3) * 8 + tq * 4;        // 4 t-rows per thread
        u64 acc[4][2];
#pragma unroll
        for (int t = 0; t < 4; t++) { acc[t][0] = 0ull; acc[t][1] = 0ull; }
        const float* bp0 = g_pwT + m0;
        ulonglong2 c0 = __ldg((const ulonglong2*)bp0);
        ulonglong2 c1 = __ldg((const ulonglong2*)(bp0 + 128));
#pragma unroll 2
        for (int j2 = 0; j2 < 256; j2++) {                   // full 512 reduction (2 j per iter)
            const int nj = (j2 < 255) ? (2 * j2 + 2) : 510;
            ulonglong2 n0 = __ldg((const ulonglong2*)(bp0 + nj * 128));
            ulonglong2 n1 = __ldg((const ulonglong2*)(bp0 + (nj + 1) * 128));
#pragma unroll
            for (int t = 0; t < 4; t++) {
                u64 a01 = lds64(s + OFF_ATT + (tb + t) * 516 + 2 * j2);
                float alo, ahi; upk2(alo, ahi, a01);
                u64 d0 = dup2(alo), d1 = dup2(ahi);
                fma2(acc[t][0], d0, c0.x); fma2(acc[t][1], d0, c0.y);
                fma2(acc[t][0], d1, c1.x); fma2(acc[t][1], d1, c1.y);
            }
            c0 = n0; c1 = n1;
        }
        float4 bb = __ldg((const float4*)(proj_b + m0));
#pragma unroll
        for (int t = 0; t < 4; t++) {
            float y0, y1, y2, y3;
            upk2(y0, y1, acc[t][0]);
            upk2(y2, y3, acc[t][1]);
            float* yrow = s + OFF_Y + (tb + t) * WR;
            const int f0 = 6 + m0, c0i = f0 >> 2;           // f0 = 2 mod 4: floats 2,3 of chunk
            const int f1 = 8 + m0, c1i = f1 >> 2;           // f1 = 0 mod 4: floats 0,1 of chunk
            *reinterpret_cast<u64*>(yrow + ((c0i + (c0i >> 3)) << 2) + 2) = pk2(y0 + bb.x, y1 + bb.y);
            *reinterpret_cast<u64*>(yrow + ((c1i + (c1i >> 3)) << 2))     = pk2(y2 + bb.z, y3 + bb.w);
        }
    }
    __syncthreads();

    // ============ Phase 4: final conv (32->64, kw13) + residual, swizzled window ============
    {
        const int co = (tid >> 3) * 2;    // this thread: co, co+1
        const int l0 = (tid & 7) * 16;
        const int cb = l0 >> 2;
        float acc[2][16];
        {
            float b0 = __ldg(&fc_b[co]), b1 = __ldg(&fc_b[co + 1]);
#pragma unroll
            for (int i = 0; i < 16; i++) { acc[0][i] = b0; acc[1][i] = b1; }
        }
#pragma unroll 1
        for (int c = 0; c < 4; c++) {
            const int ci0 = c * 8;
            __syncthreads();
            for (int i = tid; i < 64 * 8 * 13; i += NT) {
                int coi = i / 104, r = i % 104, ci = r / 13, kk = r % 13;
                s[OFF_FCW + (coi * 8 + ci) * 14 + kk] = fc_w[(coi * 32 + ci0 + ci) * 13 + kk];
            }
            __syncthreads();
#pragma unroll 1
            for (int ci = 0; ci < 8; ci++) {
                const float* xp = s + OFF_Y + (ci0 + ci) * WR;
                float xw[28];
#pragma unroll
                for (int q4 = 0; q4 < 7; q4++) {
                    int cc = cb + q4;
                    float4 t4 = *(const float4*)(xp + ((cc + (cc >> 3)) << 2));
                    xw[q4 * 4 + 0] = t4.x; xw[q4 * 4 + 1] = t4.y;
                    xw[q4 * 4 + 2] = t4.z; xw[q4 * 4 + 3] = t4.w;
                }
#pragma unroll
                for (int c2 = 0; c2 < 2; c2++) {
                    const float* wr = s + OFF_FCW + ((co + c2) * 8 + ci) * 14;
                    float wk[13];
#pragma unroll
                    for (int t = 0; t < 6; t++) {
                        float lo, hi; upk2(lo, hi, lds64(wr + 2 * t));
                        wk[2 * t] = lo; wk[2 * t + 1] = hi;
                    }
                    wk[12] = wr[12];
#pragma unroll
                    for (int kk = 0; kk < 13; kk++) {
                        float wv = wk[kk];
#pragma unroll
                        for (int i = 0; i < 16; i++)
                            acc[c2][i] = fmaf(xw[i + kk], wv, acc[c2][i]);
                    }
                }
            }
        }
        const float* qres = gq + boff;
#pragma unroll
        for (int c2 = 0; c2 < 2; c2++)
#pragma unroll
            for (int q4 = 0; q4 < 4; q4++) {
                float4 r = __ldg((const float4*)(qres + (co + c2) * 128 + l0 + q4 * 4));
                *(float4*)(s + OFF_Z + (co + c2) * 128 + l0 + q4 * 4) =
                    make_float4(acc[c2][q4 * 4] + r.x, acc[c2][q4 * 4 + 1] + r.y,
                                acc[c2][q4 * 4 + 2] + r.z, acc[c2][q4 * 4 + 3] + r.w);
            }
    }
    __syncthreads();

    // ============ Phase 5: LayerNorm (unbiased std, /(sigma+eps)) ============
    {
#pragma unroll
        for (int it = 0; it < 8; it++) {
            int r = w + it * 8;
            const float* zr = s + OFF_Z + r * 128;
            float v0 = zr[lane], v1 = zr[lane + 32], v2 = zr[lane + 64], v3 = zr[lane + 96];
            float sm = v0 + v1 + v2 + v3;
#pragma unroll
            for (int o = 16; o > 0; o >>= 1) sm += __shfl_xor_sync(0xffffffffu, sm, o);
            float mu = sm * (1.f / 128.f);
            float d0 = v0 - mu, d1 = v1 - mu, d2 = v2 - mu, d3 = v3 - mu;
            float s2 = d0 * d0 + d1 * d1 + d2 * d2 + d3 * d3;
#pragma unroll
            for (int o = 16; o > 0; o >>= 1) s2 += __shfl_xor_sync(0xffffffffu, s2, o);
            float sigma = sqrtf(s2 * (1.f / 127.f));
            float inv = 1.f / (sigma + 1e-3f);
            float* orow = out + boff + r * 128;
            orow[lane]      = d0 * inv * __ldg(&ln_a[lane])      + __ldg(&ln_b[lane]);
            orow[lane + 32] = d1 * inv * __ldg(&ln_a[lane + 32]) + __ldg(&ln_b[lane + 32]);
            orow[lane + 64] = d2 * inv * __ldg(&ln_a[lane + 64]) + __ldg(&ln_b[lane + 64]);
            orow[lane + 96] = d3 * inv * __ldg(&ln_a[lane + 96]) + __ldg(&ln_b[lane + 96]);
        }
    }
}

extern "C" void kernel_launch(void* const* d_in, const int* in_sizes, int n_in,
                              void* d_out, int out_size)
{
    const float* q      = (const float*)d_in[0];
    const float* k      = (const float*)d_in[1];
    const float* v      = (const float*)d_in[2];
    const float* cq_w   = (const float*)d_in[3];
    const float* cq_b   = (const float*)d_in[4];
    const float* ck_w   = (const float*)d_in[5];
    const float* ck_b   = (const float*)d_in[6];
    const float* cv_w   = (const float*)d_in[7];
    const float* cv_b   = (const float*)d_in[8];
    const float* w_qs   = (const float*)d_in[9];
    const float* w_ks   = (const float*)d_in[10];
    const float* w_vs   = (const float*)d_in[11];
    const float* proj_w = (const float*)d_in[12];
    const float* proj_b = (const float*)d_in[13];
    const float* fc_w   = (const float*)d_in[14];
    const float* fc_b   = (const float*)d_in[15];
    const float* ln_a   = (const float*)d_in[16];
    const float* ln_b   = (const float*)d_in[17];
    float* outp = (float*)d_out;

    const int B = in_sizes[0] / (64 * 128);

    transpose_pw_kernel<<<128, 512>>>(proj_w);

    cudaFuncSetAttribute(ha_kernel, cudaFuncAttributeMaxDynamicSharedMemorySize, SMEM_BYTES);
    cudaFuncSetAttribute(ha_kernel, cudaFuncAttributePreferredSharedMemoryCarveout, 100);
    ha_kernel<<<B, NT, SMEM_BYTES>>>(q, k, v, cq_w, cq_b, ck_w, ck_b, cv_w, cv_b,
                                     w_qs, w_ks, w_vs, proj_w, proj_b, fc_w, fc_b,
                                     ln_a, ln_b, outp);
}

// round 11
// speedup vs baseline: 1.3355x; 1.0669x over previous
#include <cuda_runtime.h>

// B=2048, DKV=64, L=128, H=16, DT=32, KW=13, PAD=6
#define NT 256
#define QS 132     // qb/kb/vb row stride
#define SCS 34     // qh/kh/vh scratch row stride
#define WR 160     // swizzled conv-window row stride (40 chunks of 16B)

// chunk skew c -> c + (c>>3) kills 64B-stride bank conflicts
#define SWZ(f) ((((((f) >> 2) + ((f) >> 5))) << 2) | ((f) & 3))

// shared layout (floats), peak 26496 (=105,984B) -> 2 CTAs/SM
#define OFF_QKV 0            // 3*32*132 = 12672            [P1 out, P2 A]
#define OFF_IN  12672        // 64*160 = 10240 -> 22912      [P1, swizzled rows]
#define OFF_CW  22912        // 16*8*28 = 3584 -> 26496      [P1 paired weight chunk]
#define OFF_SCR 12672        // 4 heads*3*32*34 = 13056 -> 25728 [P2]
#define OFF_Y   0            // 32*160 = 5120                [P3 -> P4, swizzled rows]
#define OFF_ATT 5120         // 32*516 = 16512 -> 21632      [P3]
#define OFF_FCW 5120         // 16*8*56 = 7168 -> 12288      [P4 paired chunk, over dead ATT]
#define OFF_Z   12288        // 8192 -> 20480                [P4 -> P5]
#define SMEM_FLOATS 26496
#define SMEM_BYTES (SMEM_FLOATS * 4)

typedef unsigned long long u64;

__device__ float g_att[2048 * 32 * 512];   // per-batch attention concat
__device__ float g_pwT[512 * 128];         // proj_w transposed: pwT[j][m]

__device__ __forceinline__ u64 pk2(float lo, float hi) {
    u64 r; asm("mov.b64 %0,{%1,%2};" : "=l"(r) : "f"(lo), "f"(hi)); return r;
}
__device__ __forceinline__ u64 dup2(float x) { return pk2(x, x); }
__device__ __forceinline__ void upk2(float& lo, float& hi, u64 v) {
    asm("mov.b64 {%0,%1},%2;" : "=f"(lo), "=f"(hi) : "l"(v));
}
__device__ __forceinline__ void fma2(u64& d, u64 a, u64 b) {
    asm("fma.rn.f32x2 %0,%1,%2,%0;" : "+l"(d) : "l"(a), "l"(b));
}
__device__ __forceinline__ u64 lds64(const float* p) {
    return *reinterpret_cast<const u64*>(p);
}

__global__ void transpose_pw_kernel(const float* __restrict__ pw) {
    int idx = blockIdx.x * 512 + threadIdx.x;   // 65536 total
    int j = idx >> 7, m = idx & 127;
    g_pwT[idx] = pw[m * 512 + j];
}

// One warp: C(32x32) = A(32x128) @ B(128x32); A smem (stride QS, lds64 l-pairs),
// B streamed from gmem, C to smem (stride SCS).
template<int TN>
__device__ __forceinline__ void gemm32(const float* __restrict__ A,
                                       const float* __restrict__ Bg,
                                       float* __restrict__ C,
                                       int tbase, int tr, int dc)
{
    u64 acc[TN][4];
#pragma unroll
    for (int i = 0; i < TN; i++)
#pragma unroll
        for (int j = 0; j < 4; j++) acc[i][j] = 0ull;
    const float* Ar[TN];
#pragma unroll
    for (int i = 0; i < TN; i++) Ar[i] = A + (tbase + tr + 8 * i) * QS;

    const float* bp = Bg + dc * 8;
    ulonglong2 cE0 = __ldg((const ulonglong2*)bp);
    ulonglong2 cE1 = __ldg((const ulonglong2*)(bp + 4));
    ulonglong2 cO0 = __ldg((const ulonglong2*)(bp + 32));
    ulonglong2 cO1 = __ldg((const ulonglong2*)(bp + 36));
#pragma unroll 2
    for (int l2 = 0; l2 < 64; l2++) {
        const int nb = (l2 < 63) ? (2 * l2 + 2) : 126;
        ulonglong2 nE0 = __ldg((const ulonglong2*)(bp + nb * 32));
        ulonglong2 nE1 = __ldg((const ulonglong2*)(bp + nb * 32 + 4));
        ulonglong2 nO0 = __ldg((const ulonglong2*)(bp + nb * 32 + 32));
        ulonglong2 nO1 = __ldg((const ulonglong2*)(bp + nb * 32 + 36));
#pragma unroll
        for (int i = 0; i < TN; i++) {
            u64 a01 = lds64(Ar[i] + 2 * l2);
            float alo, ahi; upk2(alo, ahi, a01);
            u64 d0 = dup2(alo), d1 = dup2(ahi);
            fma2(acc[i][0], d0, cE0.x); fma2(acc[i][1], d0, cE0.y);
            fma2(acc[i][2], d0, cE1.x); fma2(acc[i][3], d0, cE1.y);
            fma2(acc[i][0], d1, cO0.x); fma2(acc[i][1], d1, cO0.y);
            fma2(acc[i][2], d1, cO1.x); fma2(acc[i][3], d1, cO1.y);
        }
        cE0 = nE0; cE1 = nE1; cO0 = nO0; cO1 = nO1;
    }
#pragma unroll
    for (int i = 0; i < TN; i++)
#pragma unroll
        for (int j = 0; j < 4; j++)
            *reinterpret_cast<u64*>(C + (tbase + tr + 8 * i) * SCS + dc * 8 + 2 * j) = acc[i][j];
}

__global__ void __launch_bounds__(NT, 2)
ha_kernel(const float* __restrict__ gq, const float* __restrict__ gk, const float* __restrict__ gv,
          const float* __restrict__ cq_w, const float* __restrict__ cq_b,
          const float* __restrict__ ck_w, const float* __restrict__ ck_b,
          const float* __restrict__ cv_w, const float* __restrict__ cv_b,
          const float* __restrict__ w_qs, const float* __restrict__ w_ks, const float* __restrict__ w_vs,
          const float* __restrict__ proj_w, const float* __restrict__ proj_b,
          const float* __restrict__ fc_w, const float* __restrict__ fc_b,
          const float* __restrict__ ln_a, const float* __restrict__ ln_b,
          float* __restrict__ out)
{
    extern __shared__ float s[];
    const int tid  = threadIdx.x;
    const int w    = tid >> 5;       // 0..7
    const int lane = tid & 31;
    const size_t boff = (size_t)blockIdx.x * 8192;   // 64*128
    float* gatt = g_att + (size_t)blockIdx.x * 32 * 512;

    // ====== Phase 1: conv1d q/k/v (64->32), f32x2 over co-PAIRS (x shared, w pre-paired) ======
    {
        const int pr = tid >> 4;          // co-pair 0..15 (co = 2pr, 2pr+1)
        const int g  = tid & 15;
        const int l0 = g * 8;             // 8 outputs per thread per co
        const int cb = g * 2;             // base 16B chunk of window
#pragma unroll 1
        for (int m = 0; m < 3; m++) {
            const float* xin = (m == 0 ? gq : m == 1 ? gk : gv) + boff;
            const float* cw  = (m == 0 ? cq_w : m == 1 ? ck_w : cv_w);
            const float* cb_ = (m == 0 ? cq_b : m == 1 ? ck_b : cv_b);
            float* dst = s + OFF_QKV + m * 4224;
            __syncthreads();
            for (int i = tid; i < 64 * 12; i += NT) {
                int ci = i / 12, j = i % 12;
                int f = (j < 6) ? j : j + 128;
                s[OFF_IN + ci * WR + SWZ(f)] = 0.f;
            }
            for (int i = tid; i < 8192; i += NT) {
                int f = 6 + (i & 127);
                s[OFF_IN + (i >> 7) * WR + SWZ(f)] = xin[i];
            }

            u64 acc2[8];
            {
                u64 bp2 = pk2(__ldg(&cb_[2 * pr]), __ldg(&cb_[2 * pr + 1]));
#pragma unroll
                for (int i = 0; i < 8; i++) acc2[i] = bp2;
            }
#pragma unroll 1
            for (int c = 0; c < 8; c++) {
                const int ci0 = c * 8;
                __syncthreads();
                // stage weights pair-interleaved: [pair][ci][kk*2 + (co&1)], row 28
                for (int i = tid; i < 32 * 8 * 13; i += NT) {
                    int coi = i / 104, r = i % 104, ci = r / 13, kk = r % 13;
                    s[OFF_CW + ((coi >> 1) * 8 + ci) * 28 + kk * 2 + (coi & 1)]
                        = cw[(coi * 64 + ci0 + ci) * 13 + kk];
                }
                __syncthreads();
#pragma unroll 1
                for (int ci = 0; ci < 8; ci++) {
                    const float* xp = s + OFF_IN + (ci0 + ci) * WR;
                    float xw[20];
#pragma unroll
                    for (int q4 = 0; q4 < 5; q4++) {
                        int cc = cb + q4;
                        float4 t4 = *(const float4*)(xp + ((cc + (cc >> 3)) << 2));
                        xw[q4 * 4 + 0] = t4.x; xw[q4 * 4 + 1] = t4.y;
                        xw[q4 * 4 + 2] = t4.z; xw[q4 * 4 + 3] = t4.w;
                    }
                    u64 dx[20];
#pragma unroll
                    for (int j = 0; j < 20; j++) dx[j] = dup2(xw[j]);
                    const float* wr = s + OFF_CW + (pr * 8 + ci) * 28;
#pragma unroll
                    for (int kk = 0; kk < 13; kk++) {
                        u64 wp = lds64(wr + 2 * kk);
#pragma unroll
                        for (int i = 0; i < 8; i++)
                            fma2(acc2[i], dx[kk + i], wp);
                    }
                }
            }
            float o0[8], o1[8];
#pragma unroll
            for (int i = 0; i < 8; i++) upk2(o0[i], o1[i], acc2[i]);
            *(float4*)(dst + (2 * pr) * QS + l0)         = make_float4(o0[0], o0[1], o0[2], o0[3]);
            *(float4*)(dst + (2 * pr) * QS + l0 + 4)     = make_float4(o0[4], o0[5], o0[6], o0[7]);
            *(float4*)(dst + (2 * pr + 1) * QS + l0)     = make_float4(o1[0], o1[1], o1[2], o1[3]);
            *(float4*)(dst + (2 * pr + 1) * QS + l0 + 4) = make_float4(o1[4], o1[5], o1[6], o1[7]);
        }
    }

    // ============ Phase 2: per-head projections + attention, 4 passes of 4 heads ============
    {
        const int dc = lane & 3, tr = lane >> 2;
        const float inv_t = 0.08838834764831845f;   // 1/sqrt(128)
#pragma unroll 1
        for (int p = 0; p < 4; p++) {
            __syncthreads();
            {
                const int g = w, hl = g / 3, mm = g % 3;
                const float* Bsrc = (mm == 0 ? w_qs : mm == 1 ? w_ks : w_vs) + (p * 4 + hl) * 4096;
                gemm32<4>(s + OFF_QKV + mm * 4224, Bsrc,
                          s + OFF_SCR + hl * 3264 + mm * 1088, 0, tr, dc);
            }
            {
                const int g = 8 + (w >> 1), hl = g / 3, mm = g % 3;
                const float* Bsrc = (mm == 0 ? w_qs : mm == 1 ? w_ks : w_vs) + (p * 4 + hl) * 4096;
                gemm32<2>(s + OFF_QKV + mm * 4224, Bsrc,
                          s + OFF_SCR + hl * 3264 + mm * 1088, (w & 1) * 16, tr, dc);
            }
            __syncthreads();
            {
                const int hl = w >> 1, qbase = (w & 1) * 16;
                float* qh = s + OFF_SCR + hl * 3264;
                float* kh = qh + 1088;
                float* vh = qh + 2176;
                const float* qr0 = qh + (qbase + tr) * SCS;
                const float* qr1 = qh + (qbase + tr + 8) * SCS;
                u64 sc2[2][8];
#pragma unroll
                for (int i = 0; i < 2; i++)
#pragma unroll
                    for (int j = 0; j < 8; j++) sc2[i][j] = 0ull;
#pragma unroll 4
                for (int d2 = 0; d2 < 16; d2++) {
                    u64 q0 = lds64(qr0 + 2 * d2);
                    u64 q1 = lds64(qr1 + 2 * d2);
#pragma unroll
                    for (int j = 0; j < 8; j++) {
                        u64 kv = lds64(kh + (dc * 8 + j) * SCS + 2 * d2);
                        fma2(sc2[0][j], q0, kv);
                        fma2(sc2[1][j], q1, kv);
                    }
                }
                float sc[2][8];
#pragma unroll
                for (int i = 0; i < 2; i++)
#pragma unroll
                    for (int j = 0; j < 8; j++) {
                        float lo, hi; upk2(lo, hi, sc2[i][j]); sc[i][j] = lo + hi;
                    }
#pragma unroll
                for (int i = 0; i < 2; i++) {
                    float mx = -1e30f;
#pragma unroll
                    for (int j = 0; j < 8; j++) { sc[i][j] *= inv_t; mx = fmaxf(mx, sc[i][j]); }
                    mx = fmaxf(mx, __shfl_xor_sync(0xffffffffu, mx, 1));
                    mx = fmaxf(mx, __shfl_xor_sync(0xffffffffu, mx, 2));
                    float sum = 0.f;
#pragma unroll
                    for (int j = 0; j < 8; j++) { sc[i][j] = __expf(sc[i][j] - mx); sum += sc[i][j]; }
                    sum += __shfl_xor_sync(0xffffffffu, sum, 1);
                    sum += __shfl_xor_sync(0xffffffffu, sum, 2);
                    float inv = 1.f / sum;
#pragma unroll
                    for (int j = 0; j < 8; j++) sc[i][j] *= inv;
                }
#pragma unroll
                for (int i = 0; i < 2; i++)
#pragma unroll
                    for (int j = 0; j < 8; j++)
                        qh[(qbase + tr + 8 * i) * SCS + dc * 8 + j] = sc[i][j];
                __syncwarp();
                u64 av2[2][4];
#pragma unroll
                for (int i = 0; i < 2; i++)
#pragma unroll
                    for (int jp = 0; jp < 4; jp++) av2[i][jp] = 0ull;
#pragma unroll 4
                for (int k2 = 0; k2 < 32; k2++) {
                    u64 a0 = dup2(qr0[k2]);
                    u64 a1 = dup2(qr1[k2]);
#pragma unroll
                    for (int jp = 0; jp < 4; jp++) {
                        u64 vv = lds64(vh + k2 * SCS + dc * 8 + 2 * jp);
                        fma2(av2[0][jp], a0, vv);
                        fma2(av2[1][jp], a1, vv);
                    }
                }
                const int h = p * 4 + hl;
#pragma unroll
                for (int i = 0; i < 2; i++)
#pragma unroll
                    for (int jp = 0; jp < 4; jp++)
                        *reinterpret_cast<u64*>(gatt + (qbase + tr + 8 * i) * 512
                                                + h * 32 + dc * 8 + 2 * jp) = av2[i][jp];
            }
        }
    }

    // ============ Phase 3: stage ATT from gmem, proj with transposed weights ============
    __syncthreads();
    for (int i = tid; i < 16384; i += NT)
        s[OFF_ATT + (i >> 9) * 516 + (i & 511)] = gatt[i];
    for (int i = tid; i < 32 * 12; i += NT) {
        int t = i / 12, j = i % 12;
        int f = (j < 6) ? j : j + 128;
        s[OFF_Y + t * WR + SWZ(f)] = 0.f;
    }
    __syncthreads();
    {
        const int tq = lane >> 4, ml = lane & 15;
        const int m0 = (w >> 2) * 64 + ml * 4;      // 4 m's per thread
        const int tb = (w & 3) * 8 + tq * 4;        // 4 t-rows per thread
        u64 acc[4][2];
#pragma unroll
        for (int t = 0; t < 4; t++) { acc[t][0] = 0ull; acc[t][1] = 0ull; }
        const float* bp0 = g_pwT + m0;
        ulonglong2 c0 = __ldg((const ulonglong2*)bp0);
        ulonglong2 c1 = __ldg((const ulonglong2*)(bp0 + 128));
#pragma unroll 2
        for (int j2 = 0; j2 < 256; j2++) {                   // full 512 reduction
            const int nj = (j2 < 255) ? (2 * j2 + 2) : 510;
            ulonglong2 n0 = __ldg((const ulonglong2*)(bp0 + nj * 128));
            ulonglong2 n1 = __ldg((const ulonglong2*)(bp0 + (nj + 1) * 128));
#pragma unroll
            for (int t = 0; t < 4; t++) {
                u64 a01 = lds64(s + OFF_ATT + (tb + t) * 516 + 2 * j2);
                float alo, ahi; upk2(alo, ahi, a01);
                u64 d0 = dup2(alo), d1 = dup2(ahi);
                fma2(acc[t][0], d0, c0.x); fma2(acc[t][1], d0, c0.y);
                fma2(acc[t][0], d1, c1.x); fma2(acc[t][1], d1, c1.y);
            }
            c0 = n0; c1 = n1;
        }
        float4 bb = __ldg((const float4*)(proj_b + m0));
#pragma unroll
        for (int t = 0; t < 4; t++) {
            float y0, y1, y2, y3;
            upk2(y0, y1, acc[t][0]);
            upk2(y2, y3, acc[t][1]);
            float* yrow = s + OFF_Y + (tb + t) * WR;
            const int f0 = 6 + m0, c0i = f0 >> 2;           // floats 2,3 of chunk
            const int f1 = 8 + m0, c1i = f1 >> 2;           // floats 0,1 of chunk
            *reinterpret_cast<u64*>(yrow + ((c0i + (c0i >> 3)) << 2) + 2) = pk2(y0 + bb.x, y1 + bb.y);
            *reinterpret_cast<u64*>(yrow + ((c1i + (c1i >> 3)) << 2))     = pk2(y2 + bb.z, y3 + bb.w);
        }
    }
    __syncthreads();

    // ====== Phase 4: final conv (32->64) + residual, f32x2 over co-quads (2 pairs) ======
    {
        const int qd = tid >> 4;          // co-quad 0..15 (co = 4qd..4qd+3)
        const int g  = tid & 15;
        const int l0 = g * 8;
        const int cb = g * 2;
        u64 acc2[2][8];                   // [pair within quad][pos]
        {
            u64 bA = pk2(__ldg(&fc_b[4 * qd]),     __ldg(&fc_b[4 * qd + 1]));
            u64 bB = pk2(__ldg(&fc_b[4 * qd + 2]), __ldg(&fc_b[4 * qd + 3]));
#pragma unroll
            for (int i = 0; i < 8; i++) { acc2[0][i] = bA; acc2[1][i] = bB; }
        }
#pragma unroll 1
        for (int c = 0; c < 4; c++) {
            const int ci0 = c * 8;
            __syncthreads();
            // stage weights quad-interleaved: [quad][ci][kk*4 + (co&3)], row 56
            for (int i = tid; i < 64 * 8 * 13; i += NT) {
                int coi = i / 104, r = i % 104, ci = r / 13, kk = r % 13;
                s[OFF_FCW + ((coi >> 2) * 8 + ci) * 56 + kk * 4 + (coi & 3)]
                    = fc_w[(coi * 32 + ci0 + ci) * 13 + kk];
            }
            __syncthreads();
#pragma unroll 1
            for (int ci = 0; ci < 8; ci++) {
                const float* xp = s + OFF_Y + (ci0 + ci) * WR;
                float xw[20];
#pragma unroll
                for (int q4 = 0; q4 < 5; q4++) {
                    int cc = cb + q4;
                    float4 t4 = *(const float4*)(xp + ((cc + (cc >> 3)) << 2));
                    xw[q4 * 4 + 0] = t4.x; xw[q4 * 4 + 1] = t4.y;
                    xw[q4 * 4 + 2] = t4.z; xw[q4 * 4 + 3] = t4.w;
                }
                u64 dx[20];
#pragma unroll
                for (int j = 0; j < 20; j++) dx[j] = dup2(xw[j]);
                const float* wr = s + OFF_FCW + (qd * 8 + ci) * 56;
#pragma unroll
                for (int kk = 0; kk < 13; kk++) {
                    u64 wpA = lds64(wr + 4 * kk);
                    u64 wpB = lds64(wr + 4 * kk + 2);
#pragma unroll
                    for (int i = 0; i < 8; i++) {
                        fma2(acc2[0][i], dx[kk + i], wpA);
                        fma2(acc2[1][i], dx[kk + i], wpB);
                    }
                }
            }
        }
        const float* qres = gq + boff;
        float o[4][8];
#pragma unroll
        for (int i = 0; i < 8; i++) {
            upk2(o[0][i], o[1][i], acc2[0][i]);
            upk2(o[2][i], o[3][i], acc2[1][i]);
        }
#pragma unroll
        for (int c2 = 0; c2 < 4; c2++) {
            const int co = 4 * qd + c2;
            float4 r0 = __ldg((const float4*)(qres + co * 128 + l0));
            float4 r1 = __ldg((const float4*)(qres + co * 128 + l0 + 4));
            *(float4*)(s + OFF_Z + co * 128 + l0) =
                make_float4(o[c2][0] + r0.x, o[c2][1] + r0.y, o[c2][2] + r0.z, o[c2][3] + r0.w);
            *(float4*)(s + OFF_Z + co * 128 + l0 + 4) =
                make_float4(o[c2][4] + r1.x, o[c2][5] + r1.y, o[c2][6] + r1.z, o[c2][7] + r1.w);
        }
    }
    __syncthreads();

    // ============ Phase 5: LayerNorm (unbiased std, /(sigma+eps)) ============
    {
#pragma unroll
        for (int it = 0; it < 8; it++) {
            int r = w + it * 8;
            const float* zr = s + OFF_Z + r * 128;
            float v0 = zr[lane], v1 = zr[lane + 32], v2 = zr[lane + 64], v3 = zr[lane + 96];
            float sm = v0 + v1 + v2 + v3;
#pragma unroll
            for (int o = 16; o > 0; o >>= 1) sm += __shfl_xor_sync(0xffffffffu, sm, o);
            float mu = sm * (1.f / 128.f);
            float d0 = v0 - mu, d1 = v1 - mu, d2 = v2 - mu, d3 = v3 - mu;
            float s2 = d0 * d0 + d1 * d1 + d2 * d2 + d3 * d3;
#pragma unroll
            for (int o = 16; o > 0; o >>= 1) s2 += __shfl_xor_sync(0xffffffffu, s2, o);
            float sigma = sqrtf(s2 * (1.f / 127.f));
            float inv = 1.f / (sigma + 1e-3f);
            float* orow = out + boff + r * 128;
            orow[lane]      = d0 * inv * __ldg(&ln_a[lane])      + __ldg(&ln_b[lane]);
            orow[lane + 32] = d1 * inv * __ldg(&ln_a[lane + 32]) + __ldg(&ln_b[lane + 32]);
            orow[lane + 64] = d2 * inv * __ldg(&ln_a[lane + 64]) + __ldg(&ln_b[lane + 64]);
            orow[lane + 96] = d3 * inv * __ldg(&ln_a[lane + 96]) + __ldg(&ln_b[lane + 96]);
        }
    }
}

extern "C" void kernel_launch(void* const* d_in, const int* in_sizes, int n_in,
                              void* d_out, int out_size)
{
    const float* q      = (const float*)d_in[0];
    const float* k      = (const float*)d_in[1];
    const float* v      = (const float*)d_in[2];
    const float* cq_w   = (const float*)d_in[3];
    const float* cq_b   = (const float*)d_in[4];
    const float* ck_w   = (const float*)d_in[5];
    const float* ck_b   = (const float*)d_in[6];
    const float* cv_w   = (const float*)d_in[7];
    const float* cv_b   = (const float*)d_in[8];
    const float* w_qs   = (const float*)d_in[9];
    const float* w_ks   = (const float*)d_in[10];
    const float* w_vs   = (const float*)d_in[11];
    const float* proj_w = (const float*)d_in[12];
    const float* proj_b = (const float*)d_in[13];
    const float* fc_w   = (const float*)d_in[14];
    const float* fc_b   = (const float*)d_in[15];
    const float* ln_a   = (const float*)d_in[16];
    const float* ln_b   = (const float*)d_in[17];
    float* outp = (float*)d_out;

    const int B = in_sizes[0] / (64 * 128);

    transpose_pw_kernel<<<128, 512>>>(proj_w);

    cudaFuncSetAttribute(ha_kernel, cudaFuncAttributeMaxDynamicSharedMemorySize, SMEM_BYTES);
    cudaFuncSetAttribute(ha_kernel, cudaFuncAttributePreferredSharedMemoryCarveout, 100);
    ha_kernel<<<B, NT, SMEM_BYTES>>>(q, k, v, cq_w, cq_b, ck_w, ck_b, cv_w, cv_b,
                                     w_qs, w_ks, w_vs, proj_w, proj_b, fc_w, fc_b,
                                     ln_a, ln_b, outp);
}

// round 12
// speedup vs baseline: 1.4348x; 1.0743x over previous
#include <cuda_runtime.h>

// B=2048, DKV=64, L=128, H=16, DT=32, KW=13, PAD=6
#define NT 256
#define QS 132     // qb/kb/vb row stride
#define SCS 34     // qh/kh/vh scratch row stride
#define WR 160     // swizzled conv-window row stride (40 chunks of 16B)

// chunk skew c -> c + (c>>3) kills 64B-stride bank conflicts
#define SWZ(f) ((((((f) >> 2) + ((f) >> 5))) << 2) | ((f) & 3))

// shared layout (floats), peak 25728 (=102,912B) -> 2 CTAs/SM
#define OFF_QKV 0            // 3*32*132 = 12672            [P1 out, P2 A]
#define OFF_IN  12672        // 64*160 = 10240 -> 22912      [P1, swizzled rows]
#define OFF_SCR 12672        // 4 heads*3*32*34 = 13056 -> 25728 [P2]
#define OFF_Y   0            // 32*160 = 5120                [P3 -> P4, swizzled rows]
#define OFF_ATT 5120         // 32*516 = 16512 -> 21632      [P3]
#define OFF_Z   12288        // 8192 -> 20480 (over dead ATT) [P4 -> P5]
#define SMEM_FLOATS 25728
#define SMEM_BYTES (SMEM_FLOATS * 4)

typedef unsigned long long u64;

// gmem scratch (__device__ globals, no allocation)
__device__ float g_att[2048 * 32 * 512];   // per-batch attention concat
__device__ float g_pwT[512 * 128];         // proj_w transposed: pwT[j][m]
__device__ float g_cwI[3 * 26624];         // conv weights pair-interleaved [m][pr16][ci64][kk*2+half]
__device__ float g_fcI[26624];             // fc weights pair-interleaved  [pr32][ci32][kk*2+half]

__device__ __forceinline__ u64 pk2(float lo, float hi) {
    u64 r; asm("mov.b64 %0,{%1,%2};" : "=l"(r) : "f"(lo), "f"(hi)); return r;
}
__device__ __forceinline__ u64 dup2(float x) { return pk2(x, x); }
__device__ __forceinline__ void upk2(float& lo, float& hi, u64 v) {
    asm("mov.b64 {%0,%1},%2;" : "=f"(lo), "=f"(hi) : "l"(v));
}
__device__ __forceinline__ void fma2(u64& d, u64 a, u64 b) {
    asm("fma.rn.f32x2 %0,%1,%2,%0;" : "+l"(d) : "l"(a), "l"(b));
}
__device__ __forceinline__ u64 lds64(const float* p) {
    return *reinterpret_cast<const u64*>(p);
}

__global__ void transpose_pw_kernel(const float* __restrict__ pw) {
    int idx = blockIdx.x * 512 + threadIdx.x;   // 65536 total
    int j = idx >> 7, m = idx & 127;
    g_pwT[idx] = pw[m * 512 + j];
}

__global__ void interleave_cw_kernel(const float* __restrict__ cq,
                                     const float* __restrict__ ck,
                                     const float* __restrict__ cv) {
    int idx = blockIdx.x * 256 + threadIdx.x;   // 3*26624 = 79872
    if (idx >= 3 * 26624) return;
    int m = idx / 26624, i = idx % 26624;
    const float* src = (m == 0) ? cq : (m == 1) ? ck : cv;
    int co = i / 832, r = i % 832, ci = r / 13, kk = r % 13;
    g_cwI[m * 26624 + (co >> 1) * 1664 + ci * 26 + kk * 2 + (co & 1)] = src[i];
}

__global__ void interleave_fc_kernel(const float* __restrict__ fcw) {
    int idx = blockIdx.x * 256 + threadIdx.x;   // 26624
    if (idx >= 26624) return;
    int co = idx / 416, r = idx % 416, ci = r / 13, kk = r % 13;
    g_fcI[(co >> 1) * 832 + ci * 26 + kk * 2 + (co & 1)] = fcw[idx];
}

// One warp: C(32x32) = A(32x128) @ B(128x32); A smem (stride QS, lds64 l-pairs),
// B streamed from gmem, C to smem (stride SCS).
template<int TN>
__device__ __forceinline__ void gemm32(const float* __restrict__ A,
                                       const float* __restrict__ Bg,
                                       float* __restrict__ C,
                                       int tbase, int tr, int dc)
{
    u64 acc[TN][4];
#pragma unroll
    for (int i = 0; i < TN; i++)
#pragma unroll
        for (int j = 0; j < 4; j++) acc[i][j] = 0ull;
    const float* Ar[TN];
#pragma unroll
    for (int i = 0; i < TN; i++) Ar[i] = A + (tbase + tr + 8 * i) * QS;

    const float* bp = Bg + dc * 8;
    ulonglong2 cE0 = __ldg((const ulonglong2*)bp);
    ulonglong2 cE1 = __ldg((const ulonglong2*)(bp + 4));
    ulonglong2 cO0 = __ldg((const ulonglong2*)(bp + 32));
    ulonglong2 cO1 = __ldg((const ulonglong2*)(bp + 36));
#pragma unroll 2
    for (int l2 = 0; l2 < 64; l2++) {
        const int nb = (l2 < 63) ? (2 * l2 + 2) : 126;
        ulonglong2 nE0 = __ldg((const ulonglong2*)(bp + nb * 32));
        ulonglong2 nE1 = __ldg((const ulonglong2*)(bp + nb * 32 + 4));
        ulonglong2 nO0 = __ldg((const ulonglong2*)(bp + nb * 32 + 32));
        ulonglong2 nO1 = __ldg((const ulonglong2*)(bp + nb * 32 + 36));
#pragma unroll
        for (int i = 0; i < TN; i++) {
            u64 a01 = lds64(Ar[i] + 2 * l2);
            float alo, ahi; upk2(alo, ahi, a01);
            u64 d0 = dup2(alo), d1 = dup2(ahi);
            fma2(acc[i][0], d0, cE0.x); fma2(acc[i][1], d0, cE0.y);
            fma2(acc[i][2], d0, cE1.x); fma2(acc[i][3], d0, cE1.y);
            fma2(acc[i][0], d1, cO0.x); fma2(acc[i][1], d1, cO0.y);
            fma2(acc[i][2], d1, cO1.x); fma2(acc[i][3], d1, cO1.y);
        }
        cE0 = nE0; cE1 = nE1; cO0 = nO0; cO1 = nO1;
    }
#pragma unroll
    for (int i = 0; i < TN; i++)
#pragma unroll
        for (int j = 0; j < 4; j++)
            *reinterpret_cast<u64*>(C + (tbase + tr + 8 * i) * SCS + dc * 8 + 2 * j) = acc[i][j];
}

__global__ void __launch_bounds__(NT, 2)
ha_kernel(const float* __restrict__ gq, const float* __restrict__ gk, const float* __restrict__ gv,
          const float* __restrict__ cq_w, const float* __restrict__ cq_b,
          const float* __restrict__ ck_w, const float* __restrict__ ck_b,
          const float* __restrict__ cv_w, const float* __restrict__ cv_b,
          const float* __restrict__ w_qs, const float* __restrict__ w_ks, const float* __restrict__ w_vs,
          const float* __restrict__ proj_w, const float* __restrict__ proj_b,
          const float* __restrict__ fc_w, const float* __restrict__ fc_b,
          const float* __restrict__ ln_a, const float* __restrict__ ln_b,
          float* __restrict__ out)
{
    extern __shared__ float s[];
    const int tid  = threadIdx.x;
    const int w    = tid >> 5;       // 0..7
    const int lane = tid & 31;
    const size_t boff = (size_t)blockIdx.x * 8192;   // 64*128
    float* gatt = g_att + (size_t)blockIdx.x * 32 * 512;

    // ====== Phase 1: conv1d q/k/v (64->32), co-pair f32x2, weights streamed from L2 ======
    {
        const int pr = tid >> 4;          // co-pair 0..15 (co = 2pr, 2pr+1)
        const int g  = tid & 15;
        const int l0 = g * 8;
        const int cb = g * 2;
#pragma unroll 1
        for (int m = 0; m < 3; m++) {
            const float* xin = (m == 0 ? gq : m == 1 ? gk : gv) + boff;
            const float* cb_ = (m == 0 ? cq_b : m == 1 ? ck_b : cv_b);
            float* dst = s + OFF_QKV + m * 4224;
            __syncthreads();
            for (int i = tid; i < 64 * 12; i += NT) {
                int ci = i / 12, j = i % 12;
                int f = (j < 6) ? j : j + 128;
                s[OFF_IN + ci * WR + SWZ(f)] = 0.f;
            }
            for (int i = tid; i < 8192; i += NT) {
                int f = 6 + (i & 127);
                s[OFF_IN + (i >> 7) * WR + SWZ(f)] = xin[i];
            }
            __syncthreads();

            u64 acc2[8];
            {
                u64 bp2 = pk2(__ldg(&cb_[2 * pr]), __ldg(&cb_[2 * pr + 1]));
#pragma unroll
                for (int i = 0; i < 8; i++) acc2[i] = bp2;
            }
            const float* wbase = g_cwI + m * 26624 + pr * 1664;
#pragma unroll 1
            for (int ci = 0; ci < 64; ci++) {
                u64 wp[13];
                const float* wr = wbase + ci * 26;
#pragma unroll
                for (int kk = 0; kk < 13; kk++)
                    wp[kk] = __ldg((const u64*)(wr + 2 * kk));
                const float* xp = s + OFF_IN + ci * WR;
                float xw[20];
#pragma unroll
                for (int q4 = 0; q4 < 5; q4++) {
                    int cc = cb + q4;
                    float4 t4 = *(const float4*)(xp + ((cc + (cc >> 3)) << 2));
                    xw[q4 * 4 + 0] = t4.x; xw[q4 * 4 + 1] = t4.y;
                    xw[q4 * 4 + 2] = t4.z; xw[q4 * 4 + 3] = t4.w;
                }
                u64 dx[20];
#pragma unroll
                for (int j = 0; j < 20; j++) dx[j] = dup2(xw[j]);
#pragma unroll
                for (int kk = 0; kk < 13; kk++)
#pragma unroll
                    for (int i = 0; i < 8; i++)
                        fma2(acc2[i], dx[kk + i], wp[kk]);
            }
            float o0[8], o1[8];
#pragma unroll
            for (int i = 0; i < 8; i++) upk2(o0[i], o1[i], acc2[i]);
            *(float4*)(dst + (2 * pr) * QS + l0)         = make_float4(o0[0], o0[1], o0[2], o0[3]);
            *(float4*)(dst + (2 * pr) * QS + l0 + 4)     = make_float4(o0[4], o0[5], o0[6], o0[7]);
            *(float4*)(dst + (2 * pr + 1) * QS + l0)     = make_float4(o1[0], o1[1], o1[2], o1[3]);
            *(float4*)(dst + (2 * pr + 1) * QS + l0 + 4) = make_float4(o1[4], o1[5], o1[6], o1[7]);
        }
    }

    // ============ Phase 2: per-head projections + attention, 4 passes of 4 heads ============
    {
        const int dc = lane & 3, tr = lane >> 2;
        const float inv_t = 0.08838834764831845f;   // 1/sqrt(128)
#pragma unroll 1
        for (int p = 0; p < 4; p++) {
            __syncthreads();
            {
                const int g = w, hl = g / 3, mm = g % 3;
                const float* Bsrc = (mm == 0 ? w_qs : mm == 1 ? w_ks : w_vs) + (p * 4 + hl) * 4096;
                gemm32<4>(s + OFF_QKV + mm * 4224, Bsrc,
                          s + OFF_SCR + hl * 3264 + mm * 1088, 0, tr, dc);
            }
            {
                const int g = 8 + (w >> 1), hl = g / 3, mm = g % 3;
                const float* Bsrc = (mm == 0 ? w_qs : mm == 1 ? w_ks : w_vs) + (p * 4 + hl) * 4096;
                gemm32<2>(s + OFF_QKV + mm * 4224, Bsrc,
                          s + OFF_SCR + hl * 3264 + mm * 1088, (w & 1) * 16, tr, dc);
            }
            __syncthreads();
            {
                const int hl = w >> 1, qbase = (w & 1) * 16;
                float* qh = s + OFF_SCR + hl * 3264;
                float* kh = qh + 1088;
                float* vh = qh + 2176;
                const float* qr0 = qh + (qbase + tr) * SCS;
                const float* qr1 = qh + (qbase + tr + 8) * SCS;
                u64 sc2[2][8];
#pragma unroll
                for (int i = 0; i < 2; i++)
#pragma unroll
                    for (int j = 0; j < 8; j++) sc2[i][j] = 0ull;
#pragma unroll 4
                for (int d2 = 0; d2 < 16; d2++) {
                    u64 q0 = lds64(qr0 + 2 * d2);
                    u64 q1 = lds64(qr1 + 2 * d2);
#pragma unroll
                    for (int j = 0; j < 8; j++) {
                        u64 kv = lds64(kh + (dc * 8 + j) * SCS + 2 * d2);
                        fma2(sc2[0][j], q0, kv);
                        fma2(sc2[1][j], q1, kv);
                    }
                }
                float sc[2][8];
#pragma unroll
                for (int i = 0; i < 2; i++)
#pragma unroll
                    for (int j = 0; j < 8; j++) {
                        float lo, hi; upk2(lo, hi, sc2[i][j]); sc[i][j] = lo + hi;
                    }
#pragma unroll
                for (int i = 0; i < 2; i++) {
                    float mx = -1e30f;
#pragma unroll
                    for (int j = 0; j < 8; j++) { sc[i][j] *= inv_t; mx = fmaxf(mx, sc[i][j]); }
                    mx = fmaxf(mx, __shfl_xor_sync(0xffffffffu, mx, 1));
                    mx = fmaxf(mx, __shfl_xor_sync(0xffffffffu, mx, 2));
                    float sum = 0.f;
#pragma unroll
                    for (int j = 0; j < 8; j++) { sc[i][j] = __expf(sc[i][j] - mx); sum += sc[i][j]; }
                    sum += __shfl_xor_sync(0xffffffffu, sum, 1);
                    sum += __shfl_xor_sync(0xffffffffu, sum, 2);
                    float inv = 1.f / sum;
#pragma unroll
                    for (int j = 0; j < 8; j++) sc[i][j] *= inv;
                }
#pragma unroll
                for (int i = 0; i < 2; i++)
#pragma unroll
                    for (int j = 0; j < 8; j++)
                        qh[(qbase + tr + 8 * i) * SCS + dc * 8 + j] = sc[i][j];
                __syncwarp();
                u64 av2[2][4];
#pragma unroll
                for (int i = 0; i < 2; i++)
#pragma unroll
                    for (int jp = 0; jp < 4; jp++) av2[i][jp] = 0ull;
#pragma unroll 4
                for (int k2 = 0; k2 < 32; k2++) {
                    u64 a0 = dup2(qr0[k2]);
                    u64 a1 = dup2(qr1[k2]);
#pragma unroll
                    for (int jp = 0; jp < 4; jp++) {
                        u64 vv = lds64(vh + k2 * SCS + dc * 8 + 2 * jp);
                        fma2(av2[0][jp], a0, vv);
                        fma2(av2[1][jp], a1, vv);
                    }
                }
                const int h = p * 4 + hl;
#pragma unroll
                for (int i = 0; i < 2; i++)
#pragma unroll
                    for (int jp = 0; jp < 4; jp++)
                        *reinterpret_cast<u64*>(gatt + (qbase + tr + 8 * i) * 512
                                                + h * 32 + dc * 8 + 2 * jp) = av2[i][jp];
            }
        }
    }

    // ============ Phase 3: stage ATT from gmem, proj with transposed weights ============
    __syncthreads();
    for (int i = tid; i < 16384; i += NT)
        s[OFF_ATT + (i >> 9) * 516 + (i & 511)] = gatt[i];
    for (int i = tid; i < 32 * 12; i += NT) {
        int t = i / 12, j = i % 12;
        int f = (j < 6) ? j : j + 128;
        s[OFF_Y + t * WR + SWZ(f)] = 0.f;
    }
    __syncthreads();
    {
        const int tq = lane >> 4, ml = lane & 15;
        const int m0 = (w >> 2) * 64 + ml * 4;      // 4 m's per thread
        const int tb = (w & 3) * 8 + tq * 4;        // 4 t-rows per thread
        u64 acc[4][2];
#pragma unroll
        for (int t = 0; t < 4; t++) { acc[t][0] = 0ull; acc[t][1] = 0ull; }
        const float* bp0 = g_pwT + m0;
        ulonglong2 c0 = __ldg((const ulonglong2*)bp0);
        ulonglong2 c1 = __ldg((const ulonglong2*)(bp0 + 128));
#pragma unroll 2
        for (int j2 = 0; j2 < 256; j2++) {                   // full 512 reduction
            const int nj = (j2 < 255) ? (2 * j2 + 2) : 510;
            ulonglong2 n0 = __ldg((const ulonglong2*)(bp0 + nj * 128));
            ulonglong2 n1 = __ldg((const ulonglong2*)(bp0 + (nj + 1) * 128));
#pragma unroll
            for (int t = 0; t < 4; t++) {
                u64 a01 = lds64(s + OFF_ATT + (tb + t) * 516 + 2 * j2);
                float alo, ahi; upk2(alo, ahi, a01);
                u64 d0 = dup2(alo), d1 = dup2(ahi);
                fma2(acc[t][0], d0, c0.x); fma2(acc[t][1], d0, c0.y);
                fma2(acc[t][0], d1, c1.x); fma2(acc[t][1], d1, c1.y);
            }
            c0 = n0; c1 = n1;
        }
        float4 bb = __ldg((const float4*)(proj_b + m0));
#pragma unroll
        for (int t = 0; t < 4; t++) {
            float y0, y1, y2, y3;
            upk2(y0, y1, acc[t][0]);
            upk2(y2, y3, acc[t][1]);
            float* yrow = s + OFF_Y + (tb + t) * WR;
            const int f0 = 6 + m0, c0i = f0 >> 2;           // floats 2,3 of chunk
            const int f1 = 8 + m0, c1i = f1 >> 2;           // floats 0,1 of chunk
            *reinterpret_cast<u64*>(yrow + ((c0i + (c0i >> 3)) << 2) + 2) = pk2(y0 + bb.x, y1 + bb.y);
            *reinterpret_cast<u64*>(yrow + ((c1i + (c1i >> 3)) << 2))     = pk2(y2 + bb.z, y3 + bb.w);
        }
    }
    __syncthreads();

    // ====== Phase 4: final conv (32->64) + residual, two co-pair passes, weights from L2 ======
    {
        const int qd = tid >> 4;          // 0..15
        const int g  = tid & 15;
        const int l0 = g * 8;
        const int cb = g * 2;
        const float* qres = gq + boff;
#pragma unroll 1
        for (int pass = 0; pass < 2; pass++) {
            const int pr = 2 * qd + pass;             // pair 0..31, co = 2pr, 2pr+1
            u64 acc2[8];
            {
                u64 bp2 = pk2(__ldg(&fc_b[2 * pr]), __ldg(&fc_b[2 * pr + 1]));
#pragma unroll
                for (int i = 0; i < 8; i++) acc2[i] = bp2;
            }
            const float* wbase = g_fcI + pr * 832;
#pragma unroll 1
            for (int ci = 0; ci < 32; ci++) {
                u64 wp[13];
                const float* wr = wbase + ci * 26;
#pragma unroll
                for (int kk = 0; kk < 13; kk++)
                    wp[kk] = __ldg((const u64*)(wr + 2 * kk));
                const float* xp = s + OFF_Y + ci * WR;
                float xw[20];
#pragma unroll
                for (int q4 = 0; q4 < 5; q4++) {
                    int cc = cb + q4;
                    float4 t4 = *(const float4*)(xp + ((cc + (cc >> 3)) << 2));
                    xw[q4 * 4 + 0] = t4.x; xw[q4 * 4 + 1] = t4.y;
                    xw[q4 * 4 + 2] = t4.z; xw[q4 * 4 + 3] = t4.w;
                }
                u64 dx[20];
#pragma unroll
                for (int j = 0; j < 20; j++) dx[j] = dup2(xw[j]);
#pragma unroll
                for (int kk = 0; kk < 13; kk++)
#pragma unroll
                    for (int i = 0; i < 8; i++)
                        fma2(acc2[i], dx[kk + i], wp[kk]);
            }
            float o0[8], o1[8];
#pragma unroll
            for (int i = 0; i < 8; i++) upk2(o0[i], o1[i], acc2[i]);
#pragma unroll
            for (int c2 = 0; c2 < 2; c2++) {
                const int co = 2 * pr + c2;
                const float* oc = (c2 == 0) ? o0 : o1;
                float4 r0 = __ldg((const float4*)(qres + co * 128 + l0));
                float4 r1 = __ldg((const float4*)(qres + co * 128 + l0 + 4));
                *(float4*)(s + OFF_Z + co * 128 + l0) =
                    make_float4(oc[0] + r0.x, oc[1] + r0.y, oc[2] + r0.z, oc[3] + r0.w);
                *(float4*)(s + OFF_Z + co * 128 + l0 + 4) =
                    make_float4(oc[4] + r1.x, oc[5] + r1.y, oc[6] + r1.z, oc[7] + r1.w);
            }
        }
    }
    __syncthreads();

    // ============ Phase 5: LayerNorm (unbiased std, /(sigma+eps)) ============
    {
#pragma unroll
        for (int it = 0; it < 8; it++) {
            int r = w + it * 8;
            const float* zr = s + OFF_Z + r * 128;
            float v0 = zr[lane], v1 = zr[lane + 32], v2 = zr[lane + 64], v3 = zr[lane + 96];
            float sm = v0 + v1 + v2 + v3;
#pragma unroll
            for (int o = 16; o > 0; o >>= 1) sm += __shfl_xor_sync(0xffffffffu, sm, o);
            float mu = sm * (1.f / 128.f);
            float d0 = v0 - mu, d1 = v1 - mu, d2 = v2 - mu, d3 = v3 - mu;
            float s2 = d0 * d0 + d1 * d1 + d2 * d2 + d3 * d3;
#pragma unroll
            for (int o = 16; o > 0; o >>= 1) s2 += __shfl_xor_sync(0xffffffffu, s2, o);
            float sigma = sqrtf(s2 * (1.f / 127.f));
            float inv = 1.f / (sigma + 1e-3f);
            float* orow = out + boff + r * 128;
            orow[lane]      = d0 * inv * __ldg(&ln_a[lane])      + __ldg(&ln_b[lane]);
            orow[lane + 32] = d1 * inv * __ldg(&ln_a[lane + 32]) + __ldg(&ln_b[lane + 32]);
            orow[lane + 64] = d2 * inv * __ldg(&ln_a[lane + 64]) + __ldg(&ln_b[lane + 64]);
            orow[lane + 96] = d3 * inv * __ldg(&ln_a[lane + 96]) + __ldg(&ln_b[lane + 96]);
        }
    }
}

extern "C" void kernel_launch(void* const* d_in, const int* in_sizes, int n_in,
                              void* d_out, int out_size)
{
    const float* q      = (const float*)d_in[0];
    const float* k      = (const float*)d_in[1];
    const float* v      = (const float*)d_in[2];
    const float* cq_w   = (const float*)d_in[3];
    const float* cq_b   = (const float*)d_in[4];
    const float* ck_w   = (const float*)d_in[5];
    const float* ck_b   = (const float*)d_in[6];
    const float* cv_w   = (const float*)d_in[7];
    const float* cv_b   = (const float*)d_in[8];
    const float* w_qs   = (const float*)d_in[9];
    const float* w_ks   = (const float*)d_in[10];
    const float* w_vs   = (const float*)d_in[11];
    const float* proj_w = (const float*)d_in[12];
    const float* proj_b = (const float*)d_in[13];
    const float* fc_w   = (const float*)d_in[14];
    const float* fc_b   = (const float*)d_in[15];
    const float* ln_a   = (const float*)d_in[16];
    const float* ln_b   = (const float*)d_in[17];
    float* outp = (float*)d_out;

    const int B = in_sizes[0] / (64 * 128);

    transpose_pw_kernel<<<128, 512>>>(proj_w);
    interleave_cw_kernel<<<312, 256>>>(cq_w, ck_w, cv_w);
    interleave_fc_kernel<<<104, 256>>>(fc_w);

    cudaFuncSetAttribute(ha_kernel, cudaFuncAttributeMaxDynamicSharedMemorySize, SMEM_BYTES);
    cudaFuncSetAttribute(ha_kernel, cudaFuncAttributePreferredSharedMemoryCarveout, 100);
    ha_kernel<<<B, NT, SMEM_BYTES>>>(q, k, v, cq_w, cq_b, ck_w, ck_b, cv_w, cv_b,
                                     w_qs, w_ks, w_vs, proj_w, proj_b, fc_w, fc_b,
                                     ln_a, ln_b, outp);
}

// round 13
// speedup vs baseline: 1.5182x; 1.0581x over previous
#include <cuda_runtime.h>

// B=2048, DKV=64, L=128, H=16, DT=32, KW=13, PAD=6
#define NT 256
#define QS 132     // qb/kb/vb row stride
#define SCS 34     // qh/kh/vh scratch row stride
#define WR 160     // swizzled conv-window row stride (40 chunks of 16B)

// chunk skew c -> c + (c>>3) kills 64B-stride bank conflicts
#define SWZ(f) ((((((f) >> 2) + ((f) >> 5))) << 2) | ((f) & 3))

// shared layout (floats), peak 25728 (=102,912B) -> 2 CTAs/SM
#define OFF_QKV 0            // 3*32*132 = 12672            [P1 out, P2 A]
#define OFF_IN  12672        // 64*160 = 10240 -> 22912      [P1, swizzled rows]
#define OFF_SCR 12672        // 4 heads*3*32*34 = 13056 -> 25728 [P2]
#define OFF_Y   0            // 32*160 = 5120                [P3 -> P4, swizzled rows]
#define OFF_ATT 5120         // 32*516 = 16512 -> 21632      [P3]
#define OFF_Z   12288        // 8192 -> 20480 (over dead ATT) [P4 -> P5]
#define SMEM_FLOATS 25728
#define SMEM_BYTES (SMEM_FLOATS * 4)

typedef unsigned long long u64;

// gmem scratch (__device__ globals, no allocation)
__device__ float g_att[2048 * 32 * 512];   // per-batch attention concat
__device__ float g_pwT[512 * 128];         // proj_w transposed: pwT[j][m]
__device__ float g_cwI[3 * 26624];         // conv weights pair-interleaved [m][pr16][ci64][kk*2+half]
__device__ float g_fcI[26624];             // fc weights pair-interleaved  [pr32][ci32][kk*2+half]

__device__ __forceinline__ u64 pk2(float lo, float hi) {
    u64 r; asm("mov.b64 %0,{%1,%2};" : "=l"(r) : "f"(lo), "f"(hi)); return r;
}
__device__ __forceinline__ u64 dup2(float x) { return pk2(x, x); }
__device__ __forceinline__ void upk2(float& lo, float& hi, u64 v) {
    asm("mov.b64 {%0,%1},%2;" : "=f"(lo), "=f"(hi) : "l"(v));
}
__device__ __forceinline__ void fma2(u64& d, u64 a, u64 b) {
    asm("fma.rn.f32x2 %0,%1,%2,%0;" : "+l"(d) : "l"(a), "l"(b));
}
__device__ __forceinline__ u64 lds64(const float* p) {
    return *reinterpret_cast<const u64*>(p);
}

__global__ void transpose_pw_kernel(const float* __restrict__ pw) {
    int idx = blockIdx.x * 512 + threadIdx.x;   // 65536 total
    int j = idx >> 7, m = idx & 127;
    g_pwT[idx] = pw[m * 512 + j];
}

__global__ void interleave_cw_kernel(const float* __restrict__ cq,
                                     const float* __restrict__ ck,
                                     const float* __restrict__ cv) {
    int idx = blockIdx.x * 256 + threadIdx.x;   // 3*26624 = 79872
    if (idx >= 3 * 26624) return;
    int m = idx / 26624, i = idx % 26624;
    const float* src = (m == 0) ? cq : (m == 1) ? ck : cv;
    int co = i / 832, r = i % 832, ci = r / 13, kk = r % 13;
    g_cwI[m * 26624 + (co >> 1) * 1664 + ci * 26 + kk * 2 + (co & 1)] = src[i];
}

__global__ void interleave_fc_kernel(const float* __restrict__ fcw) {
    int idx = blockIdx.x * 256 + threadIdx.x;   // 26624
    if (idx >= 26624) return;
    int co = idx / 416, r = idx % 416, ci = r / 13, kk = r % 13;
    g_fcI[(co >> 1) * 832 + ci * 26 + kk * 2 + (co & 1)] = fcw[idx];
}

// One warp: C(32x32) = A(32x128) @ B(128x32); A smem (stride QS, lds64 l-pairs),
// B streamed from gmem, C to smem (stride SCS).
template<int TN>
__device__ __forceinline__ void gemm32(const float* __restrict__ A,
                                       const float* __restrict__ Bg,
                                       float* __restrict__ C,
                                       int tbase, int tr, int dc)
{
    u64 acc[TN][4];
#pragma unroll
    for (int i = 0; i < TN; i++)
#pragma unroll
        for (int j = 0; j < 4; j++) acc[i][j] = 0ull;
    const float* Ar[TN];
#pragma unroll
    for (int i = 0; i < TN; i++) Ar[i] = A + (tbase + tr + 8 * i) * QS;

    const float* bp = Bg + dc * 8;
    ulonglong2 cE0 = __ldg((const ulonglong2*)bp);
    ulonglong2 cE1 = __ldg((const ulonglong2*)(bp + 4));
    ulonglong2 cO0 = __ldg((const ulonglong2*)(bp + 32));
    ulonglong2 cO1 = __ldg((const ulonglong2*)(bp + 36));
#pragma unroll 2
    for (int l2 = 0; l2 < 64; l2++) {
        const int nb = (l2 < 63) ? (2 * l2 + 2) : 126;
        ulonglong2 nE0 = __ldg((const ulonglong2*)(bp + nb * 32));
        ulonglong2 nE1 = __ldg((const ulonglong2*)(bp + nb * 32 + 4));
        ulonglong2 nO0 = __ldg((const ulonglong2*)(bp + nb * 32 + 32));
        ulonglong2 nO1 = __ldg((const ulonglong2*)(bp + nb * 32 + 36));
#pragma unroll
        for (int i = 0; i < TN; i++) {
            u64 a01 = lds64(Ar[i] + 2 * l2);
            float alo, ahi; upk2(alo, ahi, a01);
            u64 d0 = dup2(alo), d1 = dup2(ahi);
            fma2(acc[i][0], d0, cE0.x); fma2(acc[i][1], d0, cE0.y);
            fma2(acc[i][2], d0, cE1.x); fma2(acc[i][3], d0, cE1.y);
            fma2(acc[i][0], d1, cO0.x); fma2(acc[i][1], d1, cO0.y);
            fma2(acc[i][2], d1, cO1.x); fma2(acc[i][3], d1, cO1.y);
        }
        cE0 = nE0; cE1 = nE1; cO0 = nO0; cO1 = nO1;
    }
#pragma unroll
    for (int i = 0; i < TN; i++)
#pragma unroll
        for (int j = 0; j < 4; j++)
            *reinterpret_cast<u64*>(C + (tbase + tr + 8 * i) * SCS + dc * 8 + 2 * j) = acc[i][j];
}

__global__ void __launch_bounds__(NT, 2)
ha_kernel(const float* __restrict__ gq, const float* __restrict__ gk, const float* __restrict__ gv,
          const float* __restrict__ cq_w, const float* __restrict__ cq_b,
          const float* __restrict__ ck_w, const float* __restrict__ ck_b,
          const float* __restrict__ cv_w, const float* __restrict__ cv_b,
          const float* __restrict__ w_qs, const float* __restrict__ w_ks, const float* __restrict__ w_vs,
          const float* __restrict__ proj_w, const float* __restrict__ proj_b,
          const float* __restrict__ fc_w, const float* __restrict__ fc_b,
          const float* __restrict__ ln_a, const float* __restrict__ ln_b,
          float* __restrict__ out)
{
    extern __shared__ float s[];
    const int tid  = threadIdx.x;
    const int w    = tid >> 5;       // 0..7
    const int lane = tid & 31;
    const size_t boff = (size_t)blockIdx.x * 8192;   // 64*128
    float* gatt = g_att + (size_t)blockIdx.x * 32 * 512;

    // ====== Phase 1: conv1d q/k/v (64->32), co-pair f32x2, distance-1 weight pipeline ======
    {
        const int pr = tid >> 4;          // co-pair 0..15 (co = 2pr, 2pr+1)
        const int g  = tid & 15;
        const int l0 = g * 8;
        const int cb = g * 2;
#pragma unroll 1
        for (int m = 0; m < 3; m++) {
            const float* xin = (m == 0 ? gq : m == 1 ? gk : gv) + boff;
            const float* cb_ = (m == 0 ? cq_b : m == 1 ? ck_b : cv_b);
            float* dst = s + OFF_QKV + m * 4224;
            __syncthreads();
            for (int i = tid; i < 64 * 12; i += NT) {
                int ci = i / 12, j = i % 12;
                int f = (j < 6) ? j : j + 128;
                s[OFF_IN + ci * WR + SWZ(f)] = 0.f;
            }
            for (int i = tid; i < 8192; i += NT) {
                int f = 6 + (i & 127);
                s[OFF_IN + (i >> 7) * WR + SWZ(f)] = xin[i];
            }
            __syncthreads();

            u64 acc2[8];
            {
                u64 bp2 = pk2(__ldg(&cb_[2 * pr]), __ldg(&cb_[2 * pr + 1]));
#pragma unroll
                for (int i = 0; i < 8; i++) acc2[i] = bp2;
            }
            const float* wbase = g_cwI + m * 26624 + pr * 1664;
            u64 wp[13];
#pragma unroll
            for (int kk = 0; kk < 13; kk++)
                wp[kk] = __ldg((const u64*)(wbase + 2 * kk));      // ci = 0
#pragma unroll 2
            for (int ci = 0; ci < 64; ci++) {
                // prefetch weights for ci+1 (in flight during this ci's compute)
                u64 wn[13];
                {
                    const int cn = (ci < 63) ? ci + 1 : 63;
                    const float* wr = wbase + cn * 26;
#pragma unroll
                    for (int kk = 0; kk < 13; kk++)
                        wn[kk] = __ldg((const u64*)(wr + 2 * kk));
                }
                const float* xp = s + OFF_IN + ci * WR;
                float xw[20];
#pragma unroll
                for (int q4 = 0; q4 < 5; q4++) {
                    int cc = cb + q4;
                    float4 t4 = *(const float4*)(xp + ((cc + (cc >> 3)) << 2));
                    xw[q4 * 4 + 0] = t4.x; xw[q4 * 4 + 1] = t4.y;
                    xw[q4 * 4 + 2] = t4.z; xw[q4 * 4 + 3] = t4.w;
                }
                // 8-slot dup ring: dx[(kk+i)&7] == dup2(xw[kk+i])
                u64 dx[8];
#pragma unroll
                for (int j = 0; j < 8; j++) dx[j] = dup2(xw[j]);
#pragma unroll
                for (int kk = 0; kk < 13; kk++) {
#pragma unroll
                    for (int i = 0; i < 8; i++)
                        fma2(acc2[i], dx[(kk + i) & 7], wp[kk]);
                    if (kk + 8 < 20)
                        dx[kk & 7] = dup2(xw[kk + 8]);
                }
#pragma unroll
                for (int kk = 0; kk < 13; kk++) wp[kk] = wn[kk];
            }
            float o0[8], o1[8];
#pragma unroll
            for (int i = 0; i < 8; i++) upk2(o0[i], o1[i], acc2[i]);
            *(float4*)(dst + (2 * pr) * QS + l0)         = make_float4(o0[0], o0[1], o0[2], o0[3]);
            *(float4*)(dst + (2 * pr) * QS + l0 + 4)     = make_float4(o0[4], o0[5], o0[6], o0[7]);
            *(float4*)(dst + (2 * pr + 1) * QS + l0)     = make_float4(o1[0], o1[1], o1[2], o1[3]);
            *(float4*)(dst + (2 * pr + 1) * QS + l0 + 4) = make_float4(o1[4], o1[5], o1[6], o1[7]);
        }
    }

    // ============ Phase 2: per-head projections + attention, 4 passes of 4 heads ============
    {
        const int dc = lane & 3, tr = lane >> 2;
        const float inv_t = 0.08838834764831845f;   // 1/sqrt(128)
#pragma unroll 1
        for (int p = 0; p < 4; p++) {
            __syncthreads();
            {
                const int g = w, hl = g / 3, mm = g % 3;
                const float* Bsrc = (mm == 0 ? w_qs : mm == 1 ? w_ks : w_vs) + (p * 4 + hl) * 4096;
                gemm32<4>(s + OFF_QKV + mm * 4224, Bsrc,
                          s + OFF_SCR + hl * 3264 + mm * 1088, 0, tr, dc);
            }
            {
                const int g = 8 + (w >> 1), hl = g / 3, mm = g % 3;
                const float* Bsrc = (mm == 0 ? w_qs : mm == 1 ? w_ks : w_vs) + (p * 4 + hl) * 4096;
                gemm32<2>(s + OFF_QKV + mm * 4224, Bsrc,
                          s + OFF_SCR + hl * 3264 + mm * 1088, (w & 1) * 16, tr, dc);
            }
            __syncthreads();
            {
                const int hl = w >> 1, qbase = (w & 1) * 16;
                float* qh = s + OFF_SCR + hl * 3264;
                float* kh = qh + 1088;
                float* vh = qh + 2176;
                const float* qr0 = qh + (qbase + tr) * SCS;
                const float* qr1 = qh + (qbase + tr + 8) * SCS;
                u64 sc2[2][8];
#pragma unroll
                for (int i = 0; i < 2; i++)
#pragma unroll
                    for (int j = 0; j < 8; j++) sc2[i][j] = 0ull;
#pragma unroll 4
                for (int d2 = 0; d2 < 16; d2++) {
                    u64 q0 = lds64(qr0 + 2 * d2);
                    u64 q1 = lds64(qr1 + 2 * d2);
#pragma unroll
                    for (int j = 0; j < 8; j++) {
                        u64 kv = lds64(kh + (dc * 8 + j) * SCS + 2 * d2);
                        fma2(sc2[0][j], q0, kv);
                        fma2(sc2[1][j], q1, kv);
                    }
                }
                float sc[2][8];
#pragma unroll
                for (int i = 0; i < 2; i++)
#pragma unroll
                    for (int j = 0; j < 8; j++) {
                        float lo, hi; upk2(lo, hi, sc2[i][j]); sc[i][j] = lo + hi;
                    }
#pragma unroll
                for (int i = 0; i < 2; i++) {
                    float mx = -1e30f;
#pragma unroll
                    for (int j = 0; j < 8; j++) { sc[i][j] *= inv_t; mx = fmaxf(mx, sc[i][j]); }
                    mx = fmaxf(mx, __shfl_xor_sync(0xffffffffu, mx, 1));
                    mx = fmaxf(mx, __shfl_xor_sync(0xffffffffu, mx, 2));
                    float sum = 0.f;
#pragma unroll
                    for (int j = 0; j < 8; j++) { sc[i][j] = __expf(sc[i][j] - mx); sum += sc[i][j]; }
                    sum += __shfl_xor_sync(0xffffffffu, sum, 1);
                    sum += __shfl_xor_sync(0xffffffffu, sum, 2);
                    float inv = 1.f / sum;
#pragma unroll
                    for (int j = 0; j < 8; j++) sc[i][j] *= inv;
                }
#pragma unroll
                for (int i = 0; i < 2; i++)
#pragma unroll
                    for (int j = 0; j < 8; j++)
                        qh[(qbase + tr + 8 * i) * SCS + dc * 8 + j] = sc[i][j];
                __syncwarp();
                u64 av2[2][4];
#pragma unroll
                for (int i = 0; i < 2; i++)
#pragma unroll
                    for (int jp = 0; jp < 4; jp++) av2[i][jp] = 0ull;
#pragma unroll 4
                for (int k2 = 0; k2 < 32; k2++) {
                    u64 a0 = dup2(qr0[k2]);
                    u64 a1 = dup2(qr1[k2]);
#pragma unroll
                    for (int jp = 0; jp < 4; jp++) {
                        u64 vv = lds64(vh + k2 * SCS + dc * 8 + 2 * jp);
                        fma2(av2[0][jp], a0, vv);
                        fma2(av2[1][jp], a1, vv);
                    }
                }
                const int h = p * 4 + hl;
#pragma unroll
                for (int i = 0; i < 2; i++)
#pragma unroll
                    for (int jp = 0; jp < 4; jp++)
                        *reinterpret_cast<u64*>(gatt + (qbase + tr + 8 * i) * 512
                                                + h * 32 + dc * 8 + 2 * jp) = av2[i][jp];
            }
        }
    }

    // ============ Phase 3: stage ATT from gmem, proj with transposed weights ============
    __syncthreads();
    for (int i = tid; i < 16384; i += NT)
        s[OFF_ATT + (i >> 9) * 516 + (i & 511)] = gatt[i];
    for (int i = tid; i < 32 * 12; i += NT) {
        int t = i / 12, j = i % 12;
        int f = (j < 6) ? j : j + 128;
        s[OFF_Y + t * WR + SWZ(f)] = 0.f;
    }
    __syncthreads();
    {
        const int tq = lane >> 4, ml = lane & 15;
        const int m0 = (w >> 2) * 64 + ml * 4;      // 4 m's per thread
        const int tb = (w & 3) * 8 + tq * 4;        // 4 t-rows per thread
        u64 acc[4][2];
#pragma unroll
        for (int t = 0; t < 4; t++) { acc[t][0] = 0ull; acc[t][1] = 0ull; }
        const float* bp0 = g_pwT + m0;
        ulonglong2 c0 = __ldg((const ulonglong2*)bp0);
        ulonglong2 c1 = __ldg((const ulonglong2*)(bp0 + 128));
#pragma unroll 2
        for (int j2 = 0; j2 < 256; j2++) {                   // full 512 reduction
            const int nj = (j2 < 255) ? (2 * j2 + 2) : 510;
            ulonglong2 n0 = __ldg((const ulonglong2*)(bp0 + nj * 128));
            ulonglong2 n1 = __ldg((const ulonglong2*)(bp0 + (nj + 1) * 128));
#pragma unroll
            for (int t = 0; t < 4; t++) {
                u64 a01 = lds64(s + OFF_ATT + (tb + t) * 516 + 2 * j2);
                float alo, ahi; upk2(alo, ahi, a01);
                u64 d0 = dup2(alo), d1 = dup2(ahi);
                fma2(acc[t][0], d0, c0.x); fma2(acc[t][1], d0, c0.y);
                fma2(acc[t][0], d1, c1.x); fma2(acc[t][1], d1, c1.y);
            }
            c0 = n0; c1 = n1;
        }
        float4 bb = __ldg((const float4*)(proj_b + m0));
#pragma unroll
        for (int t = 0; t < 4; t++) {
            float y0, y1, y2, y3;
            upk2(y0, y1, acc[t][0]);
            upk2(y2, y3, acc[t][1]);
            float* yrow = s + OFF_Y + (tb + t) * WR;
            const int f0 = 6 + m0, c0i = f0 >> 2;           // floats 2,3 of chunk
            const int f1 = 8 + m0, c1i = f1 >> 2;           // floats 0,1 of chunk
            *reinterpret_cast<u64*>(yrow + ((c0i + (c0i >> 3)) << 2) + 2) = pk2(y0 + bb.x, y1 + bb.y);
            *reinterpret_cast<u64*>(yrow + ((c1i + (c1i >> 3)) << 2))     = pk2(y2 + bb.z, y3 + bb.w);
        }
    }
    __syncthreads();

    // ====== Phase 4: final conv (32->64) + residual, two co-pair passes, pipelined weights ======
    {
        const int qd = tid >> 4;          // 0..15
        const int g  = tid & 15;
        const int l0 = g * 8;
        const int cb = g * 2;
        const float* qres = gq + boff;
#pragma unroll 1
        for (int pass = 0; pass < 2; pass++) {
            const int pr = 2 * qd + pass;             // pair 0..31, co = 2pr, 2pr+1
            u64 acc2[8];
            {
                u64 bp2 = pk2(__ldg(&fc_b[2 * pr]), __ldg(&fc_b[2 * pr + 1]));
#pragma unroll
                for (int i = 0; i < 8; i++) acc2[i] = bp2;
            }
            const float* wbase = g_fcI + pr * 832;
            u64 wp[13];
#pragma unroll
            for (int kk = 0; kk < 13; kk++)
                wp[kk] = __ldg((const u64*)(wbase + 2 * kk));
#pragma unroll 2
            for (int ci = 0; ci < 32; ci++) {
                u64 wn[13];
                {
                    const int cn = (ci < 31) ? ci + 1 : 31;
                    const float* wr = wbase + cn * 26;
#pragma unroll
                    for (int kk = 0; kk < 13; kk++)
                        wn[kk] = __ldg((const u64*)(wr + 2 * kk));
                }
                const float* xp = s + OFF_Y + ci * WR;
                float xw[20];
#pragma unroll
                for (int q4 = 0; q4 < 5; q4++) {
                    int cc = cb + q4;
                    float4 t4 = *(const float4*)(xp + ((cc + (cc >> 3)) << 2));
                    xw[q4 * 4 + 0] = t4.x; xw[q4 * 4 + 1] = t4.y;
                    xw[q4 * 4 + 2] = t4.z; xw[q4 * 4 + 3] = t4.w;
                }
                u64 dx[8];
#pragma unroll
                for (int j = 0; j < 8; j++) dx[j] = dup2(xw[j]);
#pragma unroll
                for (int kk = 0; kk < 13; kk++) {
#pragma unroll
                    for (int i = 0; i < 8; i++)
                        fma2(acc2[i], dx[(kk + i) & 7], wp[kk]);
                    if (kk + 8 < 20)
                        dx[kk & 7] = dup2(xw[kk + 8]);
                }
#pragma unroll
                for (int kk = 0; kk < 13; kk++) wp[kk] = wn[kk];
            }
            float o0[8], o1[8];
#pragma unroll
            for (int i = 0; i < 8; i++) upk2(o0[i], o1[i], acc2[i]);
#pragma unroll
            for (int c2 = 0; c2 < 2; c2++) {
                const int co = 2 * pr + c2;
                const float* oc = (c2 == 0) ? o0 : o1;
                float4 r0 = __ldg((const float4*)(qres + co * 128 + l0));
                float4 r1 = __ldg((const float4*)(qres + co * 128 + l0 + 4));
                *(float4*)(s + OFF_Z + co * 128 + l0) =
                    make_float4(oc[0] + r0.x, oc[1] + r0.y, oc[2] + r0.z, oc[3] + r0.w);
                *(float4*)(s + OFF_Z + co * 128 + l0 + 4) =
                    make_float4(oc[4] + r1.x, oc[5] + r1.y, oc[6] + r1.z, oc[7] + r1.w);
            }
        }
    }
    __syncthreads();

    // ============ Phase 5: LayerNorm (unbiased std, /(sigma+eps)) ============
    {
#pragma unroll
        for (int it = 0; it < 8; it++) {
            int r = w + it * 8;
            const float* zr = s + OFF_Z + r * 128;
            float v0 = zr[lane], v1 = zr[lane + 32], v2 = zr[lane + 64], v3 = zr[lane + 96];
            float sm = v0 + v1 + v2 + v3;
#pragma unroll
            for (int o = 16; o > 0; o >>= 1) sm += __shfl_xor_sync(0xffffffffu, sm, o);
            float mu = sm * (1.f / 128.f);
            float d0 = v0 - mu, d1 = v1 - mu, d2 = v2 - mu, d3 = v3 - mu;
            float s2 = d0 * d0 + d1 * d1 + d2 * d2 + d3 * d3;
#pragma unroll
            for (int o = 16; o > 0; o >>= 1) s2 += __shfl_xor_sync(0xffffffffu, s2, o);
            float sigma = sqrtf(s2 * (1.f / 127.f));
            float inv = 1.f / (sigma + 1e-3f);
            float* orow = out + boff + r * 128;
            orow[lane]      = d0 * inv * __ldg(&ln_a[lane])      + __ldg(&ln_b[lane]);
            orow[lane + 32] = d1 * inv * __ldg(&ln_a[lane + 32]) + __ldg(&ln_b[lane + 32]);
            orow[lane + 64] = d2 * inv * __ldg(&ln_a[lane + 64]) + __ldg(&ln_b[lane + 64]);
            orow[lane + 96] = d3 * inv * __ldg(&ln_a[lane + 96]) + __ldg(&ln_b[lane + 96]);
        }
    }
}

extern "C" void kernel_launch(void* const* d_in, const int* in_sizes, int n_in,
                              void* d_out, int out_size)
{
    const float* q      = (const float*)d_in[0];
    const float* k      = (const float*)d_in[1];
    const float* v      = (const float*)d_in[2];
    const float* cq_w   = (const float*)d_in[3];
    const float* cq_b   = (const float*)d_in[4];
    const float* ck_w   = (const float*)d_in[5];
    const float* ck_b   = (const float*)d_in[6];
    const float* cv_w   = (const float*)d_in[7];
    const float* cv_b   = (const float*)d_in[8];
    const float* w_qs   = (const float*)d_in[9];
    const float* w_ks   = (const float*)d_in[10];
    const float* w_vs   = (const float*)d_in[11];
    const float* proj_w = (const float*)d_in[12];
    const float* proj_b = (const float*)d_in[13];
    const float* fc_w   = (const float*)d_in[14];
    const float* fc_b   = (const float*)d_in[15];
    const float* ln_a   = (const float*)d_in[16];
    const float* ln_b   = (const float*)d_in[17];
    float* outp = (float*)d_out;

    const int B = in_sizes[0] / (64 * 128);

    transpose_pw_kernel<<<128, 512>>>(proj_w);
    interleave_cw_kernel<<<312, 256>>>(cq_w, ck_w, cv_w);
    interleave_fc_kernel<<<104, 256>>>(fc_w);

    cudaFuncSetAttribute(ha_kernel, cudaFuncAttributeMaxDynamicSharedMemorySize, SMEM_BYTES);
    cudaFuncSetAttribute(ha_kernel, cudaFuncAttributePreferredSharedMemoryCarveout, 100);
    ha_kernel<<<B, NT, SMEM_BYTES>>>(q, k, v, cq_w, cq_b, ck_w, ck_b, cv_w, cv_b,
                                     w_qs, w_ks, w_vs, proj_w, proj_b, fc_w, fc_b,
                                     ln_a, ln_b, outp);
}

// round 14
// speedup vs baseline: 1.5329x; 1.0097x over previous
#include <cuda_runtime.h>

// B=2048, DKV=64, L=128, H=16, DT=32, KW=13, PAD=6
#define NT 256
#define QS 132     // qb/kb/vb row stride
#define SCS 34     // qh/kh/vh scratch row stride
#define WR 160     // swizzled conv-window row stride (40 chunks of 16B)

// chunk skew c -> c + (c>>3) kills 64B-stride bank conflicts
#define SWZ(f) ((((((f) >> 2) + ((f) >> 5))) << 2) | ((f) & 3))

// shared layout (floats), peak 25728 (=102,912B) -> 2 CTAs/SM
#define OFF_QKV 0            // 3*32*132 = 12672            [P1 out, P2 A]
#define OFF_IN  12672        // 64*160 = 10240 -> 22912      [P1, swizzled rows]
#define OFF_SCR 12672        // 4 heads*3*32*34 = 13056 -> 25728 [P2]
#define OFF_Y   0            // 32*160 = 5120                [P3 -> P4, swizzled rows]
#define OFF_ATT 5120         // 32*516 = 16512 -> 21632      [P3]
#define OFF_Z   12288        // 8192 -> 20480 (over dead ATT) [P4 -> P5]
#define SMEM_FLOATS 25728
#define SMEM_BYTES (SMEM_FLOATS * 4)

typedef unsigned long long u64;

// gmem scratch (__device__ globals, no allocation)
__device__ float g_att[2048 * 32 * 512];   // per-batch attention concat
__device__ float g_pwT[512 * 128];         // proj_w transposed: pwT[j][m]
__device__ float g_cwI[3 * 28672];         // conv w pair-interleaved [m][pr16][ci64][28: kk*2+half]
__device__ float g_fcI[28672];             // fc w pair-interleaved  [pr32][ci32][28: kk*2+half]

__device__ __forceinline__ u64 pk2(float lo, float hi) {
    u64 r; asm("mov.b64 %0,{%1,%2};" : "=l"(r) : "f"(lo), "f"(hi)); return r;
}
__device__ __forceinline__ u64 dup2(float x) { return pk2(x, x); }
__device__ __forceinline__ void upk2(float& lo, float& hi, u64 v) {
    asm("mov.b64 {%0,%1},%2;" : "=f"(lo), "=f"(hi) : "l"(v));
}
__device__ __forceinline__ void fma2(u64& d, u64 a, u64 b) {
    asm("fma.rn.f32x2 %0,%1,%2,%0;" : "+l"(d) : "l"(a), "l"(b));
}
__device__ __forceinline__ u64 lds64(const float* p) {
    return *reinterpret_cast<const u64*>(p);
}
// load 13 contiguous u64 weights via 6x LDG.128 + 1x LDG.64 (wr must be 16B-aligned)
__device__ __forceinline__ void ldw13(u64* wp, const float* wr) {
#pragma unroll
    for (int q = 0; q < 6; q++) {
        ulonglong2 t = __ldg((const ulonglong2*)(wr + 4 * q));
        wp[2 * q] = t.x; wp[2 * q + 1] = t.y;
    }
    wp[12] = __ldg((const u64*)(wr + 24));
}

__global__ void transpose_pw_kernel(const float* __restrict__ pw) {
    int idx = blockIdx.x * 512 + threadIdx.x;   // 65536 total
    int j = idx >> 7, m = idx & 127;
    g_pwT[idx] = pw[m * 512 + j];
}

__global__ void interleave_cw_kernel(const float* __restrict__ cq,
                                     const float* __restrict__ ck,
                                     const float* __restrict__ cv) {
    int idx = blockIdx.x * 256 + threadIdx.x;   // 3*26624 = 79872
    if (idx >= 3 * 26624) return;
    int m = idx / 26624, i = idx % 26624;
    const float* src = (m == 0) ? cq : (m == 1) ? ck : cv;
    int co = i / 832, r = i % 832, ci = r / 13, kk = r % 13;
    g_cwI[m * 28672 + (co >> 1) * 1792 + ci * 28 + kk * 2 + (co & 1)] = src[i];
}

__global__ void interleave_fc_kernel(const float* __restrict__ fcw) {
    int idx = blockIdx.x * 256 + threadIdx.x;   // 26624
    if (idx >= 26624) return;
    int co = idx / 416, r = idx % 416, ci = r / 13, kk = r % 13;
    g_fcI[(co >> 1) * 896 + ci * 28 + kk * 2 + (co & 1)] = fcw[idx];
}

// One warp: C(32x32) = A(32x128) @ B(128x32); A smem (stride QS, lds64 l-pairs),
// B streamed from gmem, C to smem (stride SCS).
template<int TN>
__device__ __forceinline__ void gemm32(const float* __restrict__ A,
                                       const float* __restrict__ Bg,
                                       float* __restrict__ C,
                                       int tbase, int tr, int dc)
{
    u64 acc[TN][4];
#pragma unroll
    for (int i = 0; i < TN; i++)
#pragma unroll
        for (int j = 0; j < 4; j++) acc[i][j] = 0ull;
    const float* Ar[TN];
#pragma unroll
    for (int i = 0; i < TN; i++) Ar[i] = A + (tbase + tr + 8 * i) * QS;

    const float* bp = Bg + dc * 8;
    ulonglong2 cE0 = __ldg((const ulonglong2*)bp);
    ulonglong2 cE1 = __ldg((const ulonglong2*)(bp + 4));
    ulonglong2 cO0 = __ldg((const ulonglong2*)(bp + 32));
    ulonglong2 cO1 = __ldg((const ulonglong2*)(bp + 36));
#pragma unroll 2
    for (int l2 = 0; l2 < 64; l2++) {
        const int nb = (l2 < 63) ? (2 * l2 + 2) : 126;
        ulonglong2 nE0 = __ldg((const ulonglong2*)(bp + nb * 32));
        ulonglong2 nE1 = __ldg((const ulonglong2*)(bp + nb * 32 + 4));
        ulonglong2 nO0 = __ldg((const ulonglong2*)(bp + nb * 32 + 32));
        ulonglong2 nO1 = __ldg((const ulonglong2*)(bp + nb * 32 + 36));
#pragma unroll
        for (int i = 0; i < TN; i++) {
            u64 a01 = lds64(Ar[i] + 2 * l2);
            float alo, ahi; upk2(alo, ahi, a01);
            u64 d0 = dup2(alo), d1 = dup2(ahi);
            fma2(acc[i][0], d0, cE0.x); fma2(acc[i][1], d0, cE0.y);
            fma2(acc[i][2], d0, cE1.x); fma2(acc[i][3], d0, cE1.y);
            fma2(acc[i][0], d1, cO0.x); fma2(acc[i][1], d1, cO0.y);
            fma2(acc[i][2], d1, cO1.x); fma2(acc[i][3], d1, cO1.y);
        }
        cE0 = nE0; cE1 = nE1; cO0 = nO0; cO1 = nO1;
    }
#pragma unroll
    for (int i = 0; i < TN; i++)
#pragma unroll
        for (int j = 0; j < 4; j++)
            *reinterpret_cast<u64*>(C + (tbase + tr + 8 * i) * SCS + dc * 8 + 2 * j) = acc[i][j];
}

__global__ void __launch_bounds__(NT, 2)
ha_kernel(const float* __restrict__ gq, const float* __restrict__ gk, const float* __restrict__ gv,
          const float* __restrict__ cq_w, const float* __restrict__ cq_b,
          const float* __restrict__ ck_w, const float* __restrict__ ck_b,
          const float* __restrict__ cv_w, const float* __restrict__ cv_b,
          const float* __restrict__ w_qs, const float* __restrict__ w_ks, const float* __restrict__ w_vs,
          const float* __restrict__ proj_w, const float* __restrict__ proj_b,
          const float* __restrict__ fc_w, const float* __restrict__ fc_b,
          const float* __restrict__ ln_a, const float* __restrict__ ln_b,
          float* __restrict__ out)
{
    extern __shared__ float s[];
    const int tid  = threadIdx.x;
    const int w    = tid >> 5;       // 0..7
    const int lane = tid & 31;
    const size_t boff = (size_t)blockIdx.x * 8192;   // 64*128
    float* gatt = g_att + (size_t)blockIdx.x * 32 * 512;

    // ====== Phase 1: conv1d q/k/v (64->32), co-pair f32x2, pipelined wide weight loads ======
    {
        const int pr = tid >> 4;          // co-pair 0..15 (co = 2pr, 2pr+1)
        const int g  = tid & 15;
        const int l0 = g * 8;
        const int cb = g * 2;
#pragma unroll 1
        for (int m = 0; m < 3; m++) {
            const float* xin = (m == 0 ? gq : m == 1 ? gk : gv) + boff;
            const float* cb_ = (m == 0 ? cq_b : m == 1 ? ck_b : cv_b);
            float* dst = s + OFF_QKV + m * 4224;
            __syncthreads();
            for (int i = tid; i < 64 * 12; i += NT) {
                int ci = i / 12, j = i % 12;
                int f = (j < 6) ? j : j + 128;
                s[OFF_IN + ci * WR + SWZ(f)] = 0.f;
            }
            for (int i = tid; i < 8192; i += NT) {
                int f = 6 + (i & 127);
                s[OFF_IN + (i >> 7) * WR + SWZ(f)] = xin[i];
            }
            __syncthreads();

            u64 acc2[8];
            {
                u64 bp2 = pk2(__ldg(&cb_[2 * pr]), __ldg(&cb_[2 * pr + 1]));
#pragma unroll
                for (int i = 0; i < 8; i++) acc2[i] = bp2;
            }
            const float* wbase = g_cwI + m * 28672 + pr * 1792;
            u64 wp[13];
            ldw13(wp, wbase);                                  // ci = 0
#pragma unroll 2
            for (int ci = 0; ci < 64; ci++) {
                // prefetch weights for ci+1 (in flight during this ci's compute)
                u64 wn[13];
                {
                    const int cn = (ci < 63) ? ci + 1 : 63;
                    ldw13(wn, wbase + cn * 28);
                }
                const float* xp = s + OFF_IN + ci * WR;
                float xw[20];
#pragma unroll
                for (int q4 = 0; q4 < 5; q4++) {
                    int cc = cb + q4;
                    float4 t4 = *(const float4*)(xp + ((cc + (cc >> 3)) << 2));
                    xw[q4 * 4 + 0] = t4.x; xw[q4 * 4 + 1] = t4.y;
                    xw[q4 * 4 + 2] = t4.z; xw[q4 * 4 + 3] = t4.w;
                }
                // 8-slot dup ring: dx[(kk+i)&7] == dup2(xw[kk+i])
                u64 dx[8];
#pragma unroll
                for (int j = 0; j < 8; j++) dx[j] = dup2(xw[j]);
#pragma unroll
                for (int kk = 0; kk < 13; kk++) {
#pragma unroll
                    for (int i = 0; i < 8; i++)
                        fma2(acc2[i], dx[(kk + i) & 7], wp[kk]);
                    if (kk + 8 < 20)
                        dx[kk & 7] = dup2(xw[kk + 8]);
                }
#pragma unroll
                for (int kk = 0; kk < 13; kk++) wp[kk] = wn[kk];
            }
            float o0[8], o1[8];
#pragma unroll
            for (int i = 0; i < 8; i++) upk2(o0[i], o1[i], acc2[i]);
            *(float4*)(dst + (2 * pr) * QS + l0)         = make_float4(o0[0], o0[1], o0[2], o0[3]);
            *(float4*)(dst + (2 * pr) * QS + l0 + 4)     = make_float4(o0[4], o0[5], o0[6], o0[7]);
            *(float4*)(dst + (2 * pr + 1) * QS + l0)     = make_float4(o1[0], o1[1], o1[2], o1[3]);
            *(float4*)(dst + (2 * pr + 1) * QS + l0 + 4) = make_float4(o1[4], o1[5], o1[6], o1[7]);
        }
    }

    // ============ Phase 2: per-head projections + attention, 4 passes of 4 heads ============
    {
        const int dc = lane & 3, tr = lane >> 2;
        const float inv_t = 0.08838834764831845f;   // 1/sqrt(128)
#pragma unroll 1
        for (int p = 0; p < 4; p++) {
            __syncthreads();
            {
                const int g = w, hl = g / 3, mm = g % 3;
                const float* Bsrc = (mm == 0 ? w_qs : mm == 1 ? w_ks : w_vs) + (p * 4 + hl) * 4096;
                gemm32<4>(s + OFF_QKV + mm * 4224, Bsrc,
                          s + OFF_SCR + hl * 3264 + mm * 1088, 0, tr, dc);
            }
            {
                const int g = 8 + (w >> 1), hl = g / 3, mm = g % 3;
                const float* Bsrc = (mm == 0 ? w_qs : mm == 1 ? w_ks : w_vs) + (p * 4 + hl) * 4096;
                gemm32<2>(s + OFF_QKV + mm * 4224, Bsrc,
                          s + OFF_SCR + hl * 3264 + mm * 1088, (w & 1) * 16, tr, dc);
            }
            __syncthreads();
            {
                const int hl = w >> 1, qbase = (w & 1) * 16;
                float* qh = s + OFF_SCR + hl * 3264;
                float* kh = qh + 1088;
                float* vh = qh + 2176;
                const float* qr0 = qh + (qbase + tr) * SCS;
                const float* qr1 = qh + (qbase + tr + 8) * SCS;
                u64 sc2[2][8];
#pragma unroll
                for (int i = 0; i < 2; i++)
#pragma unroll
                    for (int j = 0; j < 8; j++) sc2[i][j] = 0ull;
#pragma unroll 4
                for (int d2 = 0; d2 < 16; d2++) {
                    u64 q0 = lds64(qr0 + 2 * d2);
                    u64 q1 = lds64(qr1 + 2 * d2);
#pragma unroll
                    for (int j = 0; j < 8; j++) {
                        u64 kv = lds64(kh + (dc * 8 + j) * SCS + 2 * d2);
                        fma2(sc2[0][j], q0, kv);
                        fma2(sc2[1][j], q1, kv);
                    }
                }
                float sc[2][8];
#pragma unroll
                for (int i = 0; i < 2; i++)
#pragma unroll
                    for (int j = 0; j < 8; j++) {
                        float lo, hi; upk2(lo, hi, sc2[i][j]); sc[i][j] = lo + hi;
                    }
#pragma unroll
                for (int i = 0; i < 2; i++) {
                    float mx = -1e30f;
#pragma unroll
                    for (int j = 0; j < 8; j++) { sc[i][j] *= inv_t; mx = fmaxf(mx, sc[i][j]); }
                    mx = fmaxf(mx, __shfl_xor_sync(0xffffffffu, mx, 1));
                    mx = fmaxf(mx, __shfl_xor_sync(0xffffffffu, mx, 2));
                    float sum = 0.f;
#pragma unroll
                    for (int j = 0; j < 8; j++) { sc[i][j] = __expf(sc[i][j] - mx); sum += sc[i][j]; }
                    sum += __shfl_xor_sync(0xffffffffu, sum, 1);
                    sum += __shfl_xor_sync(0xffffffffu, sum, 2);
                    float inv = 1.f / sum;
#pragma unroll
                    for (int j = 0; j < 8; j++) sc[i][j] *= inv;
                }
#pragma unroll
                for (int i = 0; i < 2; i++)
#pragma unroll
                    for (int j = 0; j < 8; j++)
                        qh[(qbase + tr + 8 * i) * SCS + dc * 8 + j] = sc[i][j];
                __syncwarp();
                u64 av2[2][4];
#pragma unroll
                for (int i = 0; i < 2; i++)
#pragma unroll
                    for (int jp = 0; jp < 4; jp++) av2[i][jp] = 0ull;
#pragma unroll 4
                for (int k2 = 0; k2 < 32; k2++) {
                    u64 a0 = dup2(qr0[k2]);
                    u64 a1 = dup2(qr1[k2]);
#pragma unroll
                    for (int jp = 0; jp < 4; jp++) {
                        u64 vv = lds64(vh + k2 * SCS + dc * 8 + 2 * jp);
                        fma2(av2[0][jp], a0, vv);
                        fma2(av2[1][jp], a1, vv);
                    }
                }
                const int h = p * 4 + hl;
#pragma unroll
                for (int i = 0; i < 2; i++) {
                    float* gp = gatt + (qbase + tr + 8 * i) * 512 + h * 32 + dc * 8;
                    *reinterpret_cast<ulonglong2*>(gp)     = make_ulonglong2(av2[i][0], av2[i][1]);
                    *reinterpret_cast<ulonglong2*>(gp + 4) = make_ulonglong2(av2[i][2], av2[i][3]);
                }
            }
        }
    }

    // ============ Phase 3: stage ATT from gmem (float4), proj with transposed weights ============
    __syncthreads();
    for (int i = tid * 4; i < 16384; i += NT * 4) {
        float4 v4 = *(const float4*)(gatt + i);
        *(float4*)(s + OFF_ATT + (i >> 9) * 516 + (i & 511)) = v4;
    }
    for (int i = tid; i < 32 * 12; i += NT) {
        int t = i / 12, j = i % 12;
        int f = (j < 6) ? j : j + 128;
        s[OFF_Y + t * WR + SWZ(f)] = 0.f;
    }
    __syncthreads();
    {
        const int tq = lane >> 4, ml = lane & 15;
        const int m0 = (w >> 2) * 64 + ml * 4;      // 4 m's per thread
        const int tb = (w & 3) * 8 + tq * 4;        // 4 t-rows per thread
        u64 acc[4][2];
#pragma unroll
        for (int t = 0; t < 4; t++) { acc[t][0] = 0ull; acc[t][1] = 0ull; }
        const float* bp0 = g_pwT + m0;
        ulonglong2 c0 = __ldg((const ulonglong2*)bp0);
        ulonglong2 c1 = __ldg((const ulonglong2*)(bp0 + 128));
#pragma unroll 2
        for (int j2 = 0; j2 < 256; j2++) {                   // full 512 reduction
            const int nj = (j2 < 255) ? (2 * j2 + 2) : 510;
            ulonglong2 n0 = __ldg((const ulonglong2*)(bp0 + nj * 128));
            ulonglong2 n1 = __ldg((const ulonglong2*)(bp0 + (nj + 1) * 128));
#pragma unroll
            for (int t = 0; t < 4; t++) {
                u64 a01 = lds64(s + OFF_ATT + (tb + t) * 516 + 2 * j2);
                float alo, ahi; upk2(alo, ahi, a01);
                u64 d0 = dup2(alo), d1 = dup2(ahi);
                fma2(acc[t][0], d0, c0.x); fma2(acc[t][1], d0, c0.y);
                fma2(acc[t][0], d1, c1.x); fma2(acc[t][1], d1, c1.y);
            }
            c0 = n0; c1 = n1;
        }
        float4 bb = __ldg((const float4*)(proj_b + m0));
#pragma unroll
        for (int t = 0; t < 4; t++) {
            float y0, y1, y2, y3;
            upk2(y0, y1, acc[t][0]);
            upk2(y2, y3, acc[t][1]);
            float* yrow = s + OFF_Y + (tb + t) * WR;
            const int f0 = 6 + m0, c0i = f0 >> 2;           // floats 2,3 of chunk
            const int f1 = 8 + m0, c1i = f1 >> 2;           // floats 0,1 of chunk
            *reinterpret_cast<u64*>(yrow + ((c0i + (c0i >> 3)) << 2) + 2) = pk2(y0 + bb.x, y1 + bb.y);
            *reinterpret_cast<u64*>(yrow + ((c1i + (c1i >> 3)) << 2))     = pk2(y2 + bb.z, y3 + bb.w);
        }
    }
    __syncthreads();

    // ====== Phase 4: final conv (32->64) + residual, two co-pair passes, wide pipelined weights ======
    {
        const int qd = tid >> 4;          // 0..15
        const int g  = tid & 15;
        const int l0 = g * 8;
        const int cb = g * 2;
        const float* qres = gq + boff;
#pragma unroll 1
        for (int pass = 0; pass < 2; pass++) {
            const int pr = 2 * qd + pass;             // pair 0..31, co = 2pr, 2pr+1
            u64 acc2[8];
            {
                u64 bp2 = pk2(__ldg(&fc_b[2 * pr]), __ldg(&fc_b[2 * pr + 1]));
#pragma unroll
                for (int i = 0; i < 8; i++) acc2[i] = bp2;
            }
            const float* wbase = g_fcI + pr * 896;
            u64 wp[13];
            ldw13(wp, wbase);
#pragma unroll 2
            for (int ci = 0; ci < 32; ci++) {
                u64 wn[13];
                {
                    const int cn = (ci < 31) ? ci + 1 : 31;
                    ldw13(wn, wbase + cn * 28);
                }
                const float* xp = s + OFF_Y + ci * WR;
                float xw[20];
#pragma unroll
                for (int q4 = 0; q4 < 5; q4++) {
                    int cc = cb + q4;
                    float4 t4 = *(const float4*)(xp + ((cc + (cc >> 3)) << 2));
                    xw[q4 * 4 + 0] = t4.x; xw[q4 * 4 + 1] = t4.y;
                    xw[q4 * 4 + 2] = t4.z; xw[q4 * 4 + 3] = t4.w;
                }
                u64 dx[8];
#pragma unroll
                for (int j = 0; j < 8; j++) dx[j] = dup2(xw[j]);
#pragma unroll
                for (int kk = 0; kk < 13; kk++) {
#pragma unroll
                    for (int i = 0; i < 8; i++)
                        fma2(acc2[i], dx[(kk + i) & 7], wp[kk]);
                    if (kk + 8 < 20)
                        dx[kk & 7] = dup2(xw[kk + 8]);
                }
#pragma unroll
                for (int kk = 0; kk < 13; kk++) wp[kk] = wn[kk];
            }
            float o0[8], o1[8];
#pragma unroll
            for (int i = 0; i < 8; i++) upk2(o0[i], o1[i], acc2[i]);
#pragma unroll
            for (int c2 = 0; c2 < 2; c2++) {
                const int co = 2 * pr + c2;
                const float* oc = (c2 == 0) ? o0 : o1;
                float4 r0 = __ldg((const float4*)(qres + co * 128 + l0));
                float4 r1 = __ldg((const float4*)(qres + co * 128 + l0 + 4));
                *(float4*)(s + OFF_Z + co * 128 + l0) =
                    make_float4(oc[0] + r0.x, oc[1] + r0.y, oc[2] + r0.z, oc[3] + r0.w);
                *(float4*)(s + OFF_Z + co * 128 + l0 + 4) =
                    make_float4(oc[4] + r1.x, oc[5] + r1.y, oc[6] + r1.z, oc[7] + r1.w);
            }
        }
    }
    __syncthreads();

    // ============ Phase 5: LayerNorm (unbiased std, /(sigma+eps)) ============
    {
#pragma unroll
        for (int it = 0; it < 8; it++) {
            int r = w + it * 8;
            const float* zr = s + OFF_Z + r * 128;
            float v0 = zr[lane], v1 = zr[lane + 32], v2 = zr[lane + 64], v3 = zr[lane + 96];
            float sm = v0 + v1 + v2 + v3;
#pragma unroll
            for (int o = 16; o > 0; o >>= 1) sm += __shfl_xor_sync(0xffffffffu, sm, o);
            float mu = sm * (1.f / 128.f);
            float d0 = v0 - mu, d1 = v1 - mu, d2 = v2 - mu, d3 = v3 - mu;
            float s2 = d0 * d0 + d1 * d1 + d2 * d2 + d3 * d3;
#pragma unroll
            for (int o = 16; o > 0; o >>= 1) s2 += __shfl_xor_sync(0xffffffffu, s2, o);
            float sigma = sqrtf(s2 * (1.f / 127.f));
            float inv = 1.f / (sigma + 1e-3f);
            float* orow = out + boff + r * 128;
            orow[lane]      = d0 * inv * __ldg(&ln_a[lane])      + __ldg(&ln_b[lane]);
            orow[lane + 32] = d1 * inv * __ldg(&ln_a[lane + 32]) + __ldg(&ln_b[lane + 32]);
            orow[lane + 64] = d2 * inv * __ldg(&ln_a[lane + 64]) + __ldg(&ln_b[lane + 64]);
            orow[lane + 96] = d3 * inv * __ldg(&ln_a[lane + 96]) + __ldg(&ln_b[lane + 96]);
        }
    }
}

extern "C" void kernel_launch(void* const* d_in, const int* in_sizes, int n_in,
                              void* d_out, int out_size)
{
    const float* q      = (const float*)d_in[0];
    const float* k      = (const float*)d_in[1];
    const float* v      = (const float*)d_in[2];
    const float* cq_w   = (const float*)d_in[3];
    const float* cq_b   = (const float*)d_in[4];
    const float* ck_w   = (const float*)d_in[5];
    const float* ck_b   = (const float*)d_in[6];
    const float* cv_w   = (const float*)d_in[7];
    const float* cv_b   = (const float*)d_in[8];
    const float* w_qs   = (const float*)d_in[9];
    const float* w_ks   = (const float*)d_in[10];
    const float* w_vs   = (const float*)d_in[11];
    const float* proj_w = (const float*)d_in[12];
    const float* proj_b = (const float*)d_in[13];
    const float* fc_w   = (const float*)d_in[14];
    const float* fc_b   = (const float*)d_in[15];
    const float* ln_a   = (const float*)d_in[16];
    const float* ln_b   = (const float*)d_in[17];
    float* outp = (float*)d_out;

    const int B = in_sizes[0] / (64 * 128);

    transpose_pw_kernel<<<128, 512>>>(proj_w);
    interleave_cw_kernel<<<312, 256>>>(cq_w, ck_w, cv_w);
    interleave_fc_kernel<<<104, 256>>>(fc_w);

    cudaFuncSetAttribute(ha_kernel, cudaFuncAttributeMaxDynamicSharedMemorySize, SMEM_BYTES);
    cudaFuncSetAttribute(ha_kernel, cudaFuncAttributePreferredSharedMemoryCarveout, 100);
    ha_kernel<<<B, NT, SMEM_BYTES>>>(q, k, v, cq_w, cq_b, ck_w, ck_b, cv_w, cv_b,
                                     w_qs, w_ks, w_vs, proj_w, proj_b, fc_w, fc_b,
                                     ln_a, ln_b, outp);
}

// round 15
// speedup vs baseline: 1.5641x; 1.0203x over previous
#include <cuda_runtime.h>

// B=2048, DKV=64, L=128, H=16, DT=32, KW=13, PAD=6
#define NT 256
#define QS 132     // qb/kb/vb row stride
#define SCS 34     // qh/kh/vh scratch row stride
#define WR 160     // swizzled conv-window row stride (40 chunks of 16B)

// chunk skew c -> c + (c>>3) kills 64B-stride bank conflicts
#define SWZ(f) ((((((f) >> 2) + ((f) >> 5))) << 2) | ((f) & 3))

// shared layout (floats), peak 25728 (=102,912B) -> 2 CTAs/SM
#define OFF_QKV 0            // 3*32*132 = 12672            [P1 out, P2 A]
#define OFF_IN  12672        // 64*160 = 10240 -> 22912      [P1, swizzled rows]
#define OFF_SCR 12672        // 4 heads*3*32*34 = 13056 -> 25728 [P2]
#define OFF_Y   0            // 32*160 = 5120                [P3 -> P4, swizzled rows]
#define OFF_ATT 5120         // 32*516 = 16512 -> 21632      [P3]
#define OFF_Z   12288        // 8192 -> 20480 (over dead ATT) [P4 -> P5]
#define SMEM_FLOATS 25728
#define SMEM_BYTES (SMEM_FLOATS * 4)

typedef unsigned long long u64;

// gmem scratch (__device__ globals, no allocation)
__device__ float g_att[2048 * 32 * 512];   // per-batch attention concat
__device__ float g_pwT[512 * 128];         // proj_w transposed: pwT[j][m]
__device__ float g_cwI[3 * 28672];         // conv w pair-interleaved [m][pr16][ci64][28: kk*2+half]
__device__ float g_fcI[28672];             // fc w pair-interleaved  [pr32][ci32][28: kk*2+half]

__device__ __forceinline__ u64 pk2(float lo, float hi) {
    u64 r; asm("mov.b64 %0,{%1,%2};" : "=l"(r) : "f"(lo), "f"(hi)); return r;
}
__device__ __forceinline__ u64 dup2(float x) { return pk2(x, x); }
__device__ __forceinline__ void upk2(float& lo, float& hi, u64 v) {
    asm("mov.b64 {%0,%1},%2;" : "=f"(lo), "=f"(hi) : "l"(v));
}
__device__ __forceinline__ void fma2(u64& d, u64 a, u64 b) {
    asm("fma.rn.f32x2 %0,%1,%2,%0;" : "+l"(d) : "l"(a), "l"(b));
}
__device__ __forceinline__ u64 lds64(const float* p) {
    return *reinterpret_cast<const u64*>(p);
}
// load 13 contiguous u64 weights via 6x LDG.128 + 1x LDG.64 (wr 16B-aligned)
__device__ __forceinline__ void ldw13(u64* wp, const float* wr) {
#pragma unroll
    for (int q = 0; q < 6; q++) {
        ulonglong2 t = __ldg((const ulonglong2*)(wr + 4 * q));
        wp[2 * q] = t.x; wp[2 * q + 1] = t.y;
    }
    wp[12] = __ldg((const u64*)(wr + 24));
}

__global__ void transpose_pw_kernel(const float* __restrict__ pw) {
    int idx = blockIdx.x * 512 + threadIdx.x;   // 65536 total
    int j = idx >> 7, m = idx & 127;
    g_pwT[idx] = pw[m * 512 + j];
}

__global__ void interleave_cw_kernel(const float* __restrict__ cq,
                                     const float* __restrict__ ck,
                                     const float* __restrict__ cv) {
    int idx = blockIdx.x * 256 + threadIdx.x;   // 3*26624 = 79872
    if (idx >= 3 * 26624) return;
    int m = idx / 26624, i = idx % 26624;
    const float* src = (m == 0) ? cq : (m == 1) ? ck : cv;
    int co = i / 832, r = i % 832, ci = r / 13, kk = r % 13;
    g_cwI[m * 28672 + (co >> 1) * 1792 + ci * 28 + kk * 2 + (co & 1)] = src[i];
}

__global__ void interleave_fc_kernel(const float* __restrict__ fcw) {
    int idx = blockIdx.x * 256 + threadIdx.x;   // 26624
    if (idx >= 26624) return;
    int co = idx / 416, r = idx % 416, ci = r / 13, kk = r % 13;
    g_fcI[(co >> 1) * 896 + ci * 28 + kk * 2 + (co & 1)] = fcw[idx];
}

// One warp: C(32x32) = A(32x128) @ B(128x32); A smem via lds128 (4 l per load),
// B streamed from gmem with 2-row prefetch, C to smem (stride SCS).
template<int TN>
__device__ __forceinline__ void gemm32(const float* __restrict__ A,
                                       const float* __restrict__ Bg,
                                       float* __restrict__ C,
                                       int tbase, int tr, int dc)
{
    u64 acc[TN][4];
#pragma unroll
    for (int i = 0; i < TN; i++)
#pragma unroll
        for (int j = 0; j < 4; j++) acc[i][j] = 0ull;
    const float* Ar[TN];
#pragma unroll
    for (int i = 0; i < TN; i++) Ar[i] = A + (tbase + tr + 8 * i) * QS;

    const float* bp = Bg + dc * 8;
    ulonglong2 cE0 = __ldg((const ulonglong2*)bp);          // row 0
    ulonglong2 cE1 = __ldg((const ulonglong2*)(bp + 4));
    ulonglong2 cO0 = __ldg((const ulonglong2*)(bp + 32));   // row 1
    ulonglong2 cO1 = __ldg((const ulonglong2*)(bp + 36));
#pragma unroll 1
    for (int l4 = 0; l4 < 32; l4++) {
        float4 a4[TN];
#pragma unroll
        for (int i = 0; i < TN; i++)
            a4[i] = *(const float4*)(Ar[i] + 4 * l4);
        // stage 1: rows 4l4, 4l4+1 live; prefetch 4l4+2, 4l4+3
        {
            const int nb = 4 * l4 + 2;
            ulonglong2 nE0 = __ldg((const ulonglong2*)(bp + nb * 32));
            ulonglong2 nE1 = __ldg((const ulonglong2*)(bp + nb * 32 + 4));
            ulonglong2 nO0 = __ldg((const ulonglong2*)(bp + nb * 32 + 32));
            ulonglong2 nO1 = __ldg((const ulonglong2*)(bp + nb * 32 + 36));
#pragma unroll
            for (int i = 0; i < TN; i++) {
                u64 d0 = dup2(a4[i].x), d1 = dup2(a4[i].y);
                fma2(acc[i][0], d0, cE0.x); fma2(acc[i][1], d0, cE0.y);
                fma2(acc[i][2], d0, cE1.x); fma2(acc[i][3], d0, cE1.y);
                fma2(acc[i][0], d1, cO0.x); fma2(acc[i][1], d1, cO0.y);
                fma2(acc[i][2], d1, cO1.x); fma2(acc[i][3], d1, cO1.y);
            }
            cE0 = nE0; cE1 = nE1; cO0 = nO0; cO1 = nO1;
        }
        // stage 2: rows 4l4+2, 4l4+3 live; prefetch next group
        {
            const int nb = (l4 < 31) ? 4 * l4 + 4 : 124;   // dummy at end
            ulonglong2 nE0 = __ldg((const ulonglong2*)(bp + nb * 32));
            ulonglong2 nE1 = __ldg((const ulonglong2*)(bp + nb * 32 + 4));
            ulonglong2 nO0 = __ldg((const ulonglong2*)(bp + nb * 32 + 32));
            ulonglong2 nO1 = __ldg((const ulonglong2*)(bp + nb * 32 + 36));
#pragma unroll
            for (int i = 0; i < TN; i++) {
                u64 d0 = dup2(a4[i].z), d1 = dup2(a4[i].w);
                fma2(acc[i][0], d0, cE0.x); fma2(acc[i][1], d0, cE0.y);
                fma2(acc[i][2], d0, cE1.x); fma2(acc[i][3], d0, cE1.y);
                fma2(acc[i][0], d1, cO0.x); fma2(acc[i][1], d1, cO0.y);
                fma2(acc[i][2], d1, cO1.x); fma2(acc[i][3], d1, cO1.y);
            }
            cE0 = nE0; cE1 = nE1; cO0 = nO0; cO1 = nO1;
        }
    }
#pragma unroll
    for (int i = 0; i < TN; i++)
#pragma unroll
        for (int j = 0; j < 4; j++)
            *reinterpret_cast<u64*>(C + (tbase + tr + 8 * i) * SCS + dc * 8 + 2 * j) = acc[i][j];
}

__global__ void __launch_bounds__(NT, 2)
ha_kernel(const float* __restrict__ gq, const float* __restrict__ gk, const float* __restrict__ gv,
          const float* __restrict__ cq_w, const float* __restrict__ cq_b,
          const float* __restrict__ ck_w, const float* __restrict__ ck_b,
          const float* __restrict__ cv_w, const float* __restrict__ cv_b,
          const float* __restrict__ w_qs, const float* __restrict__ w_ks, const float* __restrict__ w_vs,
          const float* __restrict__ proj_w, const float* __restrict__ proj_b,
          const float* __restrict__ fc_w, const float* __restrict__ fc_b,
          const float* __restrict__ ln_a, const float* __restrict__ ln_b,
          float* __restrict__ out)
{
    extern __shared__ float s[];
    const int tid  = threadIdx.x;
    const int w    = tid >> 5;       // 0..7
    const int lane = tid & 31;
    const size_t boff = (size_t)blockIdx.x * 8192;   // 64*128
    float* gatt = g_att + (size_t)blockIdx.x * 32 * 512;

    // ====== Phase 1: conv1d q/k/v (64->32), co-pair f32x2, pipelined wide weight loads ======
    {
        const int pr = tid >> 4;          // co-pair 0..15 (co = 2pr, 2pr+1)
        const int g  = tid & 15;
        const int l0 = g * 8;
        const int cb = g * 2;
#pragma unroll 1
        for (int m = 0; m < 3; m++) {
            const float* xin = (m == 0 ? gq : m == 1 ? gk : gv) + boff;
            const float* cb_ = (m == 0 ? cq_b : m == 1 ? ck_b : cv_b);
            float* dst = s + OFF_QKV + m * 4224;
            __syncthreads();
            for (int i = tid; i < 64 * 12; i += NT) {
                int ci = i / 12, j = i % 12;
                int f = (j < 6) ? j : j + 128;
                s[OFF_IN + ci * WR + SWZ(f)] = 0.f;
            }
            // vectorized fill: float4 LDG + 2x 8B STS (f = 6 + i%128, f ≡ 2 mod 4)
            for (int i = tid * 4; i < 8192; i += NT * 4) {
                float4 v = *(const float4*)(xin + i);
                int row = i >> 7;
                int f = 6 + (i & 127);
                int c0 = f >> 2;                 // floats f,f+1 at chunk c0 pos 2,3
                float* base = s + OFF_IN + row * WR;
                *reinterpret_cast<u64*>(base + ((c0 + (c0 >> 3)) << 2) + 2) = pk2(v.x, v.y);
                int c1 = c0 + 1;                 // floats f+2,f+3 at chunk c1 pos 0,1
                *reinterpret_cast<u64*>(base + ((c1 + (c1 >> 3)) << 2)) = pk2(v.z, v.w);
            }
            __syncthreads();

            u64 acc2[8];
            {
                u64 bp2 = pk2(__ldg(&cb_[2 * pr]), __ldg(&cb_[2 * pr + 1]));
#pragma unroll
                for (int i = 0; i < 8; i++) acc2[i] = bp2;
            }
            const float* wbase = g_cwI + m * 28672 + pr * 1792;
            u64 wp[13];
            ldw13(wp, wbase);                                  // ci = 0
#pragma unroll 2
            for (int ci = 0; ci < 64; ci++) {
                // prefetch weights for ci+1
                u64 wn[13];
                {
                    const int cn = (ci < 63) ? ci + 1 : 63;
                    ldw13(wn, wbase + cn * 28);
                }
                const float* xp = s + OFF_IN + ci * WR;
                float xw[20];
#pragma unroll
                for (int q4 = 0; q4 < 5; q4++) {
                    int cc = cb + q4;
                    float4 t4 = *(const float4*)(xp + ((cc + (cc >> 3)) << 2));
                    xw[q4 * 4 + 0] = t4.x; xw[q4 * 4 + 1] = t4.y;
                    xw[q4 * 4 + 2] = t4.z; xw[q4 * 4 + 3] = t4.w;
                }
                // 8-slot dup ring: dx[(kk+i)&7] == dup2(xw[kk+i])
                u64 dx[8];
#pragma unroll
                for (int j = 0; j < 8; j++) dx[j] = dup2(xw[j]);
#pragma unroll
                for (int kk = 0; kk < 13; kk++) {
#pragma unroll
                    for (int i = 0; i < 8; i++)
                        fma2(acc2[i], dx[(kk + i) & 7], wp[kk]);
                    if (kk + 8 < 20)
                        dx[kk & 7] = dup2(xw[kk + 8]);
                }
#pragma unroll
                for (int kk = 0; kk < 13; kk++) wp[kk] = wn[kk];
            }
            float o0[8], o1[8];
#pragma unroll
            for (int i = 0; i < 8; i++) upk2(o0[i], o1[i], acc2[i]);
            *(float4*)(dst + (2 * pr) * QS + l0)         = make_float4(o0[0], o0[1], o0[2], o0[3]);
            *(float4*)(dst + (2 * pr) * QS + l0 + 4)     = make_float4(o0[4], o0[5], o0[6], o0[7]);
            *(float4*)(dst + (2 * pr + 1) * QS + l0)     = make_float4(o1[0], o1[1], o1[2], o1[3]);
            *(float4*)(dst + (2 * pr + 1) * QS + l0 + 4) = make_float4(o1[4], o1[5], o1[6], o1[7]);
        }
    }

    // ============ Phase 2: per-head projections + attention, 4 passes of 4 heads ============
    {
        const int dc = lane & 3, tr = lane >> 2;
        const float inv_t = 0.08838834764831845f;   // 1/sqrt(128)
#pragma unroll 1
        for (int p = 0; p < 4; p++) {
            __syncthreads();
            {
                const int g = w, hl = g / 3, mm = g % 3;
                const float* Bsrc = (mm == 0 ? w_qs : mm == 1 ? w_ks : w_vs) + (p * 4 + hl) * 4096;
                gemm32<4>(s + OFF_QKV + mm * 4224, Bsrc,
                          s + OFF_SCR + hl * 3264 + mm * 1088, 0, tr, dc);
            }
            {
                const int g = 8 + (w >> 1), hl = g / 3, mm = g % 3;
                const float* Bsrc = (mm == 0 ? w_qs : mm == 1 ? w_ks : w_vs) + (p * 4 + hl) * 4096;
                gemm32<2>(s + OFF_QKV + mm * 4224, Bsrc,
                          s + OFF_SCR + hl * 3264 + mm * 1088, (w & 1) * 16, tr, dc);
            }
            __syncthreads();
            {
                const int hl = w >> 1, qbase = (w & 1) * 16;
                float* qh = s + OFF_SCR + hl * 3264;
                float* kh = qh + 1088;
                float* vh = qh + 2176;
                const float* qr0 = qh + (qbase + tr) * SCS;
                const float* qr1 = qh + (qbase + tr + 8) * SCS;
                u64 sc2[2][8];
#pragma unroll
                for (int i = 0; i < 2; i++)
#pragma unroll
                    for (int j = 0; j < 8; j++) sc2[i][j] = 0ull;
#pragma unroll 4
                for (int d2 = 0; d2 < 16; d2++) {
                    u64 q0 = lds64(qr0 + 2 * d2);
                    u64 q1 = lds64(qr1 + 2 * d2);
#pragma unroll
                    for (int j = 0; j < 8; j++) {
                        u64 kv = lds64(kh + (dc * 8 + j) * SCS + 2 * d2);
                        fma2(sc2[0][j], q0, kv);
                        fma2(sc2[1][j], q1, kv);
                    }
                }
                float sc[2][8];
#pragma unroll
                for (int i = 0; i < 2; i++)
#pragma unroll
                    for (int j = 0; j < 8; j++) {
                        float lo, hi; upk2(lo, hi, sc2[i][j]); sc[i][j] = lo + hi;
                    }
#pragma unroll
                for (int i = 0; i < 2; i++) {
                    float mx = -1e30f;
#pragma unroll
                    for (int j = 0; j < 8; j++) { sc[i][j] *= inv_t; mx = fmaxf(mx, sc[i][j]); }
                    mx = fmaxf(mx, __shfl_xor_sync(0xffffffffu, mx, 1));
                    mx = fmaxf(mx, __shfl_xor_sync(0xffffffffu, mx, 2));
                    float sum = 0.f;
#pragma unroll
                    for (int j = 0; j < 8; j++) { sc[i][j] = __expf(sc[i][j] - mx); sum += sc[i][j]; }
                    sum += __shfl_xor_sync(0xffffffffu, sum, 1);
                    sum += __shfl_xor_sync(0xffffffffu, sum, 2);
                    float inv = 1.f / sum;
#pragma unroll
                    for (int j = 0; j < 8; j++) sc[i][j] *= inv;
                }
#pragma unroll
                for (int i = 0; i < 2; i++)
#pragma unroll
                    for (int j = 0; j < 8; j++)
                        qh[(qbase + tr + 8 * i) * SCS + dc * 8 + j] = sc[i][j];
                __syncwarp();
                u64 av2[2][4];
#pragma unroll
                for (int i = 0; i < 2; i++)
#pragma unroll
                    for (int jp = 0; jp < 4; jp++) av2[i][jp] = 0ull;
#pragma unroll 4
                for (int k2 = 0; k2 < 32; k2++) {
                    u64 a0 = dup2(qr0[k2]);
                    u64 a1 = dup2(qr1[k2]);
#pragma unroll
                    for (int jp = 0; jp < 4; jp++) {
                        u64 vv = lds64(vh + k2 * SCS + dc * 8 + 2 * jp);
                        fma2(av2[0][jp], a0, vv);
                        fma2(av2[1][jp], a1, vv);
                    }
                }
                const int h = p * 4 + hl;
#pragma unroll
                for (int i = 0; i < 2; i++) {
                    float* gp = gatt + (qbase + tr + 8 * i) * 512 + h * 32 + dc * 8;
                    *reinterpret_cast<ulonglong2*>(gp)     = make_ulonglong2(av2[i][0], av2[i][1]);
                    *reinterpret_cast<ulonglong2*>(gp + 4) = make_ulonglong2(av2[i][2], av2[i][3]);
                }
            }
        }
    }

    // ============ Phase 3: stage ATT from gmem (float4), proj with transposed weights ============
    __syncthreads();
    for (int i = tid * 4; i < 16384; i += NT * 4) {
        float4 v4 = *(const float4*)(gatt + i);
        *(float4*)(s + OFF_ATT + (i >> 9) * 516 + (i & 511)) = v4;
    }
    for (int i = tid; i < 32 * 12; i += NT) {
        int t = i / 12, j = i % 12;
        int f = (j < 6) ? j : j + 128;
        s[OFF_Y + t * WR + SWZ(f)] = 0.f;
    }
    __syncthreads();
    {
        const int tq = lane >> 4, ml = lane & 15;
        const int m0 = (w >> 2) * 64 + ml * 4;      // 4 m's per thread
        const int tb = (w & 3) * 8 + tq * 4;        // 4 t-rows per thread
        u64 acc[4][2];
#pragma unroll
        for (int t = 0; t < 4; t++) { acc[t][0] = 0ull; acc[t][1] = 0ull; }
        const float* bp0 = g_pwT + m0;
        ulonglong2 c0 = __ldg((const ulonglong2*)bp0);           // row 0
        ulonglong2 c1 = __ldg((const ulonglong2*)(bp0 + 128));   // row 1
#pragma unroll 1
        for (int j4 = 0; j4 < 128; j4++) {          // 4 j per iter, full 512 reduction
            float4 a4[4];
#pragma unroll
            for (int t = 0; t < 4; t++)
                a4[t] = *(const float4*)(s + OFF_ATT + (tb + t) * 516 + 4 * j4);
            // stage 1: rows 4j4, 4j4+1; prefetch +2,+3
            {
                const int nj = 4 * j4 + 2;
                ulonglong2 n0 = __ldg((const ulonglong2*)(bp0 + nj * 128));
                ulonglong2 n1 = __ldg((const ulonglong2*)(bp0 + (nj + 1) * 128));
#pragma unroll
                for (int t = 0; t < 4; t++) {
                    u64 d0 = dup2(a4[t].x), d1 = dup2(a4[t].y);
                    fma2(acc[t][0], d0, c0.x); fma2(acc[t][1], d0, c0.y);
                    fma2(acc[t][0], d1, c1.x); fma2(acc[t][1], d1, c1.y);
                }
                c0 = n0; c1 = n1;
            }
            // stage 2: rows 4j4+2, +3; prefetch next
            {
                const int nj = (j4 < 127) ? 4 * j4 + 4 : 508;
                ulonglong2 n0 = __ldg((const ulonglong2*)(bp0 + nj * 128));
                ulonglong2 n1 = __ldg((const ulonglong2*)(bp0 + (nj + 1) * 128));
#pragma unroll
                for (int t = 0; t < 4; t++) {
                    u64 d0 = dup2(a4[t].z), d1 = dup2(a4[t].w);
                    fma2(acc[t][0], d0, c0.x); fma2(acc[t][1], d0, c0.y);
                    fma2(acc[t][0], d1, c1.x); fma2(acc[t][1], d1, c1.y);
                }
                c0 = n0; c1 = n1;
            }
        }
        float4 bb = __ldg((const float4*)(proj_b + m0));
#pragma unroll
        for (int t = 0; t < 4; t++) {
            float y0, y1, y2, y3;
            upk2(y0, y1, acc[t][0]);
            upk2(y2, y3, acc[t][1]);
            float* yrow = s + OFF_Y + (tb + t) * WR;
            const int f0 = 6 + m0, c0i = f0 >> 2;           // floats 2,3 of chunk
            const int f1 = 8 + m0, c1i = f1 >> 2;           // floats 0,1 of chunk
            *reinterpret_cast<u64*>(yrow + ((c0i + (c0i >> 3)) << 2) + 2) = pk2(y0 + bb.x, y1 + bb.y);
            *reinterpret_cast<u64*>(yrow + ((c1i + (c1i >> 3)) << 2))     = pk2(y2 + bb.z, y3 + bb.w);
        }
    }
    __syncthreads();

    // ====== Phase 4: final conv (32->64) + residual, two co-pair passes, wide pipelined weights ======
    {
        const int qd = tid >> 4;          // 0..15
        const int g  = tid & 15;
        const int l0 = g * 8;
        const int cb = g * 2;
        const float* qres = gq + boff;
#pragma unroll 1
        for (int pass = 0; pass < 2; pass++) {
            const int pr = 2 * qd + pass;             // pair 0..31, co = 2pr, 2pr+1
            u64 acc2[8];
            {
                u64 bp2 = pk2(__ldg(&fc_b[2 * pr]), __ldg(&fc_b[2 * pr + 1]));
#pragma unroll
                for (int i = 0; i < 8; i++) acc2[i] = bp2;
            }
            const float* wbase = g_fcI + pr * 896;
            u64 wp[13];
            ldw13(wp, wbase);
#pragma unroll 2
            for (int ci = 0; ci < 32; ci++) {
                u64 wn[13];
                {
                    const int cn = (ci < 31) ? ci + 1 : 31;
                    ldw13(wn, wbase + cn * 28);
                }
                const float* xp = s + OFF_Y + ci * WR;
                float xw[20];
#pragma unroll
                for (int q4 = 0; q4 < 5; q4++) {
                    int cc = cb + q4;
                    float4 t4 = *(const float4*)(xp + ((cc + (cc >> 3)) << 2));
                    xw[q4 * 4 + 0] = t4.x; xw[q4 * 4 + 1] = t4.y;
                    xw[q4 * 4 + 2] = t4.z; xw[q4 * 4 + 3] = t4.w;
                }
                u64 dx[8];
#pragma unroll
                for (int j = 0; j < 8; j++) dx[j] = dup2(xw[j]);
#pragma unroll
                for (int kk = 0; kk < 13; kk++) {
#pragma unroll
                    for (int i = 0; i < 8; i++)
                        fma2(acc2[i], dx[(kk + i) & 7], wp[kk]);
                    if (kk + 8 < 20)
                        dx[kk & 7] = dup2(xw[kk + 8]);
                }
#pragma unroll
                for (int kk = 0; kk < 13; kk++) wp[kk] = wn[kk];
            }
            float o0[8], o1[8];
#pragma unroll
            for (int i = 0; i < 8; i++) upk2(o0[i], o1[i], acc2[i]);
#pragma unroll
            for (int c2 = 0; c2 < 2; c2++) {
                const int co = 2 * pr + c2;
                const float* oc = (c2 == 0) ? o0 : o1;
                float4 r0 = __ldg((const float4*)(qres + co * 128 + l0));
                float4 r1 = __ldg((const float4*)(qres + co * 128 + l0 + 4));
                *(float4*)(s + OFF_Z + co * 128 + l0) =
                    make_float4(oc[0] + r0.x, oc[1] + r0.y, oc[2] + r0.z, oc[3] + r0.w);
                *(float4*)(s + OFF_Z + co * 128 + l0 + 4) =
                    make_float4(oc[4] + r1.x, oc[5] + r1.y, oc[6] + r1.z, oc[7] + r1.w);
            }
        }
    }
    __syncthreads();

    // ============ Phase 5: LayerNorm (unbiased std, /(sigma+eps)) ============
    {
#pragma unroll
        for (int it = 0; it < 8; it++) {
            int r = w + it * 8;
            const float* zr = s + OFF_Z + r * 128;
            float v0 = zr[lane], v1 = zr[lane + 32], v2 = zr[lane + 64], v3 = zr[lane + 96];
            float sm = v0 + v1 + v2 + v3;
#pragma unroll
            for (int o = 16; o > 0; o >>= 1) sm += __shfl_xor_sync(0xffffffffu, sm, o);
            float mu = sm * (1.f / 128.f);
            float d0 = v0 - mu, d1 = v1 - mu, d2 = v2 - mu, d3 = v3 - mu;
            float s2 = d0 * d0 + d1 * d1 + d2 * d2 + d3 * d3;
#pragma unroll
            for (int o = 16; o > 0; o >>= 1) s2 += __shfl_xor_sync(0xffffffffu, s2, o);
            float sigma = sqrtf(s2 * (1.f / 127.f));
            float inv = 1.f / (sigma + 1e-3f);
            float* orow = out + boff + r * 128;
            orow[lane]      = d0 * inv * __ldg(&ln_a[lane])      + __ldg(&ln_b[lane]);
            orow[lane + 32] = d1 * inv * __ldg(&ln_a[lane + 32]) + __ldg(&ln_b[lane + 32]);
            orow[lane + 64] = d2 * inv * __ldg(&ln_a[lane + 64]) + __ldg(&ln_b[lane + 64]);
            orow[lane + 96] = d3 * inv * __ldg(&ln_a[lane + 96]) + __ldg(&ln_b[lane + 96]);
        }
    }
}

extern "C" void kernel_launch(void* const* d_in, const int* in_sizes, int n_in,
                              void* d_out, int out_size)
{
    const float* q      = (const float*)d_in[0];
    const float* k      = (const float*)d_in[1];
    const float* v      = (const float*)d_in[2];
    const float* cq_w   = (const float*)d_in[3];
    const float* cq_b   = (const float*)d_in[4];
    const float* ck_w   = (const float*)d_in[5];
    const float* ck_b   = (const float*)d_in[6];
    const float* cv_w   = (const float*)d_in[7];
    const float* cv_b   = (const float*)d_in[8];
    const float* w_qs   = (const float*)d_in[9];
    const float* w_ks   = (const float*)d_in[10];
    const float* w_vs   = (const float*)d_in[11];
    const float* proj_w = (const float*)d_in[12];
    const float* proj_b = (const float*)d_in[13];
    const float* fc_w   = (const float*)d_in[14];
    const float* fc_b   = (const float*)d_in[15];
    const float* ln_a   = (const float*)d_in[16];
    const float* ln_b   = (const float*)d_in[17];
    float* outp = (float*)d_out;

    const int B = in_sizes[0] / (64 * 128);

    transpose_pw_kernel<<<128, 512>>>(proj_w);
    interleave_cw_kernel<<<312, 256>>>(cq_w, ck_w, cv_w);
    interleave_fc_kernel<<<104, 256>>>(fc_w);

    cudaFuncSetAttribute(ha_kernel, cudaFuncAttributeMaxDynamicSharedMemorySize, SMEM_BYTES);
    cudaFuncSetAttribute(ha_kernel, cudaFuncAttributePreferredSharedMemoryCarveout, 100);
    ha_kernel<<<B, NT, SMEM_BYTES>>>(q, k, v, cq_w, cq_b, ck_w, ck_b, cv_w, cv_b,
                                     w_qs, w_ks, w_vs, proj_w, proj_b, fc_w, fc_b,
                                     ln_a, ln_b, outp);
}

// round 16
// speedup vs baseline: 1.5921x; 1.0179x over previous
#include <cuda_runtime.h>

// B=2048, DKV=64, L=128, H=16, DT=32, KW=13, PAD=6
#define NT 256
#define QS 132     // qb/kb/vb row stride
#define SCS 34     // qh/kh/vh scratch row stride
#define WR 160     // swizzled conv-window row stride (40 chunks of 16B)

// chunk skew c -> c + (c>>3) kills 64B-stride bank conflicts
#define SWZ(f) ((((((f) >> 2) + ((f) >> 5))) << 2) | ((f) & 3))

// shared layout (floats), peak 25728 (=102,912B) -> 2 CTAs/SM
#define OFF_QKV 0            // 3*32*132 = 12672            [P1 out, P2 A]
#define OFF_IN  12672        // 64*160 = 10240 -> 22912      [P1, swizzled rows]
#define OFF_SCR 12672        // 4 heads*3*32*34 = 13056 -> 25728 [P2]
#define OFF_Y   0            // 32*160 = 5120                [P3 -> P4, swizzled rows]
#define OFF_ATT 5120         // 32*516 = 16512 -> 21632      [P3]
#define OFF_Z   12288        // 8192 -> 20480 (over dead ATT) [P4 -> P5]
#define SMEM_FLOATS 25728
#define SMEM_BYTES (SMEM_FLOATS * 4)

typedef unsigned long long u64;

// gmem scratch (__device__ globals, no allocation)
__device__ float g_att[2048 * 32 * 512];   // per-batch attention concat
__device__ float g_pwT[512 * 128];         // proj_w transposed: pwT[j][m]
__device__ float g_cwI4[3 * 28672];        // conv w quad-interleaved [m][qd8][ci64][56: pairA28|pairB28]
__device__ float g_fcI4[28672];            // fc w quad-interleaved  [qd16][ci32][56]

__device__ __forceinline__ u64 pk2(float lo, float hi) {
    u64 r; asm("mov.b64 %0,{%1,%2};" : "=l"(r) : "f"(lo), "f"(hi)); return r;
}
__device__ __forceinline__ u64 dup2(float x) { return pk2(x, x); }
__device__ __forceinline__ void upk2(float& lo, float& hi, u64 v) {
    asm("mov.b64 {%0,%1},%2;" : "=f"(lo), "=f"(hi) : "l"(v));
}
__device__ __forceinline__ void fma2(u64& d, u64 a, u64 b) {
    asm("fma.rn.f32x2 %0,%1,%2,%0;" : "+l"(d) : "l"(a), "l"(b));
}
__device__ __forceinline__ u64 lds64(const float* p) {
    return *reinterpret_cast<const u64*>(p);
}
// load 13 contiguous u64 weights via 6x LDG.128 + 1x LDG.64 (wr 16B-aligned)
__device__ __forceinline__ void ldw13(u64* wp, const float* wr) {
#pragma unroll
    for (int q = 0; q < 6; q++) {
        ulonglong2 t = __ldg((const ulonglong2*)(wr + 4 * q));
        wp[2 * q] = t.x; wp[2 * q + 1] = t.y;
    }
    wp[12] = __ldg((const u64*)(wr + 24));
}

__global__ void transpose_pw_kernel(const float* __restrict__ pw) {
    int idx = blockIdx.x * 512 + threadIdx.x;   // 65536 total
    int j = idx >> 7, m = idx & 127;
    g_pwT[idx] = pw[m * 512 + j];
}

__global__ void interleave_cw4_kernel(const float* __restrict__ cq,
                                      const float* __restrict__ ck,
                                      const float* __restrict__ cv) {
    int idx = blockIdx.x * 256 + threadIdx.x;   // 3*26624 = 79872
    if (idx >= 3 * 26624) return;
    int m = idx / 26624, i = idx % 26624;
    const float* src = (m == 0) ? cq : (m == 1) ? ck : cv;
    int co = i / 832, r = i % 832, ci = r / 13, kk = r % 13;
    g_cwI4[m * 28672 + (co >> 2) * 3584 + ci * 56 + ((co >> 1) & 1) * 28 + kk * 2 + (co & 1)] = src[i];
}

__global__ void interleave_fc4_kernel(const float* __restrict__ fcw) {
    int idx = blockIdx.x * 256 + threadIdx.x;   // 26624
    if (idx >= 26624) return;
    int co = idx / 416, r = idx % 416, ci = r / 13, kk = r % 13;
    g_fcI4[(co >> 2) * 1792 + ci * 56 + ((co >> 1) & 1) * 28 + kk * 2 + (co & 1)] = fcw[idx];
}

// One warp: C(32x32) = A(32x128) @ B(128x32); A smem via lds128 (4 l per load),
// B streamed from gmem with 2-row prefetch, C to smem (stride SCS).
template<int TN>
__device__ __forceinline__ void gemm32(const float* __restrict__ A,
                                       const float* __restrict__ Bg,
                                       float* __restrict__ C,
                                       int tbase, int tr, int dc)
{
    u64 acc[TN][4];
#pragma unroll
    for (int i = 0; i < TN; i++)
#pragma unroll
        for (int j = 0; j < 4; j++) acc[i][j] = 0ull;
    const float* Ar[TN];
#pragma unroll
    for (int i = 0; i < TN; i++) Ar[i] = A + (tbase + tr + 8 * i) * QS;

    const float* bp = Bg + dc * 8;
    ulonglong2 cE0 = __ldg((const ulonglong2*)bp);          // row 0
    ulonglong2 cE1 = __ldg((const ulonglong2*)(bp + 4));
    ulonglong2 cO0 = __ldg((const ulonglong2*)(bp + 32));   // row 1
    ulonglong2 cO1 = __ldg((const ulonglong2*)(bp + 36));
#pragma unroll 1
    for (int l4 = 0; l4 < 32; l4++) {
        float4 a4[TN];
#pragma unroll
        for (int i = 0; i < TN; i++)
            a4[i] = *(const float4*)(Ar[i] + 4 * l4);
        {
            const int nb = 4 * l4 + 2;
            ulonglong2 nE0 = __ldg((const ulonglong2*)(bp + nb * 32));
            ulonglong2 nE1 = __ldg((const ulonglong2*)(bp + nb * 32 + 4));
            ulonglong2 nO0 = __ldg((const ulonglong2*)(bp + nb * 32 + 32));
            ulonglong2 nO1 = __ldg((const ulonglong2*)(bp + nb * 32 + 36));
#pragma unroll
            for (int i = 0; i < TN; i++) {
                u64 d0 = dup2(a4[i].x), d1 = dup2(a4[i].y);
                fma2(acc[i][0], d0, cE0.x); fma2(acc[i][1], d0, cE0.y);
                fma2(acc[i][2], d0, cE1.x); fma2(acc[i][3], d0, cE1.y);
                fma2(acc[i][0], d1, cO0.x); fma2(acc[i][1], d1, cO0.y);
                fma2(acc[i][2], d1, cO1.x); fma2(acc[i][3], d1, cO1.y);
            }
            cE0 = nE0; cE1 = nE1; cO0 = nO0; cO1 = nO1;
        }
        {
            const int nb = (l4 < 31) ? 4 * l4 + 4 : 124;
            ulonglong2 nE0 = __ldg((const ulonglong2*)(bp + nb * 32));
            ulonglong2 nE1 = __ldg((const ulonglong2*)(bp + nb * 32 + 4));
            ulonglong2 nO0 = __ldg((const ulonglong2*)(bp + nb * 32 + 32));
            ulonglong2 nO1 = __ldg((const ulonglong2*)(bp + nb * 32 + 36));
#pragma unroll
            for (int i = 0; i < TN; i++) {
                u64 d0 = dup2(a4[i].z), d1 = dup2(a4[i].w);
                fma2(acc[i][0], d0, cE0.x); fma2(acc[i][1], d0, cE0.y);
                fma2(acc[i][2], d0, cE1.x); fma2(acc[i][3], d0, cE1.y);
                fma2(acc[i][0], d1, cO0.x); fma2(acc[i][1], d1, cO0.y);
                fma2(acc[i][2], d1, cO1.x); fma2(acc[i][3], d1, cO1.y);
            }
            cE0 = nE0; cE1 = nE1; cO0 = nO0; cO1 = nO1;
        }
    }
#pragma unroll
    for (int i = 0; i < TN; i++)
#pragma unroll
        for (int j = 0; j < 4; j++)
            *reinterpret_cast<u64*>(C + (tbase + tr + 8 * i) * SCS + dc * 8 + 2 * j) = acc[i][j];
}

// quad conv inner: window xw[20] (positions l0-6..l0+13), weights wr (pairA|pairB),
// accumulates acc2[2][8]
__device__ __forceinline__ void conv_quad_ci(u64 acc2[2][8], const float* xp,
                                             const float* wr, int cb)
{
    u64 wpA[13];
    ldw13(wpA, wr);
    float xw[20];
#pragma unroll
    for (int q4 = 0; q4 < 5; q4++) {
        int cc = cb + q4;
        float4 t4 = *(const float4*)(xp + ((cc + (cc >> 3)) << 2));
        xw[q4 * 4 + 0] = t4.x; xw[q4 * 4 + 1] = t4.y;
        xw[q4 * 4 + 2] = t4.z; xw[q4 * 4 + 3] = t4.w;
    }
    {
        u64 dx[8];
#pragma unroll
        for (int j = 0; j < 8; j++) dx[j] = dup2(xw[j]);
#pragma unroll
        for (int kk = 0; kk < 13; kk++) {
#pragma unroll
            for (int i = 0; i < 8; i++)
                fma2(acc2[0][i], dx[(kk + i) & 7], wpA[kk]);
            if (kk + 8 < 20)
                dx[kk & 7] = dup2(xw[kk + 8]);
        }
    }
    u64 wpB[13];
    ldw13(wpB, wr + 28);
    {
        u64 dx[8];
#pragma unroll
        for (int j = 0; j < 8; j++) dx[j] = dup2(xw[j]);
#pragma unroll
        for (int kk = 0; kk < 13; kk++) {
#pragma unroll
            for (int i = 0; i < 8; i++)
                fma2(acc2[1][i], dx[(kk + i) & 7], wpB[kk]);
            if (kk + 8 < 20)
                dx[kk & 7] = dup2(xw[kk + 8]);
        }
    }
}

__global__ void __launch_bounds__(NT, 2)
ha_kernel(const float* __restrict__ gq, const float* __restrict__ gk, const float* __restrict__ gv,
          const float* __restrict__ cq_w, const float* __restrict__ cq_b,
          const float* __restrict__ ck_w, const float* __restrict__ ck_b,
          const float* __restrict__ cv_w, const float* __restrict__ cv_b,
          const float* __restrict__ w_qs, const float* __restrict__ w_ks, const float* __restrict__ w_vs,
          const float* __restrict__ proj_w, const float* __restrict__ proj_b,
          const float* __restrict__ fc_w, const float* __restrict__ fc_b,
          const float* __restrict__ ln_a, const float* __restrict__ ln_b,
          float* __restrict__ out)
{
    extern __shared__ float s[];
    const int tid  = threadIdx.x;
    const int w    = tid >> 5;       // 0..7
    const int lane = tid & 31;
    const size_t boff = (size_t)blockIdx.x * 8192;   // 64*128
    float* gatt = g_att + (size_t)blockIdx.x * 32 * 512;

    // ====== Phase 1: conv1d q/k/v (64->32), co-QUAD per thread, ci-split, shared window ======
    {
        const int h  = w >> 2;                        // ci half: 0 or 1
        const int qd = (w & 3) * 2 + (lane >> 4);     // quad 0..7 (co 4qd..4qd+3)
        const int g  = lane & 15;
        const int l0 = g * 8;
        const int cb = g * 2;
#pragma unroll 1
        for (int m = 0; m < 3; m++) {
            const float* xin = (m == 0 ? gq : m == 1 ? gk : gv) + boff;
            const float* cb_ = (m == 0 ? cq_b : m == 1 ? ck_b : cv_b);
            float* dst = s + OFF_QKV + m * 4224;
            __syncthreads();
            for (int i = tid; i < 64 * 12; i += NT) {
                int ci = i / 12, j = i % 12;
                int f = (j < 6) ? j : j + 128;
                s[OFF_IN + ci * WR + SWZ(f)] = 0.f;
            }
            for (int i = tid * 4; i < 8192; i += NT * 4) {
                float4 v = *(const float4*)(xin + i);
                int row = i >> 7;
                int f = 6 + (i & 127);
                int c0 = f >> 2;
                float* base = s + OFF_IN + row * WR;
                *reinterpret_cast<u64*>(base + ((c0 + (c0 >> 3)) << 2) + 2) = pk2(v.x, v.y);
                int c1 = c0 + 1;
                *reinterpret_cast<u64*>(base + ((c1 + (c1 >> 3)) << 2)) = pk2(v.z, v.w);
            }
            __syncthreads();

            u64 acc2[2][8];
#pragma unroll
            for (int p = 0; p < 2; p++)
#pragma unroll
                for (int i = 0; i < 8; i++) acc2[p][i] = 0ull;
            const float* wqbase = g_cwI4 + m * 28672 + qd * 3584 + h * 32 * 56;
#pragma unroll 1
            for (int ci = 0; ci < 32; ci++)
                conv_quad_ci(acc2, s + OFF_IN + (32 * h + ci) * WR, wqbase + ci * 56, cb);

            float o[4][8];
#pragma unroll
            for (int p = 0; p < 2; p++)
#pragma unroll
                for (int i = 0; i < 8; i++)
                    upk2(o[2 * p][i], o[2 * p + 1][i], acc2[p][i]);
            if (h == 1) {
#pragma unroll
                for (int c = 0; c < 4; c++) {
                    *(float4*)(dst + (4 * qd + c) * QS + l0) =
                        make_float4(o[c][0], o[c][1], o[c][2], o[c][3]);
                    *(float4*)(dst + (4 * qd + c) * QS + l0 + 4) =
                        make_float4(o[c][4], o[c][5], o[c][6], o[c][7]);
                }
            }
            __syncthreads();
            if (h == 0) {
#pragma unroll
                for (int c = 0; c < 4; c++) {
                    float bv = __ldg(&cb_[4 * qd + c]);
                    float4 p0 = *(const float4*)(dst + (4 * qd + c) * QS + l0);
                    float4 p1 = *(const float4*)(dst + (4 * qd + c) * QS + l0 + 4);
                    *(float4*)(dst + (4 * qd + c) * QS + l0) =
                        make_float4(o[c][0] + p0.x + bv, o[c][1] + p0.y + bv,
                                    o[c][2] + p0.z + bv, o[c][3] + p0.w + bv);
                    *(float4*)(dst + (4 * qd + c) * QS + l0 + 4) =
                        make_float4(o[c][4] + p1.x + bv, o[c][5] + p1.y + bv,
                                    o[c][6] + p1.z + bv, o[c][7] + p1.w + bv);
                }
            }
        }
    }

    // ============ Phase 2: per-head projections + attention, 4 passes of 4 heads ============
    {
        const int dc = lane & 3, tr = lane >> 2;
        const float inv_t = 0.08838834764831845f;   // 1/sqrt(128)
#pragma unroll 1
        for (int p = 0; p < 4; p++) {
            __syncthreads();
            {
                const int g = w, hl = g / 3, mm = g % 3;
                const float* Bsrc = (mm == 0 ? w_qs : mm == 1 ? w_ks : w_vs) + (p * 4 + hl) * 4096;
                gemm32<4>(s + OFF_QKV + mm * 4224, Bsrc,
                          s + OFF_SCR + hl * 3264 + mm * 1088, 0, tr, dc);
            }
            {
                const int g = 8 + (w >> 1), hl = g / 3, mm = g % 3;
                const float* Bsrc = (mm == 0 ? w_qs : mm == 1 ? w_ks : w_vs) + (p * 4 + hl) * 4096;
                gemm32<2>(s + OFF_QKV + mm * 4224, Bsrc,
                          s + OFF_SCR + hl * 3264 + mm * 1088, (w & 1) * 16, tr, dc);
            }
            __syncthreads();
            {
                const int hl = w >> 1, qbase = (w & 1) * 16;
                float* qh = s + OFF_SCR + hl * 3264;
                float* kh = qh + 1088;
                float* vh = qh + 2176;
                const float* qr0 = qh + (qbase + tr) * SCS;
                const float* qr1 = qh + (qbase + tr + 8) * SCS;
                u64 sc2[2][8];
#pragma unroll
                for (int i = 0; i < 2; i++)
#pragma unroll
                    for (int j = 0; j < 8; j++) sc2[i][j] = 0ull;
#pragma unroll 4
                for (int d2 = 0; d2 < 16; d2++) {
                    u64 q0 = lds64(qr0 + 2 * d2);
                    u64 q1 = lds64(qr1 + 2 * d2);
#pragma unroll
                    for (int j = 0; j < 8; j++) {
                        u64 kv = lds64(kh + (dc * 8 + j) * SCS + 2 * d2);
                        fma2(sc2[0][j], q0, kv);
                        fma2(sc2[1][j], q1, kv);
                    }
                }
                float sc[2][8];
#pragma unroll
                for (int i = 0; i < 2; i++)
#pragma unroll
                    for (int j = 0; j < 8; j++) {
                        float lo, hi; upk2(lo, hi, sc2[i][j]); sc[i][j] = lo + hi;
                    }
#pragma unroll
                for (int i = 0; i < 2; i++) {
                    float mx = -1e30f;
#pragma unroll
                    for (int j = 0; j < 8; j++) { sc[i][j] *= inv_t; mx = fmaxf(mx, sc[i][j]); }
                    mx = fmaxf(mx, __shfl_xor_sync(0xffffffffu, mx, 1));
                    mx = fmaxf(mx, __shfl_xor_sync(0xffffffffu, mx, 2));
                    float sum = 0.f;
#pragma unroll
                    for (int j = 0; j < 8; j++) { sc[i][j] = __expf(sc[i][j] - mx); sum += sc[i][j]; }
                    sum += __shfl_xor_sync(0xffffffffu, sum, 1);
                    sum += __shfl_xor_sync(0xffffffffu, sum, 2);
                    float inv = 1.f / sum;
#pragma unroll
                    for (int j = 0; j < 8; j++) sc[i][j] *= inv;
                }
#pragma unroll
                for (int i = 0; i < 2; i++)
#pragma unroll
                    for (int j = 0; j < 8; j++)
                        qh[(qbase + tr + 8 * i) * SCS + dc * 8 + j] = sc[i][j];
                __syncwarp();
                u64 av2[2][4];
#pragma unroll
                for (int i = 0; i < 2; i++)
#pragma unroll
                    for (int jp = 0; jp < 4; jp++) av2[i][jp] = 0ull;
#pragma unroll 4
                for (int k2 = 0; k2 < 32; k2++) {
                    u64 a0 = dup2(qr0[k2]);
                    u64 a1 = dup2(qr1[k2]);
#pragma unroll
                    for (int jp = 0; jp < 4; jp++) {
                        u64 vv = lds64(vh + k2 * SCS + dc * 8 + 2 * jp);
                        fma2(av2[0][jp], a0, vv);
                        fma2(av2[1][jp], a1, vv);
                    }
                }
                const int h2 = p * 4 + hl;
#pragma unroll
                for (int i = 0; i < 2; i++) {
                    float* gp = gatt + (qbase + tr + 8 * i) * 512 + h2 * 32 + dc * 8;
                    *reinterpret_cast<ulonglong2*>(gp)     = make_ulonglong2(av2[i][0], av2[i][1]);
                    *reinterpret_cast<ulonglong2*>(gp + 4) = make_ulonglong2(av2[i][2], av2[i][3]);
                }
            }
        }
    }

    // ============ Phase 3: stage ATT from gmem (float4), proj with transposed weights ============
    __syncthreads();
    for (int i = tid * 4; i < 16384; i += NT * 4) {
        float4 v4 = *(const float4*)(gatt + i);
        *(float4*)(s + OFF_ATT + (i >> 9) * 516 + (i & 511)) = v4;
    }
    for (int i = tid; i < 32 * 12; i += NT) {
        int t = i / 12, j = i % 12;
        int f = (j < 6) ? j : j + 128;
        s[OFF_Y + t * WR + SWZ(f)] = 0.f;
    }
    __syncthreads();
    {
        const int tq = lane >> 4, ml = lane & 15;
        const int m0 = (w >> 2) * 64 + ml * 4;      // 4 m's per thread
        const int tb = (w & 3) * 8 + tq * 4;        // 4 t-rows per thread
        u64 acc[4][2];
#pragma unroll
        for (int t = 0; t < 4; t++) { acc[t][0] = 0ull; acc[t][1] = 0ull; }
        const float* bp0 = g_pwT + m0;
        ulonglong2 c0 = __ldg((const ulonglong2*)bp0);
        ulonglong2 c1 = __ldg((const ulonglong2*)(bp0 + 128));
#pragma unroll 1
        for (int j4 = 0; j4 < 128; j4++) {
            float4 a4[4];
#pragma unroll
            for (int t = 0; t < 4; t++)
                a4[t] = *(const float4*)(s + OFF_ATT + (tb + t) * 516 + 4 * j4);
            {
                const int nj = 4 * j4 + 2;
                ulonglong2 n0 = __ldg((const ulonglong2*)(bp0 + nj * 128));
                ulonglong2 n1 = __ldg((const ulonglong2*)(bp0 + (nj + 1) * 128));
#pragma unroll
                for (int t = 0; t < 4; t++) {
                    u64 d0 = dup2(a4[t].x), d1 = dup2(a4[t].y);
                    fma2(acc[t][0], d0, c0.x); fma2(acc[t][1], d0, c0.y);
                    fma2(acc[t][0], d1, c1.x); fma2(acc[t][1], d1, c1.y);
                }
                c0 = n0; c1 = n1;
            }
            {
                const int nj = (j4 < 127) ? 4 * j4 + 4 : 508;
                ulonglong2 n0 = __ldg((const ulonglong2*)(bp0 + nj * 128));
                ulonglong2 n1 = __ldg((const ulonglong2*)(bp0 + (nj + 1) * 128));
#pragma unroll
                for (int t = 0; t < 4; t++) {
                    u64 d0 = dup2(a4[t].z), d1 = dup2(a4[t].w);
                    fma2(acc[t][0], d0, c0.x); fma2(acc[t][1], d0, c0.y);
                    fma2(acc[t][0], d1, c1.x); fma2(acc[t][1], d1, c1.y);
                }
                c0 = n0; c1 = n1;
            }
        }
        float4 bb = __ldg((const float4*)(proj_b + m0));
#pragma unroll
        for (int t = 0; t < 4; t++) {
            float y0, y1, y2, y3;
            upk2(y0, y1, acc[t][0]);
            upk2(y2, y3, acc[t][1]);
            float* yrow = s + OFF_Y + (tb + t) * WR;
            const int f0 = 6 + m0, c0i = f0 >> 2;
            const int f1 = 8 + m0, c1i = f1 >> 2;
            *reinterpret_cast<u64*>(yrow + ((c0i + (c0i >> 3)) << 2) + 2) = pk2(y0 + bb.x, y1 + bb.y);
            *reinterpret_cast<u64*>(yrow + ((c1i + (c1i >> 3)) << 2))     = pk2(y2 + bb.z, y3 + bb.w);
        }
    }
    __syncthreads();

    // ====== Phase 4: final conv (32->64) + residual, co-QUAD per thread, one window read ======
    {
        const int qd = tid >> 4;          // 0..15 (co 4qd..4qd+3)
        const int g  = tid & 15;
        const int l0 = g * 8;
        const int cb = g * 2;
        const float* qres = gq + boff;
        u64 acc2[2][8];
#pragma unroll
        for (int p = 0; p < 2; p++)
#pragma unroll
            for (int i = 0; i < 8; i++) acc2[p][i] = 0ull;
        const float* wqbase = g_fcI4 + qd * 1792;
#pragma unroll 1
        for (int ci = 0; ci < 32; ci++)
            conv_quad_ci(acc2, s + OFF_Y + ci * WR, wqbase + ci * 56, cb);

        float o[4][8];
#pragma unroll
        for (int p = 0; p < 2; p++)
#pragma unroll
            for (int i = 0; i < 8; i++)
                upk2(o[2 * p][i], o[2 * p + 1][i], acc2[p][i]);
#pragma unroll
        for (int c = 0; c < 4; c++) {
            const int co = 4 * qd + c;
            float bv = __ldg(&fc_b[co]);
            float4 r0 = __ldg((const float4*)(qres + co * 128 + l0));
            float4 r1 = __ldg((const float4*)(qres + co * 128 + l0 + 4));
            *(float4*)(s + OFF_Z + co * 128 + l0) =
                make_float4(o[c][0] + bv + r0.x, o[c][1] + bv + r0.y,
                            o[c][2] + bv + r0.z, o[c][3] + bv + r0.w);
            *(float4*)(s + OFF_Z + co * 128 + l0 + 4) =
                make_float4(o[c][4] + bv + r1.x, o[c][5] + bv + r1.y,
                            o[c][6] + bv + r1.z, o[c][7] + bv + r1.w);
        }
    }
    __syncthreads();

    // ============ Phase 5: LayerNorm (unbiased std, /(sigma+eps)) ============
    {
#pragma unroll
        for (int it = 0; it < 8; it++) {
            int r = w + it * 8;
            const float* zr = s + OFF_Z + r * 128;
            float v0 = zr[lane], v1 = zr[lane + 32], v2 = zr[lane + 64], v3 = zr[lane + 96];
            float sm = v0 + v1 + v2 + v3;
#pragma unroll
            for (int o = 16; o > 0; o >>= 1) sm += __shfl_xor_sync(0xffffffffu, sm, o);
            float mu = sm * (1.f / 128.f);
            float d0 = v0 - mu, d1 = v1 - mu, d2 = v2 - mu, d3 = v3 - mu;
            float s2 = d0 * d0 + d1 * d1 + d2 * d2 + d3 * d3;
#pragma unroll
            for (int o = 16; o > 0; o >>= 1) s2 += __shfl_xor_sync(0xffffffffu, s2, o);
            float sigma = sqrtf(s2 * (1.f / 127.f));
            float inv = 1.f / (sigma + 1e-3f);
            float* orow = out + boff + r * 128;
            orow[lane]      = d0 * inv * __ldg(&ln_a[lane])      + __ldg(&ln_b[lane]);
            orow[lane + 32] = d1 * inv * __ldg(&ln_a[lane + 32]) + __ldg(&ln_b[lane + 32]);
            orow[lane + 64] = d2 * inv * __ldg(&ln_a[lane + 64]) + __ldg(&ln_b[lane + 64]);
            orow[lane + 96] = d3 * inv * __ldg(&ln_a[lane + 96]) + __ldg(&ln_b[lane + 96]);
        }
    }
}

extern "C" void kernel_launch(void* const* d_in, const int* in_sizes, int n_in,
                              void* d_out, int out_size)
{
    const float* q      = (const float*)d_in[0];
    const float* k      = (const float*)d_in[1];
    const float* v      = (const float*)d_in[2];
    const float* cq_w   = (const float*)d_in[3];
    const float* cq_b   = (const float*)d_in[4];
    const float* ck_w   = (const float*)d_in[5];
    const float* ck_b   = (const float*)d_in[6];
    const float* cv_w   = (const float*)d_in[7];
    const float* cv_b   = (const float*)d_in[8];
    const float* w_qs   = (const float*)d_in[9];
    const float* w_ks   = (const float*)d_in[10];
    const float* w_vs   = (const float*)d_in[11];
    const float* proj_w = (const float*)d_in[12];
    const float* proj_b = (const float*)d_in[13];
    const float* fc_w   = (const float*)d_in[14];
    const float* fc_b   = (const float*)d_in[15];
    const float* ln_a   = (const float*)d_in[16];
    const float* ln_b   = (const float*)d_in[17];
    float* outp = (float*)d_out;

    const int B = in_sizes[0] / (64 * 128);

    transpose_pw_kernel<<<128, 512>>>(proj_w);
    interleave_cw4_kernel<<<312, 256>>>(cq_w, ck_w, cv_w);
    interleave_fc4_kernel<<<104, 256>>>(fc_w);

    cudaFuncSetAttribute(ha_kernel, cudaFuncAttributeMaxDynamicSharedMemorySize, SMEM_BYTES);
    cudaFuncSetAttribute(ha_kernel, cudaFuncAttributePreferredSharedMemoryCarveout, 100);
    ha_kernel<<<B, NT, SMEM_BYTES>>>(q, k, v, cq_w, cq_b, ck_w, ck_b, cv_w, cv_b,
                                     w_qs, w_ks, w_vs, proj_w, proj_b, fc_w, fc_b,
                                     ln_a, ln_b, outp);
}